// round 7
// baseline (speedup 1.0000x reference)
#include <cuda_runtime.h>
#include <cuda_bf16.h>
#include <cstdint>

#define K_COMP   8
#define L_LAT    64
#define D_DATA   256
#define N_ROWS   16384
#define B_ROWS   2048
#define ENC_OUT  1536   // 3*K*L
#define DEC_OUT  6144   // 3*K*D
#define NB_SAMP  4096   // (16384*64)/256
#define D_SPLIT  4
#define NB_DEC   (256 * D_SPLIT)   // 1024
#define WT_N     196608 // 6144 cols * 32 u32 (64 bf16 k) packed

__device__ float    g_pred_e[B_ROWS * ENC_OUT];   // 12.6 MB
__device__ float    g_h[N_ROWS * L_LAT];          // 4 MB
__device__ uint32_t g_wT[WT_N];                   // W_d^T bf16 tiles [dc][kc][t][n][k]
__device__ float    g_partB[NB_SAMP];
__device__ float    g_partC[NB_DEC];

typedef unsigned long long u64;

// ---- helpers -------------------------------------------------------------
__device__ __forceinline__ u64 pack2(float lo, float hi) {
    u64 o; asm("mov.b64 %0, {%1, %2};" : "=l"(o) : "f"(lo), "f"(hi)); return o;
}
__device__ __forceinline__ u64 bcast2(float v) {
    u64 o; asm("mov.b64 %0, {%1, %1};" : "=l"(o) : "f"(v)); return o;
}
__device__ __forceinline__ void unpack2(u64 d, float& lo, float& hi) {
    asm("mov.b64 {%0, %1}, %2;" : "=f"(lo), "=f"(hi) : "l"(d));
}
__device__ __forceinline__ void fma2(u64& d, u64 a, u64 b) {
    asm("fma.rn.f32x2 %0, %1, %2, %0;" : "+l"(d) : "l"(a), "l"(b));
}
__device__ __forceinline__ uint32_t bf16x2_pack(float hi, float lo) {
    uint32_t o; asm("cvt.rn.bf16x2.f32 %0, %1, %2;" : "=r"(o) : "f"(hi), "f"(lo)); return o;
}
__device__ __forceinline__ uint32_t smem_u32(const void* p) {
    uint32_t a;
    asm("{ .reg .u64 t; cvta.to.shared.u64 t, %1; cvt.u32.u64 %0, t; }" : "=r"(a) : "l"(p));
    return a;
}
#define SW128(b) ((b) ^ (((b) >> 3) & 0x70))

#define LDMATRIX_X4(r0, r1, r2, r3, addr)                                     \
    asm volatile("ldmatrix.sync.aligned.m8n8.x4.shared.b16 {%0,%1,%2,%3}, [%4];" \
        : "=r"(r0), "=r"(r1), "=r"(r2), "=r"(r3) : "r"(addr))

#define MMA_BF16(c, a0, a1, a2, a3, b0, b1)                                   \
    asm volatile("mma.sync.aligned.m16n8k16.row.col.f32.bf16.bf16.f32 "       \
        "{%0,%1,%2,%3}, {%4,%5,%6,%7}, {%8,%9}, {%0,%1,%2,%3};"               \
        : "+f"((c)[0]), "+f"((c)[1]), "+f"((c)[2]), "+f"((c)[3])              \
        : "r"(a0), "r"(a1), "r"(a2), "r"(a3), "r"(b0), "r"(b1))

#define CP_ASYNC16(saddr, gaddr)                                              \
    asm volatile("cp.async.cg.shared.global [%0], [%1], 16;" :: "r"(saddr), "l"(gaddr))
#define CP_COMMIT() asm volatile("cp.async.commit_group;")
#define CP_WAIT(n)  asm volatile("cp.async.wait_group %0;" :: "n"(n))

__device__ __forceinline__ float block_reduce_256(float v) {
    __shared__ float red[8];
    int lane = threadIdx.x & 31, wid = threadIdx.x >> 5;
    #pragma unroll
    for (int o = 16; o > 0; o >>= 1) v += __shfl_down_sync(0xffffffffu, v, o);
    if (lane == 0) red[wid] = v;
    __syncthreads();
    if (wid == 0) {
        v = (lane < 8) ? red[lane] : 0.0f;
        #pragma unroll
        for (int o = 4; o > 0; o >>= 1) v += __shfl_down_sync(0xffffffffu, v, o);
    }
    return v;
}

// ---------------------------------------------------------------------------
// Pack W_d -> bf16 tiles: g_wT[((dc*8+kc)*3+t)*256 + n*32 + kp] =
//   {bf16(Wd[2kp+1][col]), bf16(Wd[2kp][col])}, col = t*2048+kc*256+dc*8+n
// ---------------------------------------------------------------------------
__global__ __launch_bounds__(256) void prep_w(const float* __restrict__ Wd)
{
    int i = blockIdx.x * 256 + threadIdx.x;   // < 196608
    int kp = i & 31;
    int n  = (i >> 5) & 7;
    int tile = i >> 8;
    int t = tile % 3;
    int q = tile / 3;
    int kc = q & 7, dc = q >> 3;
    int col = t * 2048 + kc * 256 + dc * 8 + n;
    float w0 = Wd[(2 * kp) * DEC_OUT + col];
    float w1 = Wd[(2 * kp + 1) * DEC_OUT + col];
    g_wT[i] = bf16x2_pack(w1, w0);
}

// ---------------------------------------------------------------------------
// Encoder GEMM (fp32 FFMA2): pred_e(2048,1536) = x @ W_e + b_e
// ---------------------------------------------------------------------------
__global__ __launch_bounds__(256) void enc_gemm(const float* __restrict__ x,
                                                const float* __restrict__ We,
                                                const float* __restrict__ be)
{
    __shared__ float As[16][64];
    __shared__ float Bs[16][64];
    const int tid = threadIdx.x;
    const int tx = tid & 15, ty = tid >> 4;
    const int bm = blockIdx.y * 64, bn = blockIdx.x * 64;

    u64 acc[4][2];
    #pragma unroll
    for (int i = 0; i < 4; i++) { acc[i][0] = pack2(0.f, 0.f); acc[i][1] = pack2(0.f, 0.f); }

    const int am = tid >> 2;
    const int ak = (tid & 3) * 4;
    const int bk = tid >> 6;
    const int bnn = tid & 63;

    for (int kt = 0; kt < 256; kt += 16) {
        float4 xa = *reinterpret_cast<const float4*>(x + (bm + am) * D_DATA + kt + ak);
        As[ak + 0][am] = xa.x;
        As[ak + 1][am] = xa.y;
        As[ak + 2][am] = xa.z;
        As[ak + 3][am] = xa.w;
        #pragma unroll
        for (int i = 0; i < 4; i++)
            Bs[bk + i * 4][bnn] = We[(kt + bk + i * 4) * ENC_OUT + bn + bnn];
        __syncthreads();

        #pragma unroll
        for (int kk = 0; kk < 16; kk++) {
            float4 av = *reinterpret_cast<const float4*>(&As[kk][ty * 4]);
            u64 b01 = *reinterpret_cast<const u64*>(&Bs[kk][tx * 4]);
            u64 b23 = *reinterpret_cast<const u64*>(&Bs[kk][tx * 4 + 2]);
            u64 a0 = bcast2(av.x), a1 = bcast2(av.y), a2 = bcast2(av.z), a3 = bcast2(av.w);
            fma2(acc[0][0], a0, b01); fma2(acc[0][1], a0, b23);
            fma2(acc[1][0], a1, b01); fma2(acc[1][1], a1, b23);
            fma2(acc[2][0], a2, b01); fma2(acc[2][1], a2, b23);
            fma2(acc[3][0], a3, b01); fma2(acc[3][1], a3, b23);
        }
        __syncthreads();
    }

    #pragma unroll
    for (int i = 0; i < 4; i++) {
        float v0, v1, v2, v3;
        unpack2(acc[i][0], v0, v1);
        unpack2(acc[i][1], v2, v3);
        int col = bn + tx * 4;
        float* outp = g_pred_e + (bm + ty * 4 + i) * ENC_OUT + col;
        outp[0] = v0 + be[col + 0];
        outp[1] = v1 + be[col + 1];
        outp[2] = v2 + be[col + 2];
        outp[3] = v3 + be[col + 3];
    }
}

// ---------------------------------------------------------------------------
// Sampling + h + (L_q - L_e) partials. One thread per (n, l). fp32 exact.
// ---------------------------------------------------------------------------
__global__ __launch_bounds__(256) void sample_k(const float* __restrict__ ue,
                                                const float* __restrict__ rr)
{
    const int g = blockIdx.x * 256 + threadIdx.x;
    const int n = g >> 6, l = g & 63;
    const float* row = g_pred_e + (n & (B_ROWS - 1)) * ENC_OUT;

    float a[K_COMP], e[K_COMP];
    float amax = -1e30f;
    #pragma unroll
    for (int k = 0; k < K_COMP; k++) {
        a[k] = row[1024 + k * 64 + l];
        amax = fmaxf(amax, a[k]);
    }
    float s = 0.0f;
    #pragma unroll
    for (int k = 0; k < K_COMP; k++) { e[k] = __expf(a[k] - amax); s += e[k]; }
    const float lse_a = amax + __logf(s);
    const float inv = 1.0f / s;

    const float rv = rr[n * 64 + l];
    float c = 0.0f;
    int idx = 0;
    #pragma unroll
    for (int k = 0; k < K_COMP; k++) {
        c += e[k] * inv;
        idx += (rv > c) ? 1 : 0;
    }
    if (idx > K_COMP - 1) idx = K_COMP - 1;

    const float msel = row[idx * 64 + l];
    const float psel = row[512 + idx * 64 + l];
    const float hv = msel + __expf(-0.5f * psel) * ue[n * 64 + l];
    g_h[n * 64 + l] = hv;

    float st = 0.0f;
    #pragma unroll
    for (int k = 0; k < K_COMP; k++) {
        float m = row[k * 64 + l];
        float p = row[512 + k * 64 + l];
        float dd = hv - m;
        st += __expf(a[k] + 0.5f * p - 0.5f * __expf(p) * dd * dd);
    }
    const float lse_s = __logf(st) - lse_a;

    float v = -0.5f * hv * hv - lse_s;
    v = block_reduce_256(v);
    if (threadIdx.x == 0) g_partB[blockIdx.x] = v;
}

// ---------------------------------------------------------------------------
// Decoder: tensor-core (mma.sync bf16) GEMM + fused mixture epilogue.
// Grid 1024 = 256 M-tiles x 4 d-splits (ds-major for L2 B-tile sharing).
// 128 threads (4 warps x m16). Each CTA: M-tile 64 rows, 8 d-chunks.
// Smem: B double buffer 2x24KB | h tile 8KB = 56KB dynamic (4 CTAs/SM).
// ---------------------------------------------------------------------------
__global__ void dec_k(const float* __restrict__ x,
                      const float* __restrict__ bd)
{
    extern __shared__ uint32_t dsm[];
    uint32_t* bufB = dsm;              // [0, 12288) u32 : two 24KB buffers
    uint32_t* hsm  = dsm + 12288;      // [12288, 14336) : h tile 64x64 bf16

    const int tid  = threadIdx.x;
    const int lane = tid & 31;
    const int warp = tid >> 5;
    const int mt = blockIdx.x & 255;
    const int ds = blockIdx.x >> 8;
    const int row0 = mt * 64;
    const int dc0 = ds * 8;

    const uint32_t sb_bufB = smem_u32(bufB);
    const uint32_t sb_h    = smem_u32(hsm);

    // stage h tile: row = tid>>1, k-half = tid&1 (32 k values -> 16 u32), SW128
    {
        int r = tid >> 1, kh = tid & 1;
        const float* hp = g_h + (row0 + r) * 64 + kh * 32;
        #pragma unroll
        for (int j = 0; j < 16; j++) {
            float2 v = *reinterpret_cast<const float2*>(hp + 2 * j);
            uint32_t off = r * 128 + (kh * 32 + 2 * j) * 2;
            hsm[SW128(off) >> 2] = bf16x2_pack(v.y, v.x);
        }
    }

    // prefetch d-chunk dc0 (can overlap with h staging; cp.async independent)
    {
        const uint32_t* gsrc = g_wT + dc0 * 6144;
        #pragma unroll
        for (int j = 0; j < 12; j++) {
            int c = tid + j * 128;
            uint32_t off = (c & 63) * 16;
            uint32_t so = (uint32_t)(c >> 6) * 1024 + SW128(off);
            CP_ASYNC16(sb_bufB + so, gsrc + c * 4);
        }
        CP_COMMIT();
    }
    __syncthreads();

    // A fragments: 4 k-steps, held for the whole kernel
    uint32_t afr[4][4];
    {
        const int m0 = warp * 16;
        #pragma unroll
        for (int s = 0; s < 4; s++) {
            int r = m0 + ((lane >> 3) & 1) * 8 + (lane & 7);
            uint32_t off = r * 128 + s * 32 + ((lane >> 4) & 1) * 16;
            uint32_t addr = sb_h + SW128(off);
            LDMATRIX_X4(afr[s][0], afr[s][1], afr[s][2], afr[s][3], addr);
        }
    }

    // epilogue geometry
    const int g8  = lane >> 2;
    const int c2  = (lane & 3) * 2;
    const int xr0 = (row0 + warp * 16 + g8) & (B_ROWS - 1);
    const int xr1 = (row0 + warp * 16 + g8 + 8) & (B_ROWS - 1);

    float part = 0.0f;

    for (int ic = 0; ic < 8; ic++) {
        const int dc = dc0 + ic;
        const uint32_t curB = sb_bufB + (ic & 1) * 24576;

        if (ic < 7) {
            const uint32_t* gsrc = g_wT + (dc + 1) * 6144;
            const uint32_t nxtB = sb_bufB + ((ic + 1) & 1) * 24576;
            #pragma unroll
            for (int j = 0; j < 12; j++) {
                int c = tid + j * 128;
                uint32_t off = (c & 63) * 16;
                uint32_t so = (uint32_t)(c >> 6) * 1024 + SW128(off);
                CP_ASYNC16(nxtB + so, gsrc + c * 4);
            }
            CP_COMMIT();
            CP_WAIT(1);
        } else {
            CP_WAIT(0);
        }
        __syncthreads();

        const int d0 = dc * 8 + c2;
        float2 x0 = *reinterpret_cast<const float2*>(x + xr0 * D_DATA + d0);
        float2 x1 = *reinterpret_cast<const float2*>(x + xr1 * D_DATA + d0);

        float s_t[4] = {0.f, 0.f, 0.f, 0.f};
        float s_a[4] = {0.f, 0.f, 0.f, 0.f};

        #pragma unroll
        for (int kc = 0; kc < K_COMP; kc++) {
            float cm[4] = {0.f, 0.f, 0.f, 0.f};
            float cp_[4] = {0.f, 0.f, 0.f, 0.f};
            float ca[4] = {0.f, 0.f, 0.f, 0.f};

            const uint32_t tb = curB + kc * 3072;
            const uint32_t boff = (uint32_t)(lane & 7) * 128 + (uint32_t)(lane >> 3) * 16;
            #pragma unroll
            for (int s2 = 0; s2 < 2; s2++) {
                uint32_t b0, b1, b2, b3;
                uint32_t a_sw = SW128(boff + s2 * 64);
                // type 0 (m)
                LDMATRIX_X4(b0, b1, b2, b3, tb + a_sw);
                MMA_BF16(cm, afr[2*s2][0], afr[2*s2][1], afr[2*s2][2], afr[2*s2][3], b0, b1);
                MMA_BF16(cm, afr[2*s2+1][0], afr[2*s2+1][1], afr[2*s2+1][2], afr[2*s2+1][3], b2, b3);
                // type 1 (logp)
                LDMATRIX_X4(b0, b1, b2, b3, tb + 1024 + a_sw);
                MMA_BF16(cp_, afr[2*s2][0], afr[2*s2][1], afr[2*s2][2], afr[2*s2][3], b0, b1);
                MMA_BF16(cp_, afr[2*s2+1][0], afr[2*s2+1][1], afr[2*s2+1][2], afr[2*s2+1][3], b2, b3);
                // type 2 (loga)
                LDMATRIX_X4(b0, b1, b2, b3, tb + 2048 + a_sw);
                MMA_BF16(ca, afr[2*s2][0], afr[2*s2][1], afr[2*s2][2], afr[2*s2][3], b0, b1);
                MMA_BF16(ca, afr[2*s2+1][0], afr[2*s2+1][1], afr[2*s2+1][2], afr[2*s2+1][3], b2, b3);
            }

            const int bi = kc * 256 + d0;
            float2 bm2 = __ldg(reinterpret_cast<const float2*>(bd + bi));
            float2 bp2 = __ldg(reinterpret_cast<const float2*>(bd + 2048 + bi));
            float2 ba2 = __ldg(reinterpret_cast<const float2*>(bd + 4096 + bi));

            #pragma unroll
            for (int p = 0; p < 4; p++) {
                float bm = (p & 1) ? bm2.y : bm2.x;
                float bp = (p & 1) ? bp2.y : bp2.x;
                float ba = (p & 1) ? ba2.y : ba2.x;
                float xval = (p == 0) ? x0.x : (p == 1) ? x0.y : (p == 2) ? x1.x : x1.y;
                float m  = cm[p] + bm;
                float pv = cp_[p] + bp;
                float av = ca[p] + ba;
                float dd = xval - m;
                float tt = av + 0.5f * pv - 0.5f * __expf(pv) * dd * dd;
                s_t[p] += __expf(tt);
                s_a[p] += __expf(av);
            }
        }

        #pragma unroll
        for (int p = 0; p < 4; p++)
            part += __logf(s_t[p]) - __logf(s_a[p]);

        __syncthreads();   // all reads of curB done before it is refilled (ic+2)
    }

    // block reduce over 128 threads
    {
        __shared__ float red[4];
        #pragma unroll
        for (int o = 16; o > 0; o >>= 1) part += __shfl_down_sync(0xffffffffu, part, o);
        if (lane == 0) red[warp] = part;
        __syncthreads();
        if (tid == 0) {
            float s = red[0] + red[1] + red[2] + red[3];
            g_partC[blockIdx.x] = s;
        }
    }
}

// ---------------------------------------------------------------------------
// Final reduction: out = -( (PB + PC)/N + c2 ),  c2 = -0.5*D*log(2*pi)
// ---------------------------------------------------------------------------
__global__ __launch_bounds__(1024) void final_k(float* __restrict__ out)
{
    __shared__ float red[32];
    float s = 0.0f;
    const float4* pb = reinterpret_cast<const float4*>(g_partB);
    for (int i = threadIdx.x; i < NB_SAMP / 4; i += 1024) {
        float4 v = pb[i]; s += (v.x + v.y) + (v.z + v.w);
    }
    const float4* pc = reinterpret_cast<const float4*>(g_partC);
    for (int i = threadIdx.x; i < NB_DEC / 4; i += 1024) {
        float4 v = pc[i]; s += (v.x + v.y) + (v.z + v.w);
    }
    int lane = threadIdx.x & 31, wid = threadIdx.x >> 5;
    #pragma unroll
    for (int o = 16; o > 0; o >>= 1) s += __shfl_down_sync(0xffffffffu, s, o);
    if (lane == 0) red[wid] = s;
    __syncthreads();
    if (wid == 0) {
        s = red[lane];
        #pragma unroll
        for (int o = 16; o > 0; o >>= 1) s += __shfl_down_sync(0xffffffffu, s, o);
        if (lane == 0) {
            const float c2 = -0.5f * 256.0f * 1.8378770664093453f;
            out[0] = -(s / (float)N_ROWS + c2);
        }
    }
}

extern "C" void kernel_launch(void* const* d_in, const int* in_sizes, int n_in,
                              void* d_out, int out_size) {
    const float* x  = (const float*)d_in[0];
    const float* We = (const float*)d_in[1];
    const float* be = (const float*)d_in[2];
    const float* Wd = (const float*)d_in[3];
    const float* bd = (const float*)d_in[4];
    const float* ue = (const float*)d_in[5];
    const float* rr = (const float*)d_in[6];
    float* out = (float*)d_out;

    static bool attr_set = false;
    if (!attr_set) {
        cudaFuncSetAttribute(dec_k, cudaFuncAttributeMaxDynamicSharedMemorySize, 57344);
        attr_set = true;
    }

    prep_w<<<WT_N / 256, 256>>>(Wd);
    dim3 ge(ENC_OUT / 64, B_ROWS / 64);
    enc_gemm<<<ge, 256>>>(x, We, be);
    sample_k<<<NB_SAMP, 256>>>(ue, rr);
    dec_k<<<NB_DEC, 128, 57344>>>(x, bd);
    final_k<<<1, 1024>>>(out);
}

// round 8
// speedup vs baseline: 1.1164x; 1.1164x over previous
#include <cuda_runtime.h>
#include <cuda_bf16.h>
#include <cstdint>

#define K_COMP   8
#define L_LAT    64
#define D_DATA   256
#define N_ROWS   16384
#define B_ROWS   2048
#define ENC_OUT  1536   // 3*K*L
#define DEC_OUT  6144   // 3*K*D
#define NB_SAMP  4096   // (16384*64)/256
#define D_SPLIT  2
#define NB_DEC   (256 * D_SPLIT)   // 512
#define WT_N     196608 // 6144 cols * 32 u32 (64 bf16 k) packed

__device__ float    g_pred_e[B_ROWS * ENC_OUT];   // 12.6 MB
__device__ float    g_h[N_ROWS * L_LAT];          // 4 MB
__device__ uint32_t g_wT[WT_N];                   // W_d^T bf16 tiles [dc][kc][t][n][k]
__device__ float    g_partB[NB_SAMP];
__device__ float    g_partC[NB_DEC];

typedef unsigned long long u64;

// ---- helpers -------------------------------------------------------------
__device__ __forceinline__ u64 pack2(float lo, float hi) {
    u64 o; asm("mov.b64 %0, {%1, %2};" : "=l"(o) : "f"(lo), "f"(hi)); return o;
}
__device__ __forceinline__ u64 bcast2(float v) {
    u64 o; asm("mov.b64 %0, {%1, %1};" : "=l"(o) : "f"(v)); return o;
}
__device__ __forceinline__ void unpack2(u64 d, float& lo, float& hi) {
    asm("mov.b64 {%0, %1}, %2;" : "=f"(lo), "=f"(hi) : "l"(d));
}
__device__ __forceinline__ void fma2(u64& d, u64 a, u64 b) {
    asm("fma.rn.f32x2 %0, %1, %2, %0;" : "+l"(d) : "l"(a), "l"(b));
}
__device__ __forceinline__ uint32_t bf16x2_pack(float hi, float lo) {
    uint32_t o; asm("cvt.rn.bf16x2.f32 %0, %1, %2;" : "=r"(o) : "f"(hi), "f"(lo)); return o;
}
__device__ __forceinline__ uint32_t smem_u32(const void* p) {
    uint32_t a;
    asm("{ .reg .u64 t; cvta.to.shared.u64 t, %1; cvt.u32.u64 %0, t; }" : "=r"(a) : "l"(p));
    return a;
}
#define SW128(b) ((b) ^ (((b) >> 3) & 0x70))

#define LDMATRIX_X4(r0, r1, r2, r3, addr)                                     \
    asm volatile("ldmatrix.sync.aligned.m8n8.x4.shared.b16 {%0,%1,%2,%3}, [%4];" \
        : "=r"(r0), "=r"(r1), "=r"(r2), "=r"(r3) : "r"(addr))

#define MMA_BF16(c, a0, a1, a2, a3, b0, b1)                                   \
    asm volatile("mma.sync.aligned.m16n8k16.row.col.f32.bf16.bf16.f32 "       \
        "{%0,%1,%2,%3}, {%4,%5,%6,%7}, {%8,%9}, {%0,%1,%2,%3};"               \
        : "+f"((c)[0]), "+f"((c)[1]), "+f"((c)[2]), "+f"((c)[3])              \
        : "r"(a0), "r"(a1), "r"(a2), "r"(a3), "r"(b0), "r"(b1))

#define CP_ASYNC16(saddr, gaddr)                                              \
    asm volatile("cp.async.cg.shared.global [%0], [%1], 16;" :: "r"(saddr), "l"(gaddr))
#define CP_COMMIT() asm volatile("cp.async.commit_group;")
#define CP_WAIT(n)  asm volatile("cp.async.wait_group %0;" :: "n"(n))

__device__ __forceinline__ float block_reduce_256(float v) {
    __shared__ float red[8];
    int lane = threadIdx.x & 31, wid = threadIdx.x >> 5;
    #pragma unroll
    for (int o = 16; o > 0; o >>= 1) v += __shfl_down_sync(0xffffffffu, v, o);
    if (lane == 0) red[wid] = v;
    __syncthreads();
    if (wid == 0) {
        v = (lane < 8) ? red[lane] : 0.0f;
        #pragma unroll
        for (int o = 4; o > 0; o >>= 1) v += __shfl_down_sync(0xffffffffu, v, o);
    }
    return v;
}

// ---------------------------------------------------------------------------
// Pack W_d -> bf16 tiles: g_wT[((dc*8+kc)*3+t)*256 + n*32 + kp] =
//   {bf16(Wd[2kp+1][col]), bf16(Wd[2kp][col])}, col = t*2048+kc*256+dc*8+n
// ---------------------------------------------------------------------------
__global__ __launch_bounds__(256) void prep_w(const float* __restrict__ Wd)
{
    int i = blockIdx.x * 256 + threadIdx.x;   // < 196608
    int kp = i & 31;
    int n  = (i >> 5) & 7;
    int tile = i >> 8;
    int t = tile % 3;
    int q = tile / 3;
    int kc = q & 7, dc = q >> 3;
    int col = t * 2048 + kc * 256 + dc * 8 + n;
    float w0 = Wd[(2 * kp) * DEC_OUT + col];
    float w1 = Wd[(2 * kp + 1) * DEC_OUT + col];
    g_wT[i] = bf16x2_pack(w1, w0);
}

// ---------------------------------------------------------------------------
// Encoder GEMM (fp32 FFMA2): pred_e(2048,1536) = x @ W_e + b_e
// ---------------------------------------------------------------------------
__global__ __launch_bounds__(256) void enc_gemm(const float* __restrict__ x,
                                                const float* __restrict__ We,
                                                const float* __restrict__ be)
{
    __shared__ float As[16][64];
    __shared__ float Bs[16][64];
    const int tid = threadIdx.x;
    const int tx = tid & 15, ty = tid >> 4;
    const int bm = blockIdx.y * 64, bn = blockIdx.x * 64;

    u64 acc[4][2];
    #pragma unroll
    for (int i = 0; i < 4; i++) { acc[i][0] = pack2(0.f, 0.f); acc[i][1] = pack2(0.f, 0.f); }

    const int am = tid >> 2;
    const int ak = (tid & 3) * 4;
    const int bk = tid >> 6;
    const int bnn = tid & 63;

    for (int kt = 0; kt < 256; kt += 16) {
        float4 xa = *reinterpret_cast<const float4*>(x + (bm + am) * D_DATA + kt + ak);
        As[ak + 0][am] = xa.x;
        As[ak + 1][am] = xa.y;
        As[ak + 2][am] = xa.z;
        As[ak + 3][am] = xa.w;
        #pragma unroll
        for (int i = 0; i < 4; i++)
            Bs[bk + i * 4][bnn] = We[(kt + bk + i * 4) * ENC_OUT + bn + bnn];
        __syncthreads();

        #pragma unroll
        for (int kk = 0; kk < 16; kk++) {
            float4 av = *reinterpret_cast<const float4*>(&As[kk][ty * 4]);
            u64 b01 = *reinterpret_cast<const u64*>(&Bs[kk][tx * 4]);
            u64 b23 = *reinterpret_cast<const u64*>(&Bs[kk][tx * 4 + 2]);
            u64 a0 = bcast2(av.x), a1 = bcast2(av.y), a2 = bcast2(av.z), a3 = bcast2(av.w);
            fma2(acc[0][0], a0, b01); fma2(acc[0][1], a0, b23);
            fma2(acc[1][0], a1, b01); fma2(acc[1][1], a1, b23);
            fma2(acc[2][0], a2, b01); fma2(acc[2][1], a2, b23);
            fma2(acc[3][0], a3, b01); fma2(acc[3][1], a3, b23);
        }
        __syncthreads();
    }

    #pragma unroll
    for (int i = 0; i < 4; i++) {
        float v0, v1, v2, v3;
        unpack2(acc[i][0], v0, v1);
        unpack2(acc[i][1], v2, v3);
        int col = bn + tx * 4;
        float* outp = g_pred_e + (bm + ty * 4 + i) * ENC_OUT + col;
        outp[0] = v0 + be[col + 0];
        outp[1] = v1 + be[col + 1];
        outp[2] = v2 + be[col + 2];
        outp[3] = v3 + be[col + 3];
    }
}

// ---------------------------------------------------------------------------
// Sampling + h + (L_q - L_e) partials. One thread per (n, l). fp32 exact.
// ---------------------------------------------------------------------------
__global__ __launch_bounds__(256) void sample_k(const float* __restrict__ ue,
                                                const float* __restrict__ rr)
{
    const int g = blockIdx.x * 256 + threadIdx.x;
    const int n = g >> 6, l = g & 63;
    const float* row = g_pred_e + (n & (B_ROWS - 1)) * ENC_OUT;

    float a[K_COMP], e[K_COMP];
    float amax = -1e30f;
    #pragma unroll
    for (int k = 0; k < K_COMP; k++) {
        a[k] = row[1024 + k * 64 + l];
        amax = fmaxf(amax, a[k]);
    }
    float s = 0.0f;
    #pragma unroll
    for (int k = 0; k < K_COMP; k++) { e[k] = __expf(a[k] - amax); s += e[k]; }
    const float lse_a = amax + __logf(s);
    const float inv = 1.0f / s;

    const float rv = rr[n * 64 + l];
    float c = 0.0f;
    int idx = 0;
    #pragma unroll
    for (int k = 0; k < K_COMP; k++) {
        c += e[k] * inv;
        idx += (rv > c) ? 1 : 0;
    }
    if (idx > K_COMP - 1) idx = K_COMP - 1;

    const float msel = row[idx * 64 + l];
    const float psel = row[512 + idx * 64 + l];
    const float hv = msel + __expf(-0.5f * psel) * ue[n * 64 + l];
    g_h[n * 64 + l] = hv;

    float st = 0.0f;
    #pragma unroll
    for (int k = 0; k < K_COMP; k++) {
        float m = row[k * 64 + l];
        float p = row[512 + k * 64 + l];
        float dd = hv - m;
        st += __expf(a[k] + 0.5f * p - 0.5f * __expf(p) * dd * dd);
    }
    const float lse_s = __logf(st) - lse_a;

    float v = -0.5f * hv * hv - lse_s;
    v = block_reduce_256(v);
    if (threadIdx.x == 0) g_partB[blockIdx.x] = v;
}

// ---------------------------------------------------------------------------
// Decoder: tensor-core (mma.sync bf16) GEMM + fused mixture epilogue.
// Grid 512 = 256 M-tiles x 2 d-halves. 256 threads = 8 warps:
//   warp&3 -> m16 row block, warp>>2 -> kc group (0-3 / 4-7).
// Per dc chunk both warpgroups share one B tile; partial s_t/s_a combined
// via smem exchange, log work split between warpgroups.
// Smem: B dbl buf 48KB | h 8KB | exchange 8KB = 64KB (3 CTAs/SM).
// ---------------------------------------------------------------------------
__global__ __launch_bounds__(256, 3) void dec_k(const float* __restrict__ x,
                                                const float* __restrict__ bd)
{
    extern __shared__ uint32_t dsm[];
    uint32_t* bufB = dsm;                       // [0, 12288) u32 : 2x24KB
    uint32_t* hsm  = dsm + 12288;               // 2048 u32 : h tile 64x64 bf16
    float*    ex_t = (float*)(dsm + 14336);     // [4][256]
    float*    ex_a = ex_t + 1024;               // [4][256]

    const int tid  = threadIdx.x;
    const int lane = tid & 31;
    const int warp = tid >> 5;
    const int wq   = warp & 3;     // m16 block
    const int wg   = warp >> 2;    // kc group
    const int mt   = blockIdx.x & 255;
    const int ds   = blockIdx.x >> 8;
    const int row0 = mt * 64;
    const int dc0  = ds * 16;

    const uint32_t sb_bufB = smem_u32(bufB);
    const uint32_t sb_h    = smem_u32(hsm);

    // stage h tile: r = tid>>2 (0..63), quarter q = tid&3 (16 k values = 8 u32)
    {
        int r = tid >> 2, q = tid & 3;
        const float* hp = g_h + (row0 + r) * 64 + q * 16;
        #pragma unroll
        for (int j = 0; j < 8; j++) {
            float2 v = *reinterpret_cast<const float2*>(hp + 2 * j);
            uint32_t off = r * 128 + (q * 16 + 2 * j) * 2;
            hsm[SW128(off) >> 2] = bf16x2_pack(v.y, v.x);
        }
    }

    // prefetch d-chunk dc0 (1536 x 16B, 6 per thread)
    {
        const uint32_t* gsrc = g_wT + dc0 * 6144;
        #pragma unroll
        for (int j = 0; j < 6; j++) {
            int c = tid + j * 256;
            uint32_t so = (uint32_t)(c >> 6) * 1024 + SW128((c & 63) * 16);
            CP_ASYNC16(sb_bufB + so, gsrc + c * 4);
        }
        CP_COMMIT();
    }
    __syncthreads();

    // A fragments: 4 k-steps, held for the whole kernel
    uint32_t afr[4][4];
    {
        const int m0 = wq * 16;
        #pragma unroll
        for (int s = 0; s < 4; s++) {
            int r = m0 + ((lane >> 3) & 1) * 8 + (lane & 7);
            uint32_t off = r * 128 + s * 32 + ((lane >> 4) & 1) * 16;
            LDMATRIX_X4(afr[s][0], afr[s][1], afr[s][2], afr[s][3], sb_h + SW128(off));
        }
    }

    // epilogue geometry
    const int g8  = lane >> 2;
    const int c2  = (lane & 3) * 2;
    const int xr0 = (row0 + wq * 16 + g8) & (B_ROWS - 1);
    const int xr1 = (row0 + wq * 16 + g8 + 8) & (B_ROWS - 1);

    float part = 0.0f;

    for (int ic = 0; ic < 16; ic++) {
        const int dc = dc0 + ic;
        const uint32_t curB = sb_bufB + (ic & 1) * 24576;

        if (ic < 15) {
            const uint32_t* gsrc = g_wT + (dc + 1) * 6144;
            const uint32_t nxtB = sb_bufB + ((ic + 1) & 1) * 24576;
            #pragma unroll
            for (int j = 0; j < 6; j++) {
                int c = tid + j * 256;
                uint32_t so = (uint32_t)(c >> 6) * 1024 + SW128((c & 63) * 16);
                CP_ASYNC16(nxtB + so, gsrc + c * 4);
            }
            CP_COMMIT();
            CP_WAIT(1);
        } else {
            CP_WAIT(0);
        }
        __syncthreads();

        const int d0 = dc * 8 + c2;
        float2 x0 = *reinterpret_cast<const float2*>(x + xr0 * D_DATA + d0);
        float2 x1 = *reinterpret_cast<const float2*>(x + xr1 * D_DATA + d0);

        float s_t[4] = {0.f, 0.f, 0.f, 0.f};
        float s_a[4] = {0.f, 0.f, 0.f, 0.f};

        #pragma unroll
        for (int kl = 0; kl < 4; kl++) {
            const int kc = wg * 4 + kl;
            float cm[4] = {0.f, 0.f, 0.f, 0.f};
            float cp_[4] = {0.f, 0.f, 0.f, 0.f};
            float ca[4] = {0.f, 0.f, 0.f, 0.f};

            const uint32_t tb = curB + kc * 3072;
            const uint32_t boff = (uint32_t)(lane & 7) * 128 + (uint32_t)(lane >> 3) * 16;
            #pragma unroll
            for (int s2 = 0; s2 < 2; s2++) {
                uint32_t b0, b1, b2, b3;
                uint32_t a_sw = SW128(boff + s2 * 64);
                LDMATRIX_X4(b0, b1, b2, b3, tb + a_sw);
                MMA_BF16(cm, afr[2*s2][0], afr[2*s2][1], afr[2*s2][2], afr[2*s2][3], b0, b1);
                MMA_BF16(cm, afr[2*s2+1][0], afr[2*s2+1][1], afr[2*s2+1][2], afr[2*s2+1][3], b2, b3);
                LDMATRIX_X4(b0, b1, b2, b3, tb + 1024 + a_sw);
                MMA_BF16(cp_, afr[2*s2][0], afr[2*s2][1], afr[2*s2][2], afr[2*s2][3], b0, b1);
                MMA_BF16(cp_, afr[2*s2+1][0], afr[2*s2+1][1], afr[2*s2+1][2], afr[2*s2+1][3], b2, b3);
                LDMATRIX_X4(b0, b1, b2, b3, tb + 2048 + a_sw);
                MMA_BF16(ca, afr[2*s2][0], afr[2*s2][1], afr[2*s2][2], afr[2*s2][3], b0, b1);
                MMA_BF16(ca, afr[2*s2+1][0], afr[2*s2+1][1], afr[2*s2+1][2], afr[2*s2+1][3], b2, b3);
            }

            const int bi = kc * 256 + d0;
            float2 bm2 = __ldg(reinterpret_cast<const float2*>(bd + bi));
            float2 bp2 = __ldg(reinterpret_cast<const float2*>(bd + 2048 + bi));
            float2 ba2 = __ldg(reinterpret_cast<const float2*>(bd + 4096 + bi));

            #pragma unroll
            for (int p = 0; p < 4; p++) {
                float bm = (p & 1) ? bm2.y : bm2.x;
                float bp = (p & 1) ? bp2.y : bp2.x;
                float ba = (p & 1) ? ba2.y : ba2.x;
                float xval = (p == 0) ? x0.x : (p == 1) ? x0.y : (p == 2) ? x1.x : x1.y;
                float m  = cm[p] + bm;
                float pv = cp_[p] + bp;
                float av = ca[p] + ba;
                float dd = xval - m;
                float tt = av + 0.5f * pv - 0.5f * __expf(pv) * dd * dd;
                s_t[p] += __expf(tt);
                s_a[p] += __expf(av);
            }
        }

        // combine partial sums across the two kc warpgroups
        #pragma unroll
        for (int p = 0; p < 4; p++) {
            ex_t[p * 256 + tid] = s_t[p];
            ex_a[p * 256 + tid] = s_a[p];
        }
        __syncthreads();
        {
            const int other = tid ^ 128;
            #pragma unroll
            for (int pp = 0; pp < 2; pp++) {
                int p = wg * 2 + pp;
                float tt = s_t[p] + ex_t[p * 256 + other];
                float ta = s_a[p] + ex_a[p * 256 + other];
                part += __logf(tt) - __logf(ta);
            }
        }
        __syncthreads();   // protect B buffer + exchange before next iter
    }

    // block reduce over 256 threads
    {
        __shared__ float red[8];
        #pragma unroll
        for (int o = 16; o > 0; o >>= 1) part += __shfl_down_sync(0xffffffffu, part, o);
        if (lane == 0) red[warp] = part;
        __syncthreads();
        if (tid == 0) {
            float s = 0.0f;
            #pragma unroll
            for (int w = 0; w < 8; w++) s += red[w];
            g_partC[blockIdx.x] = s;
        }
    }
}

// ---------------------------------------------------------------------------
// Final reduction: out = -( (PB + PC)/N + c2 ),  c2 = -0.5*D*log(2*pi)
// ---------------------------------------------------------------------------
__global__ __launch_bounds__(1024) void final_k(float* __restrict__ out)
{
    __shared__ float red[32];
    float s = 0.0f;
    const float4* pb = reinterpret_cast<const float4*>(g_partB);
    for (int i = threadIdx.x; i < NB_SAMP / 4; i += 1024) {
        float4 v = pb[i]; s += (v.x + v.y) + (v.z + v.w);
    }
    const float4* pc = reinterpret_cast<const float4*>(g_partC);
    for (int i = threadIdx.x; i < NB_DEC / 4; i += 1024) {
        float4 v = pc[i]; s += (v.x + v.y) + (v.z + v.w);
    }
    int lane = threadIdx.x & 31, wid = threadIdx.x >> 5;
    #pragma unroll
    for (int o = 16; o > 0; o >>= 1) s += __shfl_down_sync(0xffffffffu, s, o);
    if (lane == 0) red[wid] = s;
    __syncthreads();
    if (wid == 0) {
        s = red[lane];
        #pragma unroll
        for (int o = 16; o > 0; o >>= 1) s += __shfl_down_sync(0xffffffffu, s, o);
        if (lane == 0) {
            const float c2 = -0.5f * 256.0f * 1.8378770664093453f;
            out[0] = -(s / (float)N_ROWS + c2);
        }
    }
}

extern "C" void kernel_launch(void* const* d_in, const int* in_sizes, int n_in,
                              void* d_out, int out_size) {
    const float* x  = (const float*)d_in[0];
    const float* We = (const float*)d_in[1];
    const float* be = (const float*)d_in[2];
    const float* Wd = (const float*)d_in[3];
    const float* bd = (const float*)d_in[4];
    const float* ue = (const float*)d_in[5];
    const float* rr = (const float*)d_in[6];
    float* out = (float*)d_out;

    static bool attr_set = false;
    if (!attr_set) {
        cudaFuncSetAttribute(dec_k, cudaFuncAttributeMaxDynamicSharedMemorySize, 65536);
        attr_set = true;
    }

    prep_w<<<WT_N / 256, 256>>>(Wd);
    dim3 ge(ENC_OUT / 64, B_ROWS / 64);
    enc_gemm<<<ge, 256>>>(x, We, be);
    sample_k<<<NB_SAMP, 256>>>(ue, rr);
    dec_k<<<NB_DEC, 256, 65536>>>(x, bd);
    final_k<<<1, 1024>>>(out);
}

// round 9
// speedup vs baseline: 1.2222x; 1.0948x over previous
#include <cuda_runtime.h>
#include <cuda_bf16.h>
#include <cstdint>

#define K_COMP   8
#define L_LAT    64
#define D_DATA   256
#define N_ROWS   16384
#define B_ROWS   2048
#define ENC_OUT  1536   // 3*K*L
#define DEC_OUT  6144   // 3*K*D
#define NB_SAMP  4096   // (16384*64)/256
#define D_SPLIT  2
#define NB_DEC   (256 * D_SPLIT)   // 512
#define WT_N     196608 // 6144 cols * 32 u32 (64 bf16 k) packed
#define EA_N     786432 // 2048 rows * 384 u32 (768 bf16 k) packed
#define EB_N     589824 // 192 nt * 12 kc * 256 u32 tiles

__device__ float    g_pred_e[B_ROWS * ENC_OUT];   // 12.6 MB
__device__ float    g_h[N_ROWS * L_LAT];          // 4 MB
__device__ uint32_t g_wT[WT_N];                   // W_d^T bf16 tiles [dc][kc][t][n][k]
__device__ uint32_t g_eA[EA_N];                   // enc A' = [xh|xh|xl] bf16 pairs
__device__ uint32_t g_eB[EB_N];                   // enc B' = [wh;wl;wh] tiles [kc][nt][n][kp]
__device__ float    g_partB[NB_SAMP];
__device__ float    g_partC[NB_DEC];

typedef unsigned long long u64;

// ---- helpers -------------------------------------------------------------
__device__ __forceinline__ uint32_t bf16x2_pack(float hi, float lo) {
    uint32_t o; asm("cvt.rn.bf16x2.f32 %0, %1, %2;" : "=r"(o) : "f"(hi), "f"(lo)); return o;
}
__device__ __forceinline__ float bf16_rf(float v) {   // round to bf16, back to f32
    __nv_bfloat16 b = __float2bfloat16(v);
    return __bfloat162float(b);
}
__device__ __forceinline__ uint32_t smem_u32(const void* p) {
    uint32_t a;
    asm("{ .reg .u64 t; cvta.to.shared.u64 t, %1; cvt.u32.u64 %0, t; }" : "=r"(a) : "l"(p));
    return a;
}
#define SW128(b) ((b) ^ (((b) >> 3) & 0x70))

#define LDMATRIX_X4(r0, r1, r2, r3, addr)                                     \
    asm volatile("ldmatrix.sync.aligned.m8n8.x4.shared.b16 {%0,%1,%2,%3}, [%4];" \
        : "=r"(r0), "=r"(r1), "=r"(r2), "=r"(r3) : "r"(addr))

#define MMA_BF16(c, a0, a1, a2, a3, b0, b1)                                   \
    asm volatile("mma.sync.aligned.m16n8k16.row.col.f32.bf16.bf16.f32 "       \
        "{%0,%1,%2,%3}, {%4,%5,%6,%7}, {%8,%9}, {%0,%1,%2,%3};"               \
        : "+f"((c)[0]), "+f"((c)[1]), "+f"((c)[2]), "+f"((c)[3])              \
        : "r"(a0), "r"(a1), "r"(a2), "r"(a3), "r"(b0), "r"(b1))

#define CP_ASYNC16(saddr, gaddr)                                              \
    asm volatile("cp.async.cg.shared.global [%0], [%1], 16;" :: "r"(saddr), "l"(gaddr))
#define CP_COMMIT() asm volatile("cp.async.commit_group;")
#define CP_WAIT(n)  asm volatile("cp.async.wait_group %0;" :: "n"(n))

__device__ __forceinline__ float block_reduce_256(float v) {
    __shared__ float red[8];
    int lane = threadIdx.x & 31, wid = threadIdx.x >> 5;
    #pragma unroll
    for (int o = 16; o > 0; o >>= 1) v += __shfl_down_sync(0xffffffffu, v, o);
    if (lane == 0) red[wid] = v;
    __syncthreads();
    if (wid == 0) {
        v = (lane < 8) ? red[lane] : 0.0f;
        #pragma unroll
        for (int o = 4; o > 0; o >>= 1) v += __shfl_down_sync(0xffffffffu, v, o);
    }
    return v;
}

// ---------------------------------------------------------------------------
// Pack W_d -> bf16 tiles (decoder B)
// ---------------------------------------------------------------------------
__global__ __launch_bounds__(256) void prep_w(const float* __restrict__ Wd)
{
    int i = blockIdx.x * 256 + threadIdx.x;   // < 196608
    int kp = i & 31;
    int n  = (i >> 5) & 7;
    int tile = i >> 8;
    int t = tile % 3;
    int q = tile / 3;
    int kc = q & 7, dc = q >> 3;
    int col = t * 2048 + kc * 256 + dc * 8 + n;
    float w0 = Wd[(2 * kp) * DEC_OUT + col];
    float w1 = Wd[(2 * kp + 1) * DEC_OUT + col];
    g_wT[i] = bf16x2_pack(w1, w0);
}

// ---------------------------------------------------------------------------
// Encoder prep: A' (2048 x 768) = [xh | xh | xl], row-major bf16 pairs.
// ---------------------------------------------------------------------------
__global__ __launch_bounds__(256) void prep_ea(const float* __restrict__ x)
{
    int i = blockIdx.x * 256 + threadIdx.x;   // < 786432
    int row = i / 384, j = i % 384;
    int k0 = 2 * j;
    float v0, v1;
    if (k0 < 512) {
        v0 = x[row * 256 + (k0 & 255)];
        v1 = x[row * 256 + ((k0 + 1) & 255)];
        v0 = bf16_rf(v0); v1 = bf16_rf(v1);
    } else {
        float a0 = x[row * 256 + (k0 - 512)];
        float a1 = x[row * 256 + (k0 - 511)];
        v0 = a0 - bf16_rf(a0);
        v1 = a1 - bf16_rf(a1);
    }
    g_eA[i] = bf16x2_pack(v1, v0);
}

// ---------------------------------------------------------------------------
// Encoder prep: B' (768 x 1536) = [wh; wl; wh], tiles [kc][nt][n8][kp32].
// ---------------------------------------------------------------------------
__global__ __launch_bounds__(256) void prep_eb(const float* __restrict__ We)
{
    int i = blockIdx.x * 256 + threadIdx.x;   // < 589824
    int kp = i & 31;
    int n  = (i >> 5) & 7;
    int r  = i >> 8;
    int nt = r % 192, kc = r / 192;
    int col = nt * 8 + n;
    float v[2];
    #pragma unroll
    for (int s = 0; s < 2; s++) {
        int k = kc * 64 + 2 * kp + s;
        if (k < 256) {
            v[s] = bf16_rf(We[k * ENC_OUT + col]);
        } else if (k < 512) {
            float a = We[(k - 256) * ENC_OUT + col];
            v[s] = a - bf16_rf(a);
        } else {
            v[s] = bf16_rf(We[(k - 512) * ENC_OUT + col]);
        }
    }
    g_eB[i] = bf16x2_pack(v[1], v[0]);
}

// ---------------------------------------------------------------------------
// Encoder GEMM (tensor core, split-bf16 K=768): pred_e = A' @ B' + b_e
// Tile 64x64, 128 threads (4 warps x m16). 12 K-chunks, double buffered.
// ---------------------------------------------------------------------------
__global__ __launch_bounds__(128) void enc_tc(const float* __restrict__ be)
{
    __shared__ __align__(1024) uint32_t Abuf[2][2048];   // 2 x 8KB
    __shared__ __align__(1024) uint32_t Bbuf[2][2048];   // 2 x 8KB

    const int tid  = threadIdx.x;
    const int lane = tid & 31;
    const int warp = tid >> 5;
    const int bn = blockIdx.x * 64, bm = blockIdx.y * 64;
    const int nt0 = blockIdx.x * 8;

    const uint32_t sA0 = smem_u32(Abuf[0]), sA1 = smem_u32(Abuf[1]);
    const uint32_t sB0 = smem_u32(Bbuf[0]), sB1 = smem_u32(Bbuf[1]);

    // prefetch chunk 0
    {
        #pragma unroll
        for (int t = 0; t < 4; t++) {
            int g = tid + t * 128;
            int row = g >> 3, gg = g & 7;
            CP_ASYNC16(sA0 + SW128(row * 128 + gg * 16),
                       g_eA + (uint32_t)(bm + row) * 384 + gg * 4);
            CP_ASYNC16(sB0 + (uint32_t)(g >> 6) * 1024 + SW128((g & 63) * 16),
                       g_eB + (uint32_t)(nt0 + (g >> 6)) * 256 + (g & 63) * 4);
        }
        CP_COMMIT();
    }

    float c[8][4];
    #pragma unroll
    for (int nt = 0; nt < 8; nt++)
        #pragma unroll
        for (int p = 0; p < 4; p++) c[nt][p] = 0.0f;

    const int m0 = warp * 16;
    const int ar = m0 + ((lane >> 3) & 1) * 8 + (lane & 7);
    const uint32_t akoff = ((lane >> 4) & 1) * 16;
    const uint32_t boff = (uint32_t)(lane & 7) * 128 + (uint32_t)(lane >> 3) * 16;

    for (int kc = 0; kc < 12; kc++) {
        const uint32_t curA = (kc & 1) ? sA1 : sA0;
        const uint32_t curB = (kc & 1) ? sB1 : sB0;

        if (kc < 11) {
            const uint32_t nA = (kc & 1) ? sA0 : sA1;
            const uint32_t nB = (kc & 1) ? sB0 : sB1;
            #pragma unroll
            for (int t = 0; t < 4; t++) {
                int g = tid + t * 128;
                int row = g >> 3, gg = g & 7;
                CP_ASYNC16(nA + SW128(row * 128 + gg * 16),
                           g_eA + (uint32_t)(bm + row) * 384 + (kc + 1) * 32 + gg * 4);
                CP_ASYNC16(nB + (uint32_t)(g >> 6) * 1024 + SW128((g & 63) * 16),
                           g_eB + ((uint32_t)(kc + 1) * 192 + nt0 + (g >> 6)) * 256 + (g & 63) * 4);
            }
            CP_COMMIT();
            CP_WAIT(1);
        } else {
            CP_WAIT(0);
        }
        __syncthreads();

        uint32_t afr[4][4];
        #pragma unroll
        for (int s = 0; s < 4; s++) {
            uint32_t off = (uint32_t)ar * 128 + s * 32 + akoff;
            LDMATRIX_X4(afr[s][0], afr[s][1], afr[s][2], afr[s][3], curA + SW128(off));
        }

        #pragma unroll
        for (int nt = 0; nt < 8; nt++) {
            const uint32_t tb = curB + nt * 1024;
            #pragma unroll
            for (int s2 = 0; s2 < 2; s2++) {
                uint32_t b0, b1, b2, b3;
                LDMATRIX_X4(b0, b1, b2, b3, tb + SW128(boff + s2 * 64));
                MMA_BF16(c[nt], afr[2*s2][0], afr[2*s2][1], afr[2*s2][2], afr[2*s2][3], b0, b1);
                MMA_BF16(c[nt], afr[2*s2+1][0], afr[2*s2+1][1], afr[2*s2+1][2], afr[2*s2+1][3], b2, b3);
            }
        }
        __syncthreads();
    }

    // epilogue
    const int g8 = lane >> 2;
    const int c2 = (lane & 3) * 2;
    const int r0 = bm + m0 + g8, r1 = r0 + 8;
    #pragma unroll
    for (int nt = 0; nt < 8; nt++) {
        int col = bn + nt * 8 + c2;
        float b0 = be[col], b1 = be[col + 1];
        g_pred_e[r0 * ENC_OUT + col]     = c[nt][0] + b0;
        g_pred_e[r0 * ENC_OUT + col + 1] = c[nt][1] + b1;
        g_pred_e[r1 * ENC_OUT + col]     = c[nt][2] + b0;
        g_pred_e[r1 * ENC_OUT + col + 1] = c[nt][3] + b1;
    }
}

// ---------------------------------------------------------------------------
// Sampling + h + (L_q - L_e) partials. One thread per (n, l). fp32 exact.
// ---------------------------------------------------------------------------
__global__ __launch_bounds__(256) void sample_k(const float* __restrict__ ue,
                                                const float* __restrict__ rr)
{
    const int g = blockIdx.x * 256 + threadIdx.x;
    const int n = g >> 6, l = g & 63;
    const float* row = g_pred_e + (n & (B_ROWS - 1)) * ENC_OUT;

    float a[K_COMP], e[K_COMP];
    float amax = -1e30f;
    #pragma unroll
    for (int k = 0; k < K_COMP; k++) {
        a[k] = row[1024 + k * 64 + l];
        amax = fmaxf(amax, a[k]);
    }
    float s = 0.0f;
    #pragma unroll
    for (int k = 0; k < K_COMP; k++) { e[k] = __expf(a[k] - amax); s += e[k]; }
    const float lse_a = amax + __logf(s);
    const float inv = 1.0f / s;

    const float rv = rr[n * 64 + l];
    float c = 0.0f;
    int idx = 0;
    #pragma unroll
    for (int k = 0; k < K_COMP; k++) {
        c += e[k] * inv;
        idx += (rv > c) ? 1 : 0;
    }
    if (idx > K_COMP - 1) idx = K_COMP - 1;

    const float msel = row[idx * 64 + l];
    const float psel = row[512 + idx * 64 + l];
    const float hv = msel + __expf(-0.5f * psel) * ue[n * 64 + l];
    g_h[n * 64 + l] = hv;

    float st = 0.0f;
    #pragma unroll
    for (int k = 0; k < K_COMP; k++) {
        float m = row[k * 64 + l];
        float p = row[512 + k * 64 + l];
        float dd = hv - m;
        st += __expf(a[k] + 0.5f * p - 0.5f * __expf(p) * dd * dd);
    }
    const float lse_s = __logf(st) - lse_a;

    float v = -0.5f * hv * hv - lse_s;
    v = block_reduce_256(v);
    if (threadIdx.x == 0) g_partB[blockIdx.x] = v;
}

// ---------------------------------------------------------------------------
// Decoder: tensor-core bf16 GEMM + fused mixture epilogue.
// Grid 512 = 256 M-tiles x 2 d-halves; 8 warps = 4 m16 x 2 kc-groups.
// Exchange buffers reuse the dead h-tile smem (A frags register-resident).
// Smem: B dbl 48KB + h/exchange 8KB = 56KB -> 4 CTAs/SM; regs capped at 64.
// ---------------------------------------------------------------------------
__global__ __launch_bounds__(256, 4) void dec_k(const float* __restrict__ x,
                                                const float* __restrict__ bd)
{
    extern __shared__ uint32_t dsm[];
    uint32_t* bufB = dsm;                       // [0, 12288) u32 : 2x24KB
    uint32_t* hsm  = dsm + 12288;               // 2048 u32 : h tile, then exchange
    float*    ex_t = (float*)hsm;               // [4][256] after A frags loaded
    float*    ex_a = ex_t + 1024;

    const int tid  = threadIdx.x;
    const int lane = tid & 31;
    const int warp = tid >> 5;
    const int wq   = warp & 3;     // m16 block
    const int wg   = warp >> 2;    // kc group
    const int mt   = blockIdx.x & 255;
    const int ds   = blockIdx.x >> 8;
    const int row0 = mt * 64;
    const int dc0  = ds * 16;

    const uint32_t sb_bufB = smem_u32(bufB);
    const uint32_t sb_h    = smem_u32(hsm);

    // stage h tile: r = tid>>2 (0..63), quarter q = tid&3 (16 k values = 8 u32)
    {
        int r = tid >> 2, q = tid & 3;
        const float* hp = g_h + (row0 + r) * 64 + q * 16;
        #pragma unroll
        for (int j = 0; j < 8; j++) {
            float2 v = *reinterpret_cast<const float2*>(hp + 2 * j);
            uint32_t off = r * 128 + (q * 16 + 2 * j) * 2;
            hsm[SW128(off) >> 2] = bf16x2_pack(v.y, v.x);
        }
    }

    // prefetch d-chunk dc0
    {
        const uint32_t* gsrc = g_wT + dc0 * 6144;
        #pragma unroll
        for (int j = 0; j < 6; j++) {
            int c = tid + j * 256;
            uint32_t so = (uint32_t)(c >> 6) * 1024 + SW128((c & 63) * 16);
            CP_ASYNC16(sb_bufB + so, gsrc + c * 4);
        }
        CP_COMMIT();
    }
    __syncthreads();

    // A fragments: 4 k-steps, held for the whole kernel
    uint32_t afr[4][4];
    {
        const int m0 = wq * 16;
        #pragma unroll
        for (int s = 0; s < 4; s++) {
            int r = m0 + ((lane >> 3) & 1) * 8 + (lane & 7);
            uint32_t off = r * 128 + s * 32 + ((lane >> 4) & 1) * 16;
            LDMATRIX_X4(afr[s][0], afr[s][1], afr[s][2], afr[s][3], sb_h + SW128(off));
        }
    }

    // epilogue geometry
    const int g8  = lane >> 2;
    const int c2  = (lane & 3) * 2;
    const int xr0 = (row0 + wq * 16 + g8) & (B_ROWS - 1);
    const int xr1 = (row0 + wq * 16 + g8 + 8) & (B_ROWS - 1);

    float part = 0.0f;

    for (int ic = 0; ic < 16; ic++) {
        const int dc = dc0 + ic;
        const uint32_t curB = sb_bufB + (ic & 1) * 24576;

        if (ic < 15) {
            const uint32_t* gsrc = g_wT + (dc + 1) * 6144;
            const uint32_t nxtB = sb_bufB + ((ic + 1) & 1) * 24576;
            #pragma unroll
            for (int j = 0; j < 6; j++) {
                int c = tid + j * 256;
                uint32_t so = (uint32_t)(c >> 6) * 1024 + SW128((c & 63) * 16);
                CP_ASYNC16(nxtB + so, gsrc + c * 4);
            }
            CP_COMMIT();
            CP_WAIT(1);
        } else {
            CP_WAIT(0);
        }
        __syncthreads();   // also orders afr LDSM (iter 0) before hsm reuse

        const int d0 = dc * 8 + c2;
        float2 x0 = *reinterpret_cast<const float2*>(x + xr0 * D_DATA + d0);
        float2 x1 = *reinterpret_cast<const float2*>(x + xr1 * D_DATA + d0);

        float s_t[4] = {0.f, 0.f, 0.f, 0.f};
        float s_a[4] = {0.f, 0.f, 0.f, 0.f};

        #pragma unroll
        for (int kl = 0; kl < 4; kl++) {
            const int kc = wg * 4 + kl;
            float cm[4] = {0.f, 0.f, 0.f, 0.f};
            float cp_[4] = {0.f, 0.f, 0.f, 0.f};
            float ca[4] = {0.f, 0.f, 0.f, 0.f};

            const uint32_t tb = curB + kc * 3072;
            const uint32_t boff = (uint32_t)(lane & 7) * 128 + (uint32_t)(lane >> 3) * 16;
            #pragma unroll
            for (int s2 = 0; s2 < 2; s2++) {
                uint32_t b0, b1, b2, b3;
                uint32_t a_sw = SW128(boff + s2 * 64);
                LDMATRIX_X4(b0, b1, b2, b3, tb + a_sw);
                MMA_BF16(cm, afr[2*s2][0], afr[2*s2][1], afr[2*s2][2], afr[2*s2][3], b0, b1);
                MMA_BF16(cm, afr[2*s2+1][0], afr[2*s2+1][1], afr[2*s2+1][2], afr[2*s2+1][3], b2, b3);
                LDMATRIX_X4(b0, b1, b2, b3, tb + 1024 + a_sw);
                MMA_BF16(cp_, afr[2*s2][0], afr[2*s2][1], afr[2*s2][2], afr[2*s2][3], b0, b1);
                MMA_BF16(cp_, afr[2*s2+1][0], afr[2*s2+1][1], afr[2*s2+1][2], afr[2*s2+1][3], b2, b3);
                LDMATRIX_X4(b0, b1, b2, b3, tb + 2048 + a_sw);
                MMA_BF16(ca, afr[2*s2][0], afr[2*s2][1], afr[2*s2][2], afr[2*s2][3], b0, b1);
                MMA_BF16(ca, afr[2*s2+1][0], afr[2*s2+1][1], afr[2*s2+1][2], afr[2*s2+1][3], b2, b3);
            }

            const int bi = kc * 256 + d0;
            float2 bm2 = __ldg(reinterpret_cast<const float2*>(bd + bi));
            float2 bp2 = __ldg(reinterpret_cast<const float2*>(bd + 2048 + bi));
            float2 ba2 = __ldg(reinterpret_cast<const float2*>(bd + 4096 + bi));

            #pragma unroll
            for (int p = 0; p < 4; p++) {
                float bm = (p & 1) ? bm2.y : bm2.x;
                float bp = (p & 1) ? bp2.y : bp2.x;
                float ba = (p & 1) ? ba2.y : ba2.x;
                float xval = (p == 0) ? x0.x : (p == 1) ? x0.y : (p == 2) ? x1.x : x1.y;
                float m  = cm[p] + bm;
                float pv = cp_[p] + bp;
                float av = ca[p] + ba;
                float dd = xval - m;
                float tt = av + 0.5f * pv - 0.5f * __expf(pv) * dd * dd;
                s_t[p] += __expf(tt);
                s_a[p] += __expf(av);
            }
        }

        // combine partial sums across the two kc warpgroups
        #pragma unroll
        for (int p = 0; p < 4; p++) {
            ex_t[p * 256 + tid] = s_t[p];
            ex_a[p * 256 + tid] = s_a[p];
        }
        __syncthreads();
        {
            const int other = tid ^ 128;
            #pragma unroll
            for (int pp = 0; pp < 2; pp++) {
                int p = wg * 2 + pp;
                float tt = s_t[p] + ex_t[p * 256 + other];
                float ta = s_a[p] + ex_a[p * 256 + other];
                part += __logf(tt) - __logf(ta);
            }
        }
        __syncthreads();   // protect B buffer + exchange before next iter
    }

    // block reduce over 256 threads
    {
        __shared__ float red[8];
        #pragma unroll
        for (int o = 16; o > 0; o >>= 1) part += __shfl_down_sync(0xffffffffu, part, o);
        if (lane == 0) red[warp] = part;
        __syncthreads();
        if (tid == 0) {
            float s = 0.0f;
            #pragma unroll
            for (int w = 0; w < 8; w++) s += red[w];
            g_partC[blockIdx.x] = s;
        }
    }
}

// ---------------------------------------------------------------------------
// Final reduction: out = -( (PB + PC)/N + c2 ),  c2 = -0.5*D*log(2*pi)
// ---------------------------------------------------------------------------
__global__ __launch_bounds__(1024) void final_k(float* __restrict__ out)
{
    __shared__ float red[32];
    float s = 0.0f;
    const float4* pb = reinterpret_cast<const float4*>(g_partB);
    for (int i = threadIdx.x; i < NB_SAMP / 4; i += 1024) {
        float4 v = pb[i]; s += (v.x + v.y) + (v.z + v.w);
    }
    const float4* pc = reinterpret_cast<const float4*>(g_partC);
    for (int i = threadIdx.x; i < NB_DEC / 4; i += 1024) {
        float4 v = pc[i]; s += (v.x + v.y) + (v.z + v.w);
    }
    int lane = threadIdx.x & 31, wid = threadIdx.x >> 5;
    #pragma unroll
    for (int o = 16; o > 0; o >>= 1) s += __shfl_down_sync(0xffffffffu, s, o);
    if (lane == 0) red[wid] = s;
    __syncthreads();
    if (wid == 0) {
        s = red[lane];
        #pragma unroll
        for (int o = 16; o > 0; o >>= 1) s += __shfl_down_sync(0xffffffffu, s, o);
        if (lane == 0) {
            const float c2 = -0.5f * 256.0f * 1.8378770664093453f;
            out[0] = -(s / (float)N_ROWS + c2);
        }
    }
}

extern "C" void kernel_launch(void* const* d_in, const int* in_sizes, int n_in,
                              void* d_out, int out_size) {
    const float* x  = (const float*)d_in[0];
    const float* We = (const float*)d_in[1];
    const float* be = (const float*)d_in[2];
    const float* Wd = (const float*)d_in[3];
    const float* bd = (const float*)d_in[4];
    const float* ue = (const float*)d_in[5];
    const float* rr = (const float*)d_in[6];
    float* out = (float*)d_out;

    static bool attr_set = false;
    if (!attr_set) {
        cudaFuncSetAttribute(dec_k, cudaFuncAttributeMaxDynamicSharedMemorySize, 57344);
        attr_set = true;
    }

    prep_w<<<WT_N / 256, 256>>>(Wd);
    prep_ea<<<EA_N / 256, 256>>>(x);
    prep_eb<<<EB_N / 256, 256>>>(We);
    enc_tc<<<dim3(24, 32), 128>>>(be);
    sample_k<<<NB_SAMP, 256>>>(ue, rr);
    dec_k<<<NB_DEC, 256, 57344>>>(x, bd);
    final_k<<<1, 1024>>>(out);
}

// round 10
// speedup vs baseline: 1.2509x; 1.0235x over previous
#include <cuda_runtime.h>
#include <cuda_bf16.h>
#include <cstdint>

#define K_COMP   8
#define L_LAT    64
#define D_DATA   256
#define N_ROWS   16384
#define B_ROWS   2048
#define ENC_OUT  1536   // 3*K*L
#define DEC_OUT  6144   // 3*K*D
#define NB_SAMP  4096
#define D_SPLIT  2
#define NB_DEC   (256 * D_SPLIT)   // 512
#define WT_N     196608 // 6144 cols * 32 u32 (64 bf16 k) packed
#define EA_N     786432 // 2048 rows * 384 u32 (768 bf16 k) packed
#define EB_N     589824 // 192 nt * 12 kc * 256 u32 tiles

__device__ float    g_pred_e[B_ROWS * ENC_OUT];   // 12.6 MB
__device__ float    g_h[N_ROWS * L_LAT];          // 4 MB
__device__ uint32_t g_wT[WT_N];                   // W_d^T bf16 tiles [dc][kc][t][n][k]
__device__ uint32_t g_eA[EA_N];                   // enc A' = [xh|xh|xl] bf16 pairs
__device__ uint32_t g_eB[EB_N];                   // enc B' = [wh;wl;wh] tiles [kc][nt][n][kp]
__device__ float    g_accum[2];                   // [0]=sample partials, [1]=dec partials

typedef unsigned long long u64;

// ---- helpers -------------------------------------------------------------
__device__ __forceinline__ uint32_t bf16x2_pack(float hi, float lo) {
    uint32_t o; asm("cvt.rn.bf16x2.f32 %0, %1, %2;" : "=r"(o) : "f"(hi), "f"(lo)); return o;
}
__device__ __forceinline__ float bf16_rf(float v) {
    __nv_bfloat16 b = __float2bfloat16(v);
    return __bfloat162float(b);
}
__device__ __forceinline__ uint32_t smem_u32(const void* p) {
    uint32_t a;
    asm("{ .reg .u64 t; cvta.to.shared.u64 t, %1; cvt.u32.u64 %0, t; }" : "=r"(a) : "l"(p));
    return a;
}
#define SW128(b) ((b) ^ (((b) >> 3) & 0x70))

#define LDMATRIX_X4(r0, r1, r2, r3, addr)                                     \
    asm volatile("ldmatrix.sync.aligned.m8n8.x4.shared.b16 {%0,%1,%2,%3}, [%4];" \
        : "=r"(r0), "=r"(r1), "=r"(r2), "=r"(r3) : "r"(addr))

#define MMA_BF16(c, a0, a1, a2, a3, b0, b1)                                   \
    asm volatile("mma.sync.aligned.m16n8k16.row.col.f32.bf16.bf16.f32 "       \
        "{%0,%1,%2,%3}, {%4,%5,%6,%7}, {%8,%9}, {%0,%1,%2,%3};"               \
        : "+f"((c)[0]), "+f"((c)[1]), "+f"((c)[2]), "+f"((c)[3])              \
        : "r"(a0), "r"(a1), "r"(a2), "r"(a3), "r"(b0), "r"(b1))

#define CP_ASYNC16(saddr, gaddr)                                              \
    asm volatile("cp.async.cg.shared.global [%0], [%1], 16;" :: "r"(saddr), "l"(gaddr))
#define CP_COMMIT() asm volatile("cp.async.commit_group;")
#define CP_WAIT(n)  asm volatile("cp.async.wait_group %0;" :: "n"(n))

__device__ __forceinline__ float block_reduce_256(float v) {
    __shared__ float red[8];
    int lane = threadIdx.x & 31, wid = threadIdx.x >> 5;
    #pragma unroll
    for (int o = 16; o > 0; o >>= 1) v += __shfl_down_sync(0xffffffffu, v, o);
    if (lane == 0) red[wid] = v;
    __syncthreads();
    if (wid == 0) {
        v = (lane < 8) ? red[lane] : 0.0f;
        #pragma unroll
        for (int o = 4; o > 0; o >>= 1) v += __shfl_down_sync(0xffffffffu, v, o);
    }
    return v;
}

// ---------------------------------------------------------------------------
// Fused prep: blocks [0,768) pack W_d; [768,3840) pack enc A'; rest enc B'.
// Block 0 also zeroes the atomic accumulators (stream order protects them).
// ---------------------------------------------------------------------------
__global__ __launch_bounds__(256) void prep_all(const float* __restrict__ Wd,
                                                const float* __restrict__ x,
                                                const float* __restrict__ We)
{
    const int b = blockIdx.x;
    if (b == 0 && threadIdx.x < 2) g_accum[threadIdx.x] = 0.0f;

    if (b < 768) {
        int i = b * 256 + threadIdx.x;            // < 196608
        int kp = i & 31;
        int n  = (i >> 5) & 7;
        int tile = i >> 8;
        int t = tile % 3;
        int q = tile / 3;
        int kc = q & 7, dc = q >> 3;
        int col = t * 2048 + kc * 256 + dc * 8 + n;
        float w0 = Wd[(2 * kp) * DEC_OUT + col];
        float w1 = Wd[(2 * kp + 1) * DEC_OUT + col];
        g_wT[i] = bf16x2_pack(w1, w0);
    } else if (b < 3840) {
        int i = (b - 768) * 256 + threadIdx.x;    // < 786432
        int row = i / 384, j = i % 384;
        int k0 = 2 * j;
        float v0, v1;
        if (k0 < 512) {
            v0 = bf16_rf(x[row * 256 + (k0 & 255)]);
            v1 = bf16_rf(x[row * 256 + ((k0 + 1) & 255)]);
        } else {
            float a0 = x[row * 256 + (k0 - 512)];
            float a1 = x[row * 256 + (k0 - 511)];
            v0 = a0 - bf16_rf(a0);
            v1 = a1 - bf16_rf(a1);
        }
        g_eA[i] = bf16x2_pack(v1, v0);
    } else {
        int i = (b - 3840) * 256 + threadIdx.x;   // < 589824
        int kp = i & 31;
        int n  = (i >> 5) & 7;
        int r  = i >> 8;
        int nt = r % 192, kc = r / 192;
        int col = nt * 8 + n;
        float v[2];
        #pragma unroll
        for (int s = 0; s < 2; s++) {
            int k = kc * 64 + 2 * kp + s;
            if (k < 256) {
                v[s] = bf16_rf(We[k * ENC_OUT + col]);
            } else if (k < 512) {
                float a = We[(k - 256) * ENC_OUT + col];
                v[s] = a - bf16_rf(a);
            } else {
                v[s] = bf16_rf(We[(k - 512) * ENC_OUT + col]);
            }
        }
        g_eB[i] = bf16x2_pack(v[1], v[0]);
    }
}

// ---------------------------------------------------------------------------
// Encoder GEMM (tensor core, split-bf16 K=768): pred_e = A' @ B' + b_e
// Tile 128x64, 256 threads (8 warps x m16). 12 K-chunks, double buffered.
// Smem: A 2x16KB + B 2x8KB = 48KB dynamic.
// ---------------------------------------------------------------------------
__global__ __launch_bounds__(256, 3) void enc_tc(const float* __restrict__ be)
{
    extern __shared__ uint32_t esm[];
    const uint32_t sA0 = smem_u32(esm);             // 4096 u32
    const uint32_t sA1 = sA0 + 16384;
    const uint32_t sB0 = sA1 + 16384;               // 2048 u32
    const uint32_t sB1 = sB0 + 8192;

    const int tid  = threadIdx.x;
    const int lane = tid & 31;
    const int warp = tid >> 5;
    const int bn = blockIdx.x * 64, bm = blockIdx.y * 128;
    const int nt0 = blockIdx.x * 8;

    // prefetch chunk 0: A 1024 x 16B, B 512 x 16B
    {
        #pragma unroll
        for (int t = 0; t < 4; t++) {
            int u = tid + t * 256;
            int row = u >> 3, gg = u & 7;
            CP_ASYNC16(sA0 + SW128(row * 128 + gg * 16),
                       g_eA + (uint32_t)(bm + row) * 384 + gg * 4);
        }
        #pragma unroll
        for (int t = 0; t < 2; t++) {
            int u = tid + t * 256;
            CP_ASYNC16(sB0 + (uint32_t)(u >> 6) * 1024 + SW128((u & 63) * 16),
                       g_eB + (uint32_t)(nt0 + (u >> 6)) * 256 + (u & 63) * 4);
        }
        CP_COMMIT();
    }

    float c[8][4];
    #pragma unroll
    for (int nt = 0; nt < 8; nt++)
        #pragma unroll
        for (int p = 0; p < 4; p++) c[nt][p] = 0.0f;

    const int m0 = warp * 16;
    const int ar = m0 + ((lane >> 3) & 1) * 8 + (lane & 7);
    const uint32_t akoff = ((lane >> 4) & 1) * 16;
    const uint32_t boff = (uint32_t)(lane & 7) * 128 + (uint32_t)(lane >> 3) * 16;

    for (int kc = 0; kc < 12; kc++) {
        const uint32_t curA = (kc & 1) ? sA1 : sA0;
        const uint32_t curB = (kc & 1) ? sB1 : sB0;

        if (kc < 11) {
            const uint32_t nA = (kc & 1) ? sA0 : sA1;
            const uint32_t nB = (kc & 1) ? sB0 : sB1;
            #pragma unroll
            for (int t = 0; t < 4; t++) {
                int u = tid + t * 256;
                int row = u >> 3, gg = u & 7;
                CP_ASYNC16(nA + SW128(row * 128 + gg * 16),
                           g_eA + (uint32_t)(bm + row) * 384 + (kc + 1) * 32 + gg * 4);
            }
            #pragma unroll
            for (int t = 0; t < 2; t++) {
                int u = tid + t * 256;
                CP_ASYNC16(nB + (uint32_t)(u >> 6) * 1024 + SW128((u & 63) * 16),
                           g_eB + ((uint32_t)(kc + 1) * 192 + nt0 + (u >> 6)) * 256 + (u & 63) * 4);
            }
            CP_COMMIT();
            CP_WAIT(1);
        } else {
            CP_WAIT(0);
        }
        __syncthreads();

        uint32_t afr[4][4];
        #pragma unroll
        for (int s = 0; s < 4; s++) {
            uint32_t off = (uint32_t)ar * 128 + s * 32 + akoff;
            LDMATRIX_X4(afr[s][0], afr[s][1], afr[s][2], afr[s][3], curA + SW128(off));
        }

        #pragma unroll
        for (int nt = 0; nt < 8; nt++) {
            const uint32_t tb = curB + nt * 1024;
            #pragma unroll
            for (int s2 = 0; s2 < 2; s2++) {
                uint32_t b0, b1, b2, b3;
                LDMATRIX_X4(b0, b1, b2, b3, tb + SW128(boff + s2 * 64));
                MMA_BF16(c[nt], afr[2*s2][0], afr[2*s2][1], afr[2*s2][2], afr[2*s2][3], b0, b1);
                MMA_BF16(c[nt], afr[2*s2+1][0], afr[2*s2+1][1], afr[2*s2+1][2], afr[2*s2+1][3], b2, b3);
            }
        }
        __syncthreads();
    }

    // epilogue
    const int g8 = lane >> 2;
    const int c2 = (lane & 3) * 2;
    const int r0 = bm + m0 + g8, r1 = r0 + 8;
    #pragma unroll
    for (int nt = 0; nt < 8; nt++) {
        int col = bn + nt * 8 + c2;
        float b0 = be[col], b1 = be[col + 1];
        g_pred_e[r0 * ENC_OUT + col]     = c[nt][0] + b0;
        g_pred_e[r0 * ENC_OUT + col + 1] = c[nt][1] + b1;
        g_pred_e[r1 * ENC_OUT + col]     = c[nt][2] + b0;
        g_pred_e[r1 * ENC_OUT + col + 1] = c[nt][3] + b1;
    }
}

// ---------------------------------------------------------------------------
// Sampling + h + (L_q - L_e) partials. One thread per (n, l). fp32 exact.
// ---------------------------------------------------------------------------
__global__ __launch_bounds__(256) void sample_k(const float* __restrict__ ue,
                                                const float* __restrict__ rr)
{
    const int g = blockIdx.x * 256 + threadIdx.x;
    const int n = g >> 6, l = g & 63;
    const float* row = g_pred_e + (n & (B_ROWS - 1)) * ENC_OUT;

    float a[K_COMP], e[K_COMP];
    float amax = -1e30f;
    #pragma unroll
    for (int k = 0; k < K_COMP; k++) {
        a[k] = row[1024 + k * 64 + l];
        amax = fmaxf(amax, a[k]);
    }
    float s = 0.0f;
    #pragma unroll
    for (int k = 0; k < K_COMP; k++) { e[k] = __expf(a[k] - amax); s += e[k]; }
    const float lse_a = amax + __logf(s);
    const float inv = 1.0f / s;

    const float rv = rr[n * 64 + l];
    float c = 0.0f;
    int idx = 0;
    #pragma unroll
    for (int k = 0; k < K_COMP; k++) {
        c += e[k] * inv;
        idx += (rv > c) ? 1 : 0;
    }
    if (idx > K_COMP - 1) idx = K_COMP - 1;

    const float msel = row[idx * 64 + l];
    const float psel = row[512 + idx * 64 + l];
    const float hv = msel + __expf(-0.5f * psel) * ue[n * 64 + l];
    g_h[n * 64 + l] = hv;

    float st = 0.0f;
    #pragma unroll
    for (int k = 0; k < K_COMP; k++) {
        float m = row[k * 64 + l];
        float p = row[512 + k * 64 + l];
        float dd = hv - m;
        st += __expf(a[k] + 0.5f * p - 0.5f * __expf(p) * dd * dd);
    }
    const float lse_s = __logf(st) - lse_a;

    float v = -0.5f * hv * hv - lse_s;
    v = block_reduce_256(v);
    if (threadIdx.x == 0) atomicAdd(&g_accum[0], v);
}

// ---------------------------------------------------------------------------
// Decoder: tensor-core bf16 GEMM + fused mixture epilogue.
// Grid 512 = 256 M-tiles x 2 d-halves; 8 warps = 4 m16 x 2 kc-groups.
// Exchange halved: each thread publishes only the 2 p-values its partner logs.
// Smem: B dbl 48KB + h/exchange 8KB = 56KB (4 CTAs/SM); regs capped at 64.
// ---------------------------------------------------------------------------
__global__ __launch_bounds__(256, 4) void dec_k(const float* __restrict__ x,
                                                const float* __restrict__ bd)
{
    extern __shared__ uint32_t dsm[];
    uint32_t* bufB = dsm;                       // [0, 12288) u32 : 2x24KB
    uint32_t* hsm  = dsm + 12288;               // 2048 u32 : h tile, then exchange
    float*    ex_t = (float*)hsm;               // [2][256]
    float*    ex_a = ex_t + 512;                // [2][256]

    const int tid  = threadIdx.x;
    const int lane = tid & 31;
    const int warp = tid >> 5;
    const int wq   = warp & 3;     // m16 block
    const int wg   = warp >> 2;    // kc group
    const int mt   = blockIdx.x & 255;
    const int ds   = blockIdx.x >> 8;
    const int row0 = mt * 64;
    const int dc0  = ds * 16;

    const uint32_t sb_bufB = smem_u32(bufB);
    const uint32_t sb_h    = smem_u32(hsm);

    // stage h tile
    {
        int r = tid >> 2, q = tid & 3;
        const float* hp = g_h + (row0 + r) * 64 + q * 16;
        #pragma unroll
        for (int j = 0; j < 8; j++) {
            float2 v = *reinterpret_cast<const float2*>(hp + 2 * j);
            uint32_t off = r * 128 + (q * 16 + 2 * j) * 2;
            hsm[SW128(off) >> 2] = bf16x2_pack(v.y, v.x);
        }
    }

    // prefetch d-chunk dc0
    {
        const uint32_t* gsrc = g_wT + dc0 * 6144;
        #pragma unroll
        for (int j = 0; j < 6; j++) {
            int c = tid + j * 256;
            uint32_t so = (uint32_t)(c >> 6) * 1024 + SW128((c & 63) * 16);
            CP_ASYNC16(sb_bufB + so, gsrc + c * 4);
        }
        CP_COMMIT();
    }
    __syncthreads();

    // A fragments: held for the whole kernel
    uint32_t afr[4][4];
    {
        const int m0 = wq * 16;
        #pragma unroll
        for (int s = 0; s < 4; s++) {
            int r = m0 + ((lane >> 3) & 1) * 8 + (lane & 7);
            uint32_t off = r * 128 + s * 32 + ((lane >> 4) & 1) * 16;
            LDMATRIX_X4(afr[s][0], afr[s][1], afr[s][2], afr[s][3], sb_h + SW128(off));
        }
    }

    // epilogue geometry
    const int g8  = lane >> 2;
    const int c2  = (lane & 3) * 2;
    const int xr0 = (row0 + wq * 16 + g8) & (B_ROWS - 1);
    const int xr1 = (row0 + wq * 16 + g8 + 8) & (B_ROWS - 1);
    const int po  = (wg ^ 1) * 2;   // p-values published to the partner group

    float part = 0.0f;

    for (int ic = 0; ic < 16; ic++) {
        const int dc = dc0 + ic;
        const uint32_t curB = sb_bufB + (ic & 1) * 24576;

        if (ic < 15) {
            const uint32_t* gsrc = g_wT + (dc + 1) * 6144;
            const uint32_t nxtB = sb_bufB + ((ic + 1) & 1) * 24576;
            #pragma unroll
            for (int j = 0; j < 6; j++) {
                int c = tid + j * 256;
                uint32_t so = (uint32_t)(c >> 6) * 1024 + SW128((c & 63) * 16);
                CP_ASYNC16(nxtB + so, gsrc + c * 4);
            }
            CP_COMMIT();
            CP_WAIT(1);
        } else {
            CP_WAIT(0);
        }
        __syncthreads();   // also orders afr LDSM (iter 0) before hsm reuse

        const int d0 = dc * 8 + c2;
        float2 x0 = *reinterpret_cast<const float2*>(x + xr0 * D_DATA + d0);
        float2 x1 = *reinterpret_cast<const float2*>(x + xr1 * D_DATA + d0);

        float s_t[4] = {0.f, 0.f, 0.f, 0.f};
        float s_a[4] = {0.f, 0.f, 0.f, 0.f};

        #pragma unroll
        for (int kl = 0; kl < 4; kl++) {
            const int kc = wg * 4 + kl;
            float cm[4] = {0.f, 0.f, 0.f, 0.f};
            float cp_[4] = {0.f, 0.f, 0.f, 0.f};
            float ca[4] = {0.f, 0.f, 0.f, 0.f};

            const uint32_t tb = curB + kc * 3072;
            const uint32_t boff = (uint32_t)(lane & 7) * 128 + (uint32_t)(lane >> 3) * 16;
            #pragma unroll
            for (int s2 = 0; s2 < 2; s2++) {
                uint32_t b0, b1, b2, b3;
                uint32_t a_sw = SW128(boff + s2 * 64);
                LDMATRIX_X4(b0, b1, b2, b3, tb + a_sw);
                MMA_BF16(cm, afr[2*s2][0], afr[2*s2][1], afr[2*s2][2], afr[2*s2][3], b0, b1);
                MMA_BF16(cm, afr[2*s2+1][0], afr[2*s2+1][1], afr[2*s2+1][2], afr[2*s2+1][3], b2, b3);
                LDMATRIX_X4(b0, b1, b2, b3, tb + 1024 + a_sw);
                MMA_BF16(cp_, afr[2*s2][0], afr[2*s2][1], afr[2*s2][2], afr[2*s2][3], b0, b1);
                MMA_BF16(cp_, afr[2*s2+1][0], afr[2*s2+1][1], afr[2*s2+1][2], afr[2*s2+1][3], b2, b3);
                LDMATRIX_X4(b0, b1, b2, b3, tb + 2048 + a_sw);
                MMA_BF16(ca, afr[2*s2][0], afr[2*s2][1], afr[2*s2][2], afr[2*s2][3], b0, b1);
                MMA_BF16(ca, afr[2*s2+1][0], afr[2*s2+1][1], afr[2*s2+1][2], afr[2*s2+1][3], b2, b3);
            }

            const int bi = kc * 256 + d0;
            float2 bm2 = __ldg(reinterpret_cast<const float2*>(bd + bi));
            float2 bp2 = __ldg(reinterpret_cast<const float2*>(bd + 2048 + bi));
            float2 ba2 = __ldg(reinterpret_cast<const float2*>(bd + 4096 + bi));

            #pragma unroll
            for (int p = 0; p < 4; p++) {
                float bm = (p & 1) ? bm2.y : bm2.x;
                float bp = (p & 1) ? bp2.y : bp2.x;
                float ba = (p & 1) ? ba2.y : ba2.x;
                float xval = (p == 0) ? x0.x : (p == 1) ? x0.y : (p == 2) ? x1.x : x1.y;
                float m  = cm[p] + bm;
                float pv = cp_[p] + bp;
                float av = ca[p] + ba;
                float dd = xval - m;
                float tt = av + 0.5f * pv - 0.5f * __expf(pv) * dd * dd;
                s_t[p] += __expf(tt);
                s_a[p] += __expf(av);
            }
        }

        // publish only the partner group's p-values
        ex_t[0 * 256 + tid] = s_t[po];
        ex_t[1 * 256 + tid] = s_t[po + 1];
        ex_a[0 * 256 + tid] = s_a[po];
        ex_a[1 * 256 + tid] = s_a[po + 1];
        __syncthreads();
        {
            const int other = tid ^ 128;
            #pragma unroll
            for (int pp = 0; pp < 2; pp++) {
                int p = wg * 2 + pp;
                float tt = s_t[p] + ex_t[pp * 256 + other];
                float ta = s_a[p] + ex_a[pp * 256 + other];
                part += __logf(tt) - __logf(ta);
            }
        }
        __syncthreads();   // protect B buffer + exchange before next iter
    }

    // block reduce over 256 threads
    {
        __shared__ float red[8];
        #pragma unroll
        for (int o = 16; o > 0; o >>= 1) part += __shfl_down_sync(0xffffffffu, part, o);
        if (lane == 0) red[warp] = part;
        __syncthreads();
        if (tid == 0) {
            float s = 0.0f;
            #pragma unroll
            for (int w = 0; w < 8; w++) s += red[w];
            atomicAdd(&g_accum[1], s);
        }
    }
}

// ---------------------------------------------------------------------------
// Final: out = -( (accum0 + accum1)/N + c2 ),  c2 = -0.5*D*log(2*pi)
// ---------------------------------------------------------------------------
__global__ void final_k(float* __restrict__ out)
{
    if (threadIdx.x == 0) {
        const float c2 = -0.5f * 256.0f * 1.8378770664093453f;
        out[0] = -((g_accum[0] + g_accum[1]) / (float)N_ROWS + c2);
    }
}

extern "C" void kernel_launch(void* const* d_in, const int* in_sizes, int n_in,
                              void* d_out, int out_size) {
    const float* x  = (const float*)d_in[0];
    const float* We = (const float*)d_in[1];
    const float* be = (const float*)d_in[2];
    const float* Wd = (const float*)d_in[3];
    const float* bd = (const float*)d_in[4];
    const float* ue = (const float*)d_in[5];
    const float* rr = (const float*)d_in[6];
    float* out = (float*)d_out;

    static bool attr_set = false;
    if (!attr_set) {
        cudaFuncSetAttribute(dec_k, cudaFuncAttributeMaxDynamicSharedMemorySize, 57344);
        cudaFuncSetAttribute(enc_tc, cudaFuncAttributeMaxDynamicSharedMemorySize, 49152);
        attr_set = true;
    }

    prep_all<<<6144, 256>>>(Wd, x, We);
    enc_tc<<<dim3(24, 16), 256, 49152>>>(be);
    sample_k<<<NB_SAMP, 256>>>(ue, rr);
    dec_k<<<NB_DEC, 256, 57344>>>(x, bd);
    final_k<<<1, 32>>>(out);
}

// round 11
// speedup vs baseline: 1.3156x; 1.0517x over previous
#include <cuda_runtime.h>
#include <cuda_bf16.h>
#include <cstdint>

#define K_COMP   8
#define L_LAT    64
#define D_DATA   256
#define N_ROWS   16384
#define B_ROWS   2048
#define ENC_OUT  1536   // 3*K*L
#define DEC_OUT  6144   // 3*K*D
#define NB_SAMP  4096
#define D_SPLIT  2
#define NB_DEC   (256 * D_SPLIT)   // 512
#define WT_N     196608
#define EA_N     786432
#define EB_N     589824

__device__ float    g_pred_e[B_ROWS * ENC_OUT];
__device__ float    g_h[N_ROWS * L_LAT];
__device__ uint32_t g_wT[WT_N];
__device__ uint32_t g_eA[EA_N];
__device__ uint32_t g_eB[EB_N];
__device__ float    g_accum[2];

typedef unsigned long long u64;

// ---- helpers -------------------------------------------------------------
__device__ __forceinline__ uint32_t bf16x2_pack(float hi, float lo) {
    uint32_t o; asm("cvt.rn.bf16x2.f32 %0, %1, %2;" : "=r"(o) : "f"(hi), "f"(lo)); return o;
}
__device__ __forceinline__ float bf16_rf(float v) {
    __nv_bfloat16 b = __float2bfloat16(v);
    return __bfloat162float(b);
}
__device__ __forceinline__ uint32_t smem_u32(const void* p) {
    uint32_t a;
    asm("{ .reg .u64 t; cvta.to.shared.u64 t, %1; cvt.u32.u64 %0, t; }" : "=r"(a) : "l"(p));
    return a;
}
#define SW128(b) ((b) ^ (((b) >> 3) & 0x70))

#define LDMATRIX_X4(r0, r1, r2, r3, addr)                                     \
    asm volatile("ldmatrix.sync.aligned.m8n8.x4.shared.b16 {%0,%1,%2,%3}, [%4];" \
        : "=r"(r0), "=r"(r1), "=r"(r2), "=r"(r3) : "r"(addr))

#define MMA_BF16(c, a0, a1, a2, a3, b0, b1)                                   \
    asm volatile("mma.sync.aligned.m16n8k16.row.col.f32.bf16.bf16.f32 "       \
        "{%0,%1,%2,%3}, {%4,%5,%6,%7}, {%8,%9}, {%0,%1,%2,%3};"               \
        : "+f"((c)[0]), "+f"((c)[1]), "+f"((c)[2]), "+f"((c)[3])              \
        : "r"(a0), "r"(a1), "r"(a2), "r"(a3), "r"(b0), "r"(b1))

#define CP_ASYNC16(saddr, gaddr)                                              \
    asm volatile("cp.async.cg.shared.global [%0], [%1], 16;" :: "r"(saddr), "l"(gaddr))
#define CP_COMMIT() asm volatile("cp.async.commit_group;")
#define CP_WAIT(n)  asm volatile("cp.async.wait_group %0;" :: "n"(n))

__device__ __forceinline__ float block_reduce_256(float v) {
    __shared__ float red[8];
    int lane = threadIdx.x & 31, wid = threadIdx.x >> 5;
    #pragma unroll
    for (int o = 16; o > 0; o >>= 1) v += __shfl_down_sync(0xffffffffu, v, o);
    if (lane == 0) red[wid] = v;
    __syncthreads();
    if (wid == 0) {
        v = (lane < 8) ? red[lane] : 0.0f;
        #pragma unroll
        for (int o = 4; o > 0; o >>= 1) v += __shfl_down_sync(0xffffffffu, v, o);
    }
    return v;
}

// ---------------------------------------------------------------------------
// Fused prep: [0,768) W_d tiles; [768,3840) enc A'; rest enc B'.
// ---------------------------------------------------------------------------
__global__ __launch_bounds__(256) void prep_all(const float* __restrict__ Wd,
                                                const float* __restrict__ x,
                                                const float* __restrict__ We)
{
    const int b = blockIdx.x;
    if (b == 0 && threadIdx.x < 2) g_accum[threadIdx.x] = 0.0f;

    if (b < 768) {
        int i = b * 256 + threadIdx.x;
        int kp = i & 31;
        int n  = (i >> 5) & 7;
        int tile = i >> 8;
        int t = tile % 3;
        int q = tile / 3;
        int kc = q & 7, dc = q >> 3;
        int col = t * 2048 + kc * 256 + dc * 8 + n;
        float w0 = Wd[(2 * kp) * DEC_OUT + col];
        float w1 = Wd[(2 * kp + 1) * DEC_OUT + col];
        g_wT[i] = bf16x2_pack(w1, w0);
    } else if (b < 3840) {
        int i = (b - 768) * 256 + threadIdx.x;
        int row = i / 384, j = i % 384;
        int k0 = 2 * j;
        float v0, v1;
        if (k0 < 512) {
            v0 = bf16_rf(x[row * 256 + (k0 & 255)]);
            v1 = bf16_rf(x[row * 256 + ((k0 + 1) & 255)]);
        } else {
            float a0 = x[row * 256 + (k0 - 512)];
            float a1 = x[row * 256 + (k0 - 511)];
            v0 = a0 - bf16_rf(a0);
            v1 = a1 - bf16_rf(a1);
        }
        g_eA[i] = bf16x2_pack(v1, v0);
    } else {
        int i = (b - 3840) * 256 + threadIdx.x;
        int kp = i & 31;
        int n  = (i >> 5) & 7;
        int r  = i >> 8;
        int nt = r % 192, kc = r / 192;
        int col = nt * 8 + n;
        float v[2];
        #pragma unroll
        for (int s = 0; s < 2; s++) {
            int k = kc * 64 + 2 * kp + s;
            if (k < 256) {
                v[s] = bf16_rf(We[k * ENC_OUT + col]);
            } else if (k < 512) {
                float a = We[(k - 256) * ENC_OUT + col];
                v[s] = a - bf16_rf(a);
            } else {
                v[s] = bf16_rf(We[(k - 512) * ENC_OUT + col]);
            }
        }
        g_eB[i] = bf16x2_pack(v[1], v[0]);
    }
}

// ---------------------------------------------------------------------------
// Encoder GEMM (tensor core, split-bf16 K=768): pred_e = A' @ B' + b_e
// Tile 128x64, 256 threads (8 warps x m16). 12 K-chunks, double buffered.
// ---------------------------------------------------------------------------
__global__ __launch_bounds__(256, 3) void enc_tc(const float* __restrict__ be)
{
    extern __shared__ uint32_t esm[];
    const uint32_t sA0 = smem_u32(esm);
    const uint32_t sA1 = sA0 + 16384;
    const uint32_t sB0 = sA1 + 16384;
    const uint32_t sB1 = sB0 + 8192;

    const int tid  = threadIdx.x;
    const int lane = tid & 31;
    const int warp = tid >> 5;
    const int bn = blockIdx.x * 64, bm = blockIdx.y * 128;
    const int nt0 = blockIdx.x * 8;

    {
        #pragma unroll
        for (int t = 0; t < 4; t++) {
            int u = tid + t * 256;
            int row = u >> 3, gg = u & 7;
            CP_ASYNC16(sA0 + SW128(row * 128 + gg * 16),
                       g_eA + (uint32_t)(bm + row) * 384 + gg * 4);
        }
        #pragma unroll
        for (int t = 0; t < 2; t++) {
            int u = tid + t * 256;
            CP_ASYNC16(sB0 + (uint32_t)(u >> 6) * 1024 + SW128((u & 63) * 16),
                       g_eB + (uint32_t)(nt0 + (u >> 6)) * 256 + (u & 63) * 4);
        }
        CP_COMMIT();
    }

    float c[8][4];
    #pragma unroll
    for (int nt = 0; nt < 8; nt++)
        #pragma unroll
        for (int p = 0; p < 4; p++) c[nt][p] = 0.0f;

    const int m0 = warp * 16;
    const int ar = m0 + ((lane >> 3) & 1) * 8 + (lane & 7);
    const uint32_t akoff = ((lane >> 4) & 1) * 16;
    const uint32_t boff = (uint32_t)(lane & 7) * 128 + (uint32_t)(lane >> 3) * 16;

    for (int kc = 0; kc < 12; kc++) {
        const uint32_t curA = (kc & 1) ? sA1 : sA0;
        const uint32_t curB = (kc & 1) ? sB1 : sB0;

        if (kc < 11) {
            const uint32_t nA = (kc & 1) ? sA0 : sA1;
            const uint32_t nB = (kc & 1) ? sB0 : sB1;
            #pragma unroll
            for (int t = 0; t < 4; t++) {
                int u = tid + t * 256;
                int row = u >> 3, gg = u & 7;
                CP_ASYNC16(nA + SW128(row * 128 + gg * 16),
                           g_eA + (uint32_t)(bm + row) * 384 + (kc + 1) * 32 + gg * 4);
            }
            #pragma unroll
            for (int t = 0; t < 2; t++) {
                int u = tid + t * 256;
                CP_ASYNC16(nB + (uint32_t)(u >> 6) * 1024 + SW128((u & 63) * 16),
                           g_eB + ((uint32_t)(kc + 1) * 192 + nt0 + (u >> 6)) * 256 + (u & 63) * 4);
            }
            CP_COMMIT();
            CP_WAIT(1);
        } else {
            CP_WAIT(0);
        }
        __syncthreads();

        uint32_t afr[4][4];
        #pragma unroll
        for (int s = 0; s < 4; s++) {
            uint32_t off = (uint32_t)ar * 128 + s * 32 + akoff;
            LDMATRIX_X4(afr[s][0], afr[s][1], afr[s][2], afr[s][3], curA + SW128(off));
        }

        #pragma unroll
        for (int nt = 0; nt < 8; nt++) {
            const uint32_t tb = curB + nt * 1024;
            #pragma unroll
            for (int s2 = 0; s2 < 2; s2++) {
                uint32_t b0, b1, b2, b3;
                LDMATRIX_X4(b0, b1, b2, b3, tb + SW128(boff + s2 * 64));
                MMA_BF16(c[nt], afr[2*s2][0], afr[2*s2][1], afr[2*s2][2], afr[2*s2][3], b0, b1);
                MMA_BF16(c[nt], afr[2*s2+1][0], afr[2*s2+1][1], afr[2*s2+1][2], afr[2*s2+1][3], b2, b3);
            }
        }
        __syncthreads();
    }

    const int g8 = lane >> 2;
    const int c2 = (lane & 3) * 2;
    const int r0 = bm + m0 + g8, r1 = r0 + 8;
    #pragma unroll
    for (int nt = 0; nt < 8; nt++) {
        int col = bn + nt * 8 + c2;
        float b0 = be[col], b1 = be[col + 1];
        g_pred_e[r0 * ENC_OUT + col]     = c[nt][0] + b0;
        g_pred_e[r0 * ENC_OUT + col + 1] = c[nt][1] + b1;
        g_pred_e[r1 * ENC_OUT + col]     = c[nt][2] + b0;
        g_pred_e[r1 * ENC_OUT + col + 1] = c[nt][3] + b1;
    }
}

// ---------------------------------------------------------------------------
// Sampling + h + (L_q - L_e) partials. One thread per (n, l). fp32 exact.
// ---------------------------------------------------------------------------
__global__ __launch_bounds__(256) void sample_k(const float* __restrict__ ue,
                                                const float* __restrict__ rr)
{
    const int g = blockIdx.x * 256 + threadIdx.x;
    const int n = g >> 6, l = g & 63;
    const float* row = g_pred_e + (n & (B_ROWS - 1)) * ENC_OUT;

    float a[K_COMP], e[K_COMP];
    float amax = -1e30f;
    #pragma unroll
    for (int k = 0; k < K_COMP; k++) {
        a[k] = row[1024 + k * 64 + l];
        amax = fmaxf(amax, a[k]);
    }
    float s = 0.0f;
    #pragma unroll
    for (int k = 0; k < K_COMP; k++) { e[k] = __expf(a[k] - amax); s += e[k]; }
    const float lse_a = amax + __logf(s);
    const float inv = 1.0f / s;

    const float rv = rr[n * 64 + l];
    float c = 0.0f;
    int idx = 0;
    #pragma unroll
    for (int k = 0; k < K_COMP; k++) {
        c += e[k] * inv;
        idx += (rv > c) ? 1 : 0;
    }
    if (idx > K_COMP - 1) idx = K_COMP - 1;

    const float msel = row[idx * 64 + l];
    const float psel = row[512 + idx * 64 + l];
    const float hv = msel + __expf(-0.5f * psel) * ue[n * 64 + l];
    g_h[n * 64 + l] = hv;

    float st = 0.0f;
    #pragma unroll
    for (int k = 0; k < K_COMP; k++) {
        float m = row[k * 64 + l];
        float p = row[512 + k * 64 + l];
        float dd = hv - m;
        st += __expf(a[k] + 0.5f * p - 0.5f * __expf(p) * dd * dd);
    }
    const float lse_s = __logf(st) - lse_a;

    float v = -0.5f * hv * hv - lse_s;
    v = block_reduce_256(v);
    if (threadIdx.x == 0) atomicAdd(&g_accum[0], v);
}

// ---------------------------------------------------------------------------
// Decoder: tensor-core bf16 GEMM + fused mixture epilogue.
// Grid 512 = 256 M-tiles x 2 d-halves; 8 warps = 4 m16 x 2 kc-groups.
// h tile staged INSIDE B-buffer-1 (dead until ic=0's prefetch); exchange 4KB.
// Dynamic smem = 48KB + 4KB = 52KB -> genuinely 4 CTAs/SM at regs<=64.
// ---------------------------------------------------------------------------
__global__ __launch_bounds__(256, 4) void dec_k(const float* __restrict__ x,
                                                const float* __restrict__ bd)
{
    extern __shared__ uint32_t dsm[];
    uint32_t* bufB = dsm;                       // [0, 12288) u32 : 2x24KB
    uint32_t* hsm  = dsm + 6144;                // h tile inside bufB[1] (prologue only)
    float*    ex_t = (float*)(dsm + 12288);     // [2][256]
    float*    ex_a = ex_t + 512;                // [2][256]

    const int tid  = threadIdx.x;
    const int lane = tid & 31;
    const int warp = tid >> 5;
    const int wq   = warp & 3;     // m16 block
    const int wg   = warp >> 2;    // kc group
    const int mt   = blockIdx.x & 255;
    const int ds   = blockIdx.x >> 8;
    const int row0 = mt * 64;
    const int dc0  = ds * 16;

    const uint32_t sb_bufB = smem_u32(bufB);
    const uint32_t sb_h    = smem_u32(hsm);

    // stage h tile (into bufB[1] space)
    {
        int r = tid >> 2, q = tid & 3;
        const float* hp = g_h + (row0 + r) * 64 + q * 16;
        #pragma unroll
        for (int j = 0; j < 8; j++) {
            float2 v = *reinterpret_cast<const float2*>(hp + 2 * j);
            uint32_t off = r * 128 + (q * 16 + 2 * j) * 2;
            hsm[SW128(off) >> 2] = bf16x2_pack(v.y, v.x);
        }
    }

    // prefetch d-chunk dc0 into bufB[0]
    {
        const uint32_t* gsrc = g_wT + dc0 * 6144;
        #pragma unroll
        for (int j = 0; j < 6; j++) {
            int c = tid + j * 256;
            uint32_t so = (uint32_t)(c >> 6) * 1024 + SW128((c & 63) * 16);
            CP_ASYNC16(sb_bufB + so, gsrc + c * 4);
        }
        CP_COMMIT();
    }
    __syncthreads();

    // A fragments from h tile (bufB[1] space); held for the whole kernel
    uint32_t afr[4][4];
    {
        const int m0 = wq * 16;
        #pragma unroll
        for (int s = 0; s < 4; s++) {
            int r = m0 + ((lane >> 3) & 1) * 8 + (lane & 7);
            uint32_t off = r * 128 + s * 32 + ((lane >> 4) & 1) * 16;
            LDMATRIX_X4(afr[s][0], afr[s][1], afr[s][2], afr[s][3], sb_h + SW128(off));
        }
    }
    __syncthreads();   // ALL warps' afr loads complete before bufB[1] is overwritten

    // epilogue geometry
    const int g8  = lane >> 2;
    const int c2  = (lane & 3) * 2;
    const int xr0 = (row0 + wq * 16 + g8) & (B_ROWS - 1);
    const int xr1 = (row0 + wq * 16 + g8 + 8) & (B_ROWS - 1);
    const int po  = (wg ^ 1) * 2;   // p-values published to the partner group

    float part = 0.0f;

    for (int ic = 0; ic < 16; ic++) {
        const int dc = dc0 + ic;
        const uint32_t curB = sb_bufB + (ic & 1) * 24576;

        if (ic < 15) {
            const uint32_t* gsrc = g_wT + (dc + 1) * 6144;
            const uint32_t nxtB = sb_bufB + ((ic + 1) & 1) * 24576;
            #pragma unroll
            for (int j = 0; j < 6; j++) {
                int c = tid + j * 256;
                uint32_t so = (uint32_t)(c >> 6) * 1024 + SW128((c & 63) * 16);
                CP_ASYNC16(nxtB + so, gsrc + c * 4);
            }
            CP_COMMIT();
            CP_WAIT(1);
        } else {
            CP_WAIT(0);
        }
        __syncthreads();

        const int d0 = dc * 8 + c2;
        float2 x0 = *reinterpret_cast<const float2*>(x + xr0 * D_DATA + d0);
        float2 x1 = *reinterpret_cast<const float2*>(x + xr1 * D_DATA + d0);

        float s_t[4] = {0.f, 0.f, 0.f, 0.f};
        float s_a[4] = {0.f, 0.f, 0.f, 0.f};

        #pragma unroll
        for (int kl = 0; kl < 4; kl++) {
            const int kc = wg * 4 + kl;
            float cm[4] = {0.f, 0.f, 0.f, 0.f};
            float cp_[4] = {0.f, 0.f, 0.f, 0.f};
            float ca[4] = {0.f, 0.f, 0.f, 0.f};

            const uint32_t tb = curB + kc * 3072;
            const uint32_t boff = (uint32_t)(lane & 7) * 128 + (uint32_t)(lane >> 3) * 16;
            #pragma unroll
            for (int s2 = 0; s2 < 2; s2++) {
                uint32_t b0, b1, b2, b3;
                uint32_t a_sw = SW128(boff + s2 * 64);
                LDMATRIX_X4(b0, b1, b2, b3, tb + a_sw);
                MMA_BF16(cm, afr[2*s2][0], afr[2*s2][1], afr[2*s2][2], afr[2*s2][3], b0, b1);
                MMA_BF16(cm, afr[2*s2+1][0], afr[2*s2+1][1], afr[2*s2+1][2], afr[2*s2+1][3], b2, b3);
                LDMATRIX_X4(b0, b1, b2, b3, tb + 1024 + a_sw);
                MMA_BF16(cp_, afr[2*s2][0], afr[2*s2][1], afr[2*s2][2], afr[2*s2][3], b0, b1);
                MMA_BF16(cp_, afr[2*s2+1][0], afr[2*s2+1][1], afr[2*s2+1][2], afr[2*s2+1][3], b2, b3);
                LDMATRIX_X4(b0, b1, b2, b3, tb + 2048 + a_sw);
                MMA_BF16(ca, afr[2*s2][0], afr[2*s2][1], afr[2*s2][2], afr[2*s2][3], b0, b1);
                MMA_BF16(ca, afr[2*s2+1][0], afr[2*s2+1][1], afr[2*s2+1][2], afr[2*s2+1][3], b2, b3);
            }

            const int bi = kc * 256 + d0;
            float2 bm2 = __ldg(reinterpret_cast<const float2*>(bd + bi));
            float2 bp2 = __ldg(reinterpret_cast<const float2*>(bd + 2048 + bi));
            float2 ba2 = __ldg(reinterpret_cast<const float2*>(bd + 4096 + bi));

            #pragma unroll
            for (int p = 0; p < 4; p++) {
                float bm = (p & 1) ? bm2.y : bm2.x;
                float bp = (p & 1) ? bp2.y : bp2.x;
                float ba = (p & 1) ? ba2.y : ba2.x;
                float xval = (p == 0) ? x0.x : (p == 1) ? x0.y : (p == 2) ? x1.x : x1.y;
                float m  = cm[p] + bm;
                float pv = cp_[p] + bp;
                float av = ca[p] + ba;
                float dd = xval - m;
                float tt = av + 0.5f * pv - 0.5f * __expf(pv) * dd * dd;
                s_t[p] += __expf(tt);
                s_a[p] += __expf(av);
            }
        }

        // publish only the partner group's p-values
        ex_t[0 * 256 + tid] = s_t[po];
        ex_t[1 * 256 + tid] = s_t[po + 1];
        ex_a[0 * 256 + tid] = s_a[po];
        ex_a[1 * 256 + tid] = s_a[po + 1];
        __syncthreads();
        {
            const int other = tid ^ 128;
            #pragma unroll
            for (int pp = 0; pp < 2; pp++) {
                int p = wg * 2 + pp;
                float tt = s_t[p] + ex_t[pp * 256 + other];
                float ta = s_a[p] + ex_a[pp * 256 + other];
                part += __logf(tt) - __logf(ta);
            }
        }
        __syncthreads();
    }

    // block reduce over 256 threads
    {
        __shared__ float red[8];
        #pragma unroll
        for (int o = 16; o > 0; o >>= 1) part += __shfl_down_sync(0xffffffffu, part, o);
        if (lane == 0) red[warp] = part;
        __syncthreads();
        if (tid == 0) {
            float s = 0.0f;
            #pragma unroll
            for (int w = 0; w < 8; w++) s += red[w];
            atomicAdd(&g_accum[1], s);
        }
    }
}

// ---------------------------------------------------------------------------
// Final: out = -( (accum0 + accum1)/N + c2 ),  c2 = -0.5*D*log(2*pi)
// ---------------------------------------------------------------------------
__global__ void final_k(float* __restrict__ out)
{
    if (threadIdx.x == 0) {
        const float c2 = -0.5f * 256.0f * 1.8378770664093453f;
        out[0] = -((g_accum[0] + g_accum[1]) / (float)N_ROWS + c2);
    }
}

extern "C" void kernel_launch(void* const* d_in, const int* in_sizes, int n_in,
                              void* d_out, int out_size) {
    const float* x  = (const float*)d_in[0];
    const float* We = (const float*)d_in[1];
    const float* be = (const float*)d_in[2];
    const float* Wd = (const float*)d_in[3];
    const float* bd = (const float*)d_in[4];
    const float* ue = (const float*)d_in[5];
    const float* rr = (const float*)d_in[6];
    float* out = (float*)d_out;

    static bool attr_set = false;
    if (!attr_set) {
        cudaFuncSetAttribute(dec_k, cudaFuncAttributeMaxDynamicSharedMemorySize, 53248);
        cudaFuncSetAttribute(enc_tc, cudaFuncAttributeMaxDynamicSharedMemorySize, 49152);
        attr_set = true;
    }

    prep_all<<<6144, 256>>>(Wd, x, We);
    enc_tc<<<dim3(24, 16), 256, 49152>>>(be);
    sample_k<<<NB_SAMP, 256>>>(ue, rr);
    dec_k<<<NB_DEC, 256, 53248>>>(x, bd);
    final_k<<<1, 32>>>(out);
}

// round 12
// speedup vs baseline: 1.4078x; 1.0700x over previous
#include <cuda_runtime.h>
#include <cuda_bf16.h>
#include <cstdint>

#define K_COMP   8
#define L_LAT    64
#define D_DATA   256
#define N_ROWS   16384
#define B_ROWS   2048
#define ENC_OUT  1536   // 3*K*L
#define DEC_OUT  6144   // 3*K*D
#define NB_SAMP  4096
#define D_SPLIT  4
#define NB_DEC   (128 * D_SPLIT)   // 512
#define WT_N     196608
#define EA_N     786432
#define EB_N     589824

__device__ float    g_pred_e[B_ROWS * ENC_OUT];
__device__ float    g_h[N_ROWS * L_LAT];
__device__ uint32_t g_wT[WT_N];
__device__ uint32_t g_eA[EA_N];
__device__ uint32_t g_eB[EB_N];
__device__ float    g_accum[2];

typedef unsigned long long u64;

// ---- helpers -------------------------------------------------------------
__device__ __forceinline__ uint32_t bf16x2_pack(float hi, float lo) {
    uint32_t o; asm("cvt.rn.bf16x2.f32 %0, %1, %2;" : "=r"(o) : "f"(hi), "f"(lo)); return o;
}
__device__ __forceinline__ float bf16_rf(float v) {
    __nv_bfloat16 b = __float2bfloat16(v);
    return __bfloat162float(b);
}
__device__ __forceinline__ uint32_t smem_u32(const void* p) {
    uint32_t a;
    asm("{ .reg .u64 t; cvta.to.shared.u64 t, %1; cvt.u32.u64 %0, t; }" : "=r"(a) : "l"(p));
    return a;
}
#define SW128(b) ((b) ^ (((b) >> 3) & 0x70))

#define LDMATRIX_X4(r0, r1, r2, r3, addr)                                     \
    asm volatile("ldmatrix.sync.aligned.m8n8.x4.shared.b16 {%0,%1,%2,%3}, [%4];" \
        : "=r"(r0), "=r"(r1), "=r"(r2), "=r"(r3) : "r"(addr))

#define MMA_BF16(c, a0, a1, a2, a3, b0, b1)                                   \
    asm volatile("mma.sync.aligned.m16n8k16.row.col.f32.bf16.bf16.f32 "       \
        "{%0,%1,%2,%3}, {%4,%5,%6,%7}, {%8,%9}, {%0,%1,%2,%3};"               \
        : "+f"((c)[0]), "+f"((c)[1]), "+f"((c)[2]), "+f"((c)[3])              \
        : "r"(a0), "r"(a1), "r"(a2), "r"(a3), "r"(b0), "r"(b1))

#define CP_ASYNC16(saddr, gaddr)                                              \
    asm volatile("cp.async.cg.shared.global [%0], [%1], 16;" :: "r"(saddr), "l"(gaddr))
#define CP_COMMIT() asm volatile("cp.async.commit_group;")
#define CP_WAIT(n)  asm volatile("cp.async.wait_group %0;" :: "n"(n))

__device__ __forceinline__ float block_reduce_256(float v) {
    __shared__ float red[8];
    int lane = threadIdx.x & 31, wid = threadIdx.x >> 5;
    #pragma unroll
    for (int o = 16; o > 0; o >>= 1) v += __shfl_down_sync(0xffffffffu, v, o);
    if (lane == 0) red[wid] = v;
    __syncthreads();
    if (wid == 0) {
        v = (lane < 8) ? red[lane] : 0.0f;
        #pragma unroll
        for (int o = 4; o > 0; o >>= 1) v += __shfl_down_sync(0xffffffffu, v, o);
    }
    return v;
}

// ---------------------------------------------------------------------------
// Fused prep: [0,768) W_d tiles; [768,3840) enc A'; rest enc B'.
// ---------------------------------------------------------------------------
__global__ __launch_bounds__(256) void prep_all(const float* __restrict__ Wd,
                                                const float* __restrict__ x,
                                                const float* __restrict__ We)
{
    const int b = blockIdx.x;
    if (b == 0 && threadIdx.x < 2) g_accum[threadIdx.x] = 0.0f;

    if (b < 768) {
        int i = b * 256 + threadIdx.x;
        int kp = i & 31;
        int n  = (i >> 5) & 7;
        int tile = i >> 8;
        int t = tile % 3;
        int q = tile / 3;
        int kc = q & 7, dc = q >> 3;
        int col = t * 2048 + kc * 256 + dc * 8 + n;
        float w0 = Wd[(2 * kp) * DEC_OUT + col];
        float w1 = Wd[(2 * kp + 1) * DEC_OUT + col];
        g_wT[i] = bf16x2_pack(w1, w0);
    } else if (b < 3840) {
        int i = (b - 768) * 256 + threadIdx.x;
        int row = i / 384, j = i % 384;
        int k0 = 2 * j;
        float v0, v1;
        if (k0 < 512) {
            v0 = bf16_rf(x[row * 256 + (k0 & 255)]);
            v1 = bf16_rf(x[row * 256 + ((k0 + 1) & 255)]);
        } else {
            float a0 = x[row * 256 + (k0 - 512)];
            float a1 = x[row * 256 + (k0 - 511)];
            v0 = a0 - bf16_rf(a0);
            v1 = a1 - bf16_rf(a1);
        }
        g_eA[i] = bf16x2_pack(v1, v0);
    } else {
        int i = (b - 3840) * 256 + threadIdx.x;
        int kp = i & 31;
        int n  = (i >> 5) & 7;
        int r  = i >> 8;
        int nt = r % 192, kc = r / 192;
        int col = nt * 8 + n;
        float v[2];
        #pragma unroll
        for (int s = 0; s < 2; s++) {
            int k = kc * 64 + 2 * kp + s;
            if (k < 256) {
                v[s] = bf16_rf(We[k * ENC_OUT + col]);
            } else if (k < 512) {
                float a = We[(k - 256) * ENC_OUT + col];
                v[s] = a - bf16_rf(a);
            } else {
                v[s] = bf16_rf(We[(k - 512) * ENC_OUT + col]);
            }
        }
        g_eB[i] = bf16x2_pack(v[1], v[0]);
    }
}

// ---------------------------------------------------------------------------
// Encoder GEMM (tensor core, split-bf16 K=768): pred_e = A' @ B' + b_e
// ---------------------------------------------------------------------------
__global__ __launch_bounds__(256, 3) void enc_tc(const float* __restrict__ be)
{
    extern __shared__ uint32_t esm[];
    const uint32_t sA0 = smem_u32(esm);
    const uint32_t sA1 = sA0 + 16384;
    const uint32_t sB0 = sA1 + 16384;
    const uint32_t sB1 = sB0 + 8192;

    const int tid  = threadIdx.x;
    const int lane = tid & 31;
    const int warp = tid >> 5;
    const int bn = blockIdx.x * 64, bm = blockIdx.y * 128;
    const int nt0 = blockIdx.x * 8;

    {
        #pragma unroll
        for (int t = 0; t < 4; t++) {
            int u = tid + t * 256;
            int row = u >> 3, gg = u & 7;
            CP_ASYNC16(sA0 + SW128(row * 128 + gg * 16),
                       g_eA + (uint32_t)(bm + row) * 384 + gg * 4);
        }
        #pragma unroll
        for (int t = 0; t < 2; t++) {
            int u = tid + t * 256;
            CP_ASYNC16(sB0 + (uint32_t)(u >> 6) * 1024 + SW128((u & 63) * 16),
                       g_eB + (uint32_t)(nt0 + (u >> 6)) * 256 + (u & 63) * 4);
        }
        CP_COMMIT();
    }

    float c[8][4];
    #pragma unroll
    for (int nt = 0; nt < 8; nt++)
        #pragma unroll
        for (int p = 0; p < 4; p++) c[nt][p] = 0.0f;

    const int m0 = warp * 16;
    const int ar = m0 + ((lane >> 3) & 1) * 8 + (lane & 7);
    const uint32_t akoff = ((lane >> 4) & 1) * 16;
    const uint32_t boff = (uint32_t)(lane & 7) * 128 + (uint32_t)(lane >> 3) * 16;

    for (int kc = 0; kc < 12; kc++) {
        const uint32_t curA = (kc & 1) ? sA1 : sA0;
        const uint32_t curB = (kc & 1) ? sB1 : sB0;

        if (kc < 11) {
            const uint32_t nA = (kc & 1) ? sA0 : sA1;
            const uint32_t nB = (kc & 1) ? sB0 : sB1;
            #pragma unroll
            for (int t = 0; t < 4; t++) {
                int u = tid + t * 256;
                int row = u >> 3, gg = u & 7;
                CP_ASYNC16(nA + SW128(row * 128 + gg * 16),
                           g_eA + (uint32_t)(bm + row) * 384 + (kc + 1) * 32 + gg * 4);
            }
            #pragma unroll
            for (int t = 0; t < 2; t++) {
                int u = tid + t * 256;
                CP_ASYNC16(nB + (uint32_t)(u >> 6) * 1024 + SW128((u & 63) * 16),
                           g_eB + ((uint32_t)(kc + 1) * 192 + nt0 + (u >> 6)) * 256 + (u & 63) * 4);
            }
            CP_COMMIT();
            CP_WAIT(1);
        } else {
            CP_WAIT(0);
        }
        __syncthreads();

        uint32_t afr[4][4];
        #pragma unroll
        for (int s = 0; s < 4; s++) {
            uint32_t off = (uint32_t)ar * 128 + s * 32 + akoff;
            LDMATRIX_X4(afr[s][0], afr[s][1], afr[s][2], afr[s][3], curA + SW128(off));
        }

        #pragma unroll
        for (int nt = 0; nt < 8; nt++) {
            const uint32_t tb = curB + nt * 1024;
            #pragma unroll
            for (int s2 = 0; s2 < 2; s2++) {
                uint32_t b0, b1, b2, b3;
                LDMATRIX_X4(b0, b1, b2, b3, tb + SW128(boff + s2 * 64));
                MMA_BF16(c[nt], afr[2*s2][0], afr[2*s2][1], afr[2*s2][2], afr[2*s2][3], b0, b1);
                MMA_BF16(c[nt], afr[2*s2+1][0], afr[2*s2+1][1], afr[2*s2+1][2], afr[2*s2+1][3], b2, b3);
            }
        }
        __syncthreads();
    }

    const int g8 = lane >> 2;
    const int c2 = (lane & 3) * 2;
    const int r0 = bm + m0 + g8, r1 = r0 + 8;
    #pragma unroll
    for (int nt = 0; nt < 8; nt++) {
        int col = bn + nt * 8 + c2;
        float b0 = be[col], b1 = be[col + 1];
        g_pred_e[r0 * ENC_OUT + col]     = c[nt][0] + b0;
        g_pred_e[r0 * ENC_OUT + col + 1] = c[nt][1] + b1;
        g_pred_e[r1 * ENC_OUT + col]     = c[nt][2] + b0;
        g_pred_e[r1 * ENC_OUT + col + 1] = c[nt][3] + b1;
    }
}

// ---------------------------------------------------------------------------
// Sampling + h + (L_q - L_e) partials. One thread per (n, l). fp32 exact.
// ---------------------------------------------------------------------------
__global__ __launch_bounds__(256) void sample_k(const float* __restrict__ ue,
                                                const float* __restrict__ rr)
{
    const int g = blockIdx.x * 256 + threadIdx.x;
    const int n = g >> 6, l = g & 63;
    const float* row = g_pred_e + (n & (B_ROWS - 1)) * ENC_OUT;

    float a[K_COMP], e[K_COMP];
    float amax = -1e30f;
    #pragma unroll
    for (int k = 0; k < K_COMP; k++) {
        a[k] = row[1024 + k * 64 + l];
        amax = fmaxf(amax, a[k]);
    }
    float s = 0.0f;
    #pragma unroll
    for (int k = 0; k < K_COMP; k++) { e[k] = __expf(a[k] - amax); s += e[k]; }
    const float lse_a = amax + __logf(s);
    const float inv = 1.0f / s;

    const float rv = rr[n * 64 + l];
    float c = 0.0f;
    int idx = 0;
    #pragma unroll
    for (int k = 0; k < K_COMP; k++) {
        c += e[k] * inv;
        idx += (rv > c) ? 1 : 0;
    }
    if (idx > K_COMP - 1) idx = K_COMP - 1;

    const float msel = row[idx * 64 + l];
    const float psel = row[512 + idx * 64 + l];
    const float hv = msel + __expf(-0.5f * psel) * ue[n * 64 + l];
    g_h[n * 64 + l] = hv;

    float st = 0.0f;
    #pragma unroll
    for (int k = 0; k < K_COMP; k++) {
        float m = row[k * 64 + l];
        float p = row[512 + k * 64 + l];
        float dd = hv - m;
        st += __expf(a[k] + 0.5f * p - 0.5f * __expf(p) * dd * dd);
    }
    const float lse_s = __logf(st) - lse_a;

    float v = -0.5f * hv * hv - lse_s;
    v = block_reduce_256(v);
    if (threadIdx.x == 0) atomicAdd(&g_accum[0], v);
}

// ---------------------------------------------------------------------------
// Decoder: tensor-core bf16 GEMM + fused mixture epilogue.
// Grid 512 = 128 M-tiles(128 rows) x 4 d-quarters; 8 warps = 8 x m16 rows.
// Every warp processes ALL 8 kc for its rows -> no exchange, no partner sync.
// h tile (16KB) staged inside bufB[1] (dead until ic=1's prefetch).
// Dynamic smem = 48KB; (256,3) -> regs ~80, spill-free.
// ---------------------------------------------------------------------------
__global__ __launch_bounds__(256, 3) void dec_k(const float* __restrict__ x,
                                                const float* __restrict__ bd)
{
    extern __shared__ uint32_t dsm[];
    uint32_t* bufB = dsm;                       // [0, 12288) u32 : 2x24KB
    uint32_t* hsm  = dsm + 6144;                // h tile inside bufB[1] (prologue only)

    const int tid  = threadIdx.x;
    const int lane = tid & 31;
    const int warp = tid >> 5;                  // m16 block 0..7
    const int mt   = blockIdx.x & 127;
    const int ds   = blockIdx.x >> 7;
    const int row0 = mt * 128;
    const int dc0  = ds * 8;

    const uint32_t sb_bufB = smem_u32(bufB);
    const uint32_t sb_h    = smem_u32(hsm);

    // stage h tile (128 rows x 64 bf16 = 16KB) into bufB[1] space
    {
        int r = tid >> 1, q = tid & 1;
        const float* hp = g_h + (row0 + r) * 64 + q * 32;
        #pragma unroll
        for (int j = 0; j < 16; j++) {
            float2 v = *reinterpret_cast<const float2*>(hp + 2 * j);
            uint32_t off = r * 128 + (q * 32 + 2 * j) * 2;
            hsm[SW128(off) >> 2] = bf16x2_pack(v.y, v.x);
        }
    }

    // prefetch d-chunk dc0 into bufB[0]
    {
        const uint32_t* gsrc = g_wT + dc0 * 6144;
        #pragma unroll
        for (int j = 0; j < 6; j++) {
            int c = tid + j * 256;
            uint32_t so = (uint32_t)(c >> 6) * 1024 + SW128((c & 63) * 16);
            CP_ASYNC16(sb_bufB + so, gsrc + c * 4);
        }
        CP_COMMIT();
    }
    __syncthreads();

    // A fragments (this warp's 16 rows, K=64); held for the whole kernel
    uint32_t afr[4][4];
    {
        const int m0 = warp * 16;
        #pragma unroll
        for (int s = 0; s < 4; s++) {
            int r = m0 + ((lane >> 3) & 1) * 8 + (lane & 7);
            uint32_t off = r * 128 + s * 32 + ((lane >> 4) & 1) * 16;
            LDMATRIX_X4(afr[s][0], afr[s][1], afr[s][2], afr[s][3], sb_h + SW128(off));
        }
    }
    __syncthreads();   // all afr loads complete before bufB[1] is overwritten

    // epilogue geometry
    const int g8  = lane >> 2;
    const int c2  = (lane & 3) * 2;
    const int xr0 = (row0 + warp * 16 + g8) & (B_ROWS - 1);
    const int xr1 = (row0 + warp * 16 + g8 + 8) & (B_ROWS - 1);

    float part = 0.0f;

    for (int ic = 0; ic < 8; ic++) {
        const int dc = dc0 + ic;
        const uint32_t curB = sb_bufB + (ic & 1) * 24576;

        if (ic < 7) {
            const uint32_t* gsrc = g_wT + (dc + 1) * 6144;
            const uint32_t nxtB = sb_bufB + ((ic + 1) & 1) * 24576;
            #pragma unroll
            for (int j = 0; j < 6; j++) {
                int c = tid + j * 256;
                uint32_t so = (uint32_t)(c >> 6) * 1024 + SW128((c & 63) * 16);
                CP_ASYNC16(nxtB + so, gsrc + c * 4);
            }
            CP_COMMIT();
            CP_WAIT(1);
        } else {
            CP_WAIT(0);
        }
        __syncthreads();

        const int d0 = dc * 8 + c2;
        float2 x0 = *reinterpret_cast<const float2*>(x + xr0 * D_DATA + d0);
        float2 x1 = *reinterpret_cast<const float2*>(x + xr1 * D_DATA + d0);

        float s_t[4] = {0.f, 0.f, 0.f, 0.f};
        float s_a[4] = {0.f, 0.f, 0.f, 0.f};

        #pragma unroll
        for (int kc = 0; kc < K_COMP; kc++) {
            float cm[4] = {0.f, 0.f, 0.f, 0.f};
            float cp_[4] = {0.f, 0.f, 0.f, 0.f};
            float ca[4] = {0.f, 0.f, 0.f, 0.f};

            const uint32_t tb = curB + kc * 3072;
            const uint32_t boff = (uint32_t)(lane & 7) * 128 + (uint32_t)(lane >> 3) * 16;
            #pragma unroll
            for (int s2 = 0; s2 < 2; s2++) {
                uint32_t b0, b1, b2, b3;
                uint32_t a_sw = SW128(boff + s2 * 64);
                LDMATRIX_X4(b0, b1, b2, b3, tb + a_sw);
                MMA_BF16(cm, afr[2*s2][0], afr[2*s2][1], afr[2*s2][2], afr[2*s2][3], b0, b1);
                MMA_BF16(cm, afr[2*s2+1][0], afr[2*s2+1][1], afr[2*s2+1][2], afr[2*s2+1][3], b2, b3);
                LDMATRIX_X4(b0, b1, b2, b3, tb + 1024 + a_sw);
                MMA_BF16(cp_, afr[2*s2][0], afr[2*s2][1], afr[2*s2][2], afr[2*s2][3], b0, b1);
                MMA_BF16(cp_, afr[2*s2+1][0], afr[2*s2+1][1], afr[2*s2+1][2], afr[2*s2+1][3], b2, b3);
                LDMATRIX_X4(b0, b1, b2, b3, tb + 2048 + a_sw);
                MMA_BF16(ca, afr[2*s2][0], afr[2*s2][1], afr[2*s2][2], afr[2*s2][3], b0, b1);
                MMA_BF16(ca, afr[2*s2+1][0], afr[2*s2+1][1], afr[2*s2+1][2], afr[2*s2+1][3], b2, b3);
            }

            const int bi = kc * 256 + d0;
            float2 bm2 = __ldg(reinterpret_cast<const float2*>(bd + bi));
            float2 bp2 = __ldg(reinterpret_cast<const float2*>(bd + 2048 + bi));
            float2 ba2 = __ldg(reinterpret_cast<const float2*>(bd + 4096 + bi));

            #pragma unroll
            for (int p = 0; p < 4; p++) {
                float bm = (p & 1) ? bm2.y : bm2.x;
                float bp = (p & 1) ? bp2.y : bp2.x;
                float ba = (p & 1) ? ba2.y : ba2.x;
                float xval = (p == 0) ? x0.x : (p == 1) ? x0.y : (p == 2) ? x1.x : x1.y;
                float m  = cm[p] + bm;
                float pv = cp_[p] + bp;
                float av = ca[p] + ba;
                float dd = xval - m;
                float tt = av + 0.5f * pv - 0.5f * __expf(pv) * dd * dd;
                s_t[p] += __expf(tt);
                s_a[p] += __expf(av);
            }
        }

        #pragma unroll
        for (int p = 0; p < 4; p++)
            part += __logf(s_t[p]) - __logf(s_a[p]);

        __syncthreads();   // all curB reads done before it is refilled (ic+2)
    }

    // block reduce over 256 threads
    {
        __shared__ float red[8];
        #pragma unroll
        for (int o = 16; o > 0; o >>= 1) part += __shfl_down_sync(0xffffffffu, part, o);
        if (lane == 0) red[warp] = part;
        __syncthreads();
        if (tid == 0) {
            float s = 0.0f;
            #pragma unroll
            for (int w = 0; w < 8; w++) s += red[w];
            atomicAdd(&g_accum[1], s);
        }
    }
}

// ---------------------------------------------------------------------------
// Final: out = -( (accum0 + accum1)/N + c2 ),  c2 = -0.5*D*log(2*pi)
// ---------------------------------------------------------------------------
__global__ void final_k(float* __restrict__ out)
{
    if (threadIdx.x == 0) {
        const float c2 = -0.5f * 256.0f * 1.8378770664093453f;
        out[0] = -((g_accum[0] + g_accum[1]) / (float)N_ROWS + c2);
    }
}

extern "C" void kernel_launch(void* const* d_in, const int* in_sizes, int n_in,
                              void* d_out, int out_size) {
    const float* x  = (const float*)d_in[0];
    const float* We = (const float*)d_in[1];
    const float* be = (const float*)d_in[2];
    const float* Wd = (const float*)d_in[3];
    const float* bd = (const float*)d_in[4];
    const float* ue = (const float*)d_in[5];
    const float* rr = (const float*)d_in[6];
    float* out = (float*)d_out;

    static bool attr_set = false;
    if (!attr_set) {
        cudaFuncSetAttribute(dec_k, cudaFuncAttributeMaxDynamicSharedMemorySize, 49152);
        cudaFuncSetAttribute(enc_tc, cudaFuncAttributeMaxDynamicSharedMemorySize, 49152);
        attr_set = true;
    }

    prep_all<<<6144, 256>>>(Wd, x, We);
    enc_tc<<<dim3(24, 16), 256, 49152>>>(be);
    sample_k<<<NB_SAMP, 256>>>(ue, rr);
    dec_k<<<NB_DEC, 256, 49152>>>(x, bd);
    final_k<<<1, 32>>>(out);
}

// round 13
// speedup vs baseline: 1.5211x; 1.0805x over previous
#include <cuda_runtime.h>
#include <cuda_bf16.h>
#include <cstdint>

#define K_COMP   8
#define L_LAT    64
#define D_DATA   256
#define N_ROWS   16384
#define B_ROWS   2048
#define ENC_OUT  1536   // 3*K*L
#define DEC_OUT  6144   // 3*K*D
#define D_SPLIT  4
#define NB_DEC   (128 * D_SPLIT)   // 512
#define WT_N     196608
#define EA_N     786432
#define EB_N     589824

__device__ float    g_pred_e[B_ROWS * ENC_OUT];
__device__ float    g_h[N_ROWS * L_LAT];
__device__ uint32_t g_wT[WT_N];
__device__ uint32_t g_eA[EA_N];
__device__ uint32_t g_eB[EB_N];
__device__ float    g_accum[2];

typedef unsigned long long u64;

// ---- helpers -------------------------------------------------------------
__device__ __forceinline__ uint32_t bf16x2_pack(float hi, float lo) {
    uint32_t o; asm("cvt.rn.bf16x2.f32 %0, %1, %2;" : "=r"(o) : "f"(hi), "f"(lo)); return o;
}
__device__ __forceinline__ float bf16_rf(float v) {
    __nv_bfloat16 b = __float2bfloat16(v);
    return __bfloat162float(b);
}
__device__ __forceinline__ uint32_t smem_u32(const void* p) {
    uint32_t a;
    asm("{ .reg .u64 t; cvta.to.shared.u64 t, %1; cvt.u32.u64 %0, t; }" : "=r"(a) : "l"(p));
    return a;
}
#define SW128(b) ((b) ^ (((b) >> 3) & 0x70))

#define LDMATRIX_X4(r0, r1, r2, r3, addr)                                     \
    asm volatile("ldmatrix.sync.aligned.m8n8.x4.shared.b16 {%0,%1,%2,%3}, [%4];" \
        : "=r"(r0), "=r"(r1), "=r"(r2), "=r"(r3) : "r"(addr))

#define MMA_BF16(c, a0, a1, a2, a3, b0, b1)                                   \
    asm volatile("mma.sync.aligned.m16n8k16.row.col.f32.bf16.bf16.f32 "       \
        "{%0,%1,%2,%3}, {%4,%5,%6,%7}, {%8,%9}, {%0,%1,%2,%3};"               \
        : "+f"((c)[0]), "+f"((c)[1]), "+f"((c)[2]), "+f"((c)[3])              \
        : "r"(a0), "r"(a1), "r"(a2), "r"(a3), "r"(b0), "r"(b1))

#define CP_ASYNC16(saddr, gaddr)                                              \
    asm volatile("cp.async.cg.shared.global [%0], [%1], 16;" :: "r"(saddr), "l"(gaddr))
#define CP_COMMIT() asm volatile("cp.async.commit_group;")
#define CP_WAIT(n)  asm volatile("cp.async.wait_group %0;" :: "n"(n))

__device__ __forceinline__ float block_reduce_256(float v) {
    __shared__ float red[8];
    int lane = threadIdx.x & 31, wid = threadIdx.x >> 5;
    #pragma unroll
    for (int o = 16; o > 0; o >>= 1) v += __shfl_down_sync(0xffffffffu, v, o);
    if (lane == 0) red[wid] = v;
    __syncthreads();
    if (wid == 0) {
        v = (lane < 8) ? red[lane] : 0.0f;
        #pragma unroll
        for (int o = 4; o > 0; o >>= 1) v += __shfl_down_sync(0xffffffffu, v, o);
    }
    return v;
}

// ---------------------------------------------------------------------------
// Fused prep: [0,768) W_d tiles; [768,3840) enc A'; rest enc B'.
// ---------------------------------------------------------------------------
__global__ __launch_bounds__(256) void prep_all(const float* __restrict__ Wd,
                                                const float* __restrict__ x,
                                                const float* __restrict__ We)
{
    const int b = blockIdx.x;
    if (b == 0 && threadIdx.x < 2) g_accum[threadIdx.x] = 0.0f;

    if (b < 768) {
        int i = b * 256 + threadIdx.x;
        int kp = i & 31;
        int n  = (i >> 5) & 7;
        int tile = i >> 8;
        int t = tile % 3;
        int q = tile / 3;
        int kc = q & 7, dc = q >> 3;
        int col = t * 2048 + kc * 256 + dc * 8 + n;
        float w0 = Wd[(2 * kp) * DEC_OUT + col];
        float w1 = Wd[(2 * kp + 1) * DEC_OUT + col];
        g_wT[i] = bf16x2_pack(w1, w0);
    } else if (b < 3840) {
        int i = (b - 768) * 256 + threadIdx.x;
        int row = i / 384, j = i % 384;
        int k0 = 2 * j;
        float v0, v1;
        if (k0 < 512) {
            v0 = bf16_rf(x[row * 256 + (k0 & 255)]);
            v1 = bf16_rf(x[row * 256 + ((k0 + 1) & 255)]);
        } else {
            float a0 = x[row * 256 + (k0 - 512)];
            float a1 = x[row * 256 + (k0 - 511)];
            v0 = a0 - bf16_rf(a0);
            v1 = a1 - bf16_rf(a1);
        }
        g_eA[i] = bf16x2_pack(v1, v0);
    } else {
        int i = (b - 3840) * 256 + threadIdx.x;
        int kp = i & 31;
        int n  = (i >> 5) & 7;
        int r  = i >> 8;
        int nt = r % 192, kc = r / 192;
        int col = nt * 8 + n;
        float v[2];
        #pragma unroll
        for (int s = 0; s < 2; s++) {
            int k = kc * 64 + 2 * kp + s;
            if (k < 256) {
                v[s] = bf16_rf(We[k * ENC_OUT + col]);
            } else if (k < 512) {
                float a = We[(k - 256) * ENC_OUT + col];
                v[s] = a - bf16_rf(a);
            } else {
                v[s] = bf16_rf(We[(k - 512) * ENC_OUT + col]);
            }
        }
        g_eB[i] = bf16x2_pack(v[1], v[0]);
    }
}

// ---------------------------------------------------------------------------
// Encoder GEMM (tensor core, split-bf16 K=768): pred_e = A' @ B' + b_e
// ---------------------------------------------------------------------------
__global__ __launch_bounds__(256, 3) void enc_tc(const float* __restrict__ be)
{
    extern __shared__ uint32_t esm[];
    const uint32_t sA0 = smem_u32(esm);
    const uint32_t sA1 = sA0 + 16384;
    const uint32_t sB0 = sA1 + 16384;
    const uint32_t sB1 = sB0 + 8192;

    const int tid  = threadIdx.x;
    const int lane = tid & 31;
    const int warp = tid >> 5;
    const int bn = blockIdx.x * 64, bm = blockIdx.y * 128;
    const int nt0 = blockIdx.x * 8;

    {
        #pragma unroll
        for (int t = 0; t < 4; t++) {
            int u = tid + t * 256;
            int row = u >> 3, gg = u & 7;
            CP_ASYNC16(sA0 + SW128(row * 128 + gg * 16),
                       g_eA + (uint32_t)(bm + row) * 384 + gg * 4);
        }
        #pragma unroll
        for (int t = 0; t < 2; t++) {
            int u = tid + t * 256;
            CP_ASYNC16(sB0 + (uint32_t)(u >> 6) * 1024 + SW128((u & 63) * 16),
                       g_eB + (uint32_t)(nt0 + (u >> 6)) * 256 + (u & 63) * 4);
        }
        CP_COMMIT();
    }

    float c[8][4];
    #pragma unroll
    for (int nt = 0; nt < 8; nt++)
        #pragma unroll
        for (int p = 0; p < 4; p++) c[nt][p] = 0.0f;

    const int m0 = warp * 16;
    const int ar = m0 + ((lane >> 3) & 1) * 8 + (lane & 7);
    const uint32_t akoff = ((lane >> 4) & 1) * 16;
    const uint32_t boff = (uint32_t)(lane & 7) * 128 + (uint32_t)(lane >> 3) * 16;

    for (int kc = 0; kc < 12; kc++) {
        const uint32_t curA = (kc & 1) ? sA1 : sA0;
        const uint32_t curB = (kc & 1) ? sB1 : sB0;

        if (kc < 11) {
            const uint32_t nA = (kc & 1) ? sA0 : sA1;
            const uint32_t nB = (kc & 1) ? sB0 : sB1;
            #pragma unroll
            for (int t = 0; t < 4; t++) {
                int u = tid + t * 256;
                int row = u >> 3, gg = u & 7;
                CP_ASYNC16(nA + SW128(row * 128 + gg * 16),
                           g_eA + (uint32_t)(bm + row) * 384 + (kc + 1) * 32 + gg * 4);
            }
            #pragma unroll
            for (int t = 0; t < 2; t++) {
                int u = tid + t * 256;
                CP_ASYNC16(nB + (uint32_t)(u >> 6) * 1024 + SW128((u & 63) * 16),
                           g_eB + ((uint32_t)(kc + 1) * 192 + nt0 + (u >> 6)) * 256 + (u & 63) * 4);
            }
            CP_COMMIT();
            CP_WAIT(1);
        } else {
            CP_WAIT(0);
        }
        __syncthreads();

        uint32_t afr[4][4];
        #pragma unroll
        for (int s = 0; s < 4; s++) {
            uint32_t off = (uint32_t)ar * 128 + s * 32 + akoff;
            LDMATRIX_X4(afr[s][0], afr[s][1], afr[s][2], afr[s][3], curA + SW128(off));
        }

        #pragma unroll
        for (int nt = 0; nt < 8; nt++) {
            const uint32_t tb = curB + nt * 1024;
            #pragma unroll
            for (int s2 = 0; s2 < 2; s2++) {
                uint32_t b0, b1, b2, b3;
                LDMATRIX_X4(b0, b1, b2, b3, tb + SW128(boff + s2 * 64));
                MMA_BF16(c[nt], afr[2*s2][0], afr[2*s2][1], afr[2*s2][2], afr[2*s2][3], b0, b1);
                MMA_BF16(c[nt], afr[2*s2+1][0], afr[2*s2+1][1], afr[2*s2+1][2], afr[2*s2+1][3], b2, b3);
            }
        }
        __syncthreads();
    }

    const int g8 = lane >> 2;
    const int c2 = (lane & 3) * 2;
    const int r0 = bm + m0 + g8, r1 = r0 + 8;
    #pragma unroll
    for (int nt = 0; nt < 8; nt++) {
        int col = bn + nt * 8 + c2;
        float b0 = be[col], b1 = be[col + 1];
        g_pred_e[r0 * ENC_OUT + col]     = c[nt][0] + b0;
        g_pred_e[r0 * ENC_OUT + col + 1] = c[nt][1] + b1;
        g_pred_e[r1 * ENC_OUT + col]     = c[nt][2] + b0;
        g_pred_e[r1 * ENC_OUT + col + 1] = c[nt][3] + b1;
    }
}

// ---------------------------------------------------------------------------
// Sampling + h + (L_q - L_e) partials, replica-folded.
// Thread = (base row br, latent l); loops the 8 replicas n = br + 2048*j.
// Row softmax / exp(p) / cumsum computed ONCE; per-replica work is 8 exps,
// 1 rsq, 1 log. Grid 512 x 256 (4 base rows per block).
// ---------------------------------------------------------------------------
__global__ __launch_bounds__(256) void sample_k(const float* __restrict__ ue,
                                                const float* __restrict__ rr)
{
    const int l  = threadIdx.x & 63;
    const int rb = threadIdx.x >> 6;
    const int br = blockIdx.x * 4 + rb;          // 0..2047
    const float* row = g_pred_e + br * ENC_OUT;

    float m[K_COMP], ep[K_COMP], q[K_COMP], c[K_COMP];

    // softmax over loga (once per row,l)
    float a[K_COMP], e[K_COMP];
    float amax = -1e30f;
    #pragma unroll
    for (int k = 0; k < K_COMP; k++) {
        a[k] = row[1024 + k * 64 + l];
        amax = fmaxf(amax, a[k]);
    }
    float s = 0.0f;
    #pragma unroll
    for (int k = 0; k < K_COMP; k++) { e[k] = __expf(a[k] - amax); s += e[k]; }
    const float lse_a = amax + __logf(s);
    const float inv = 1.0f / s;
    {
        float cc = 0.0f;
        #pragma unroll
        for (int k = 0; k < K_COMP; k++) { cc += e[k] * inv; c[k] = cc; }
    }
    #pragma unroll
    for (int k = 0; k < K_COMP; k++) {
        m[k]  = row[k * 64 + l];
        float p = row[512 + k * 64 + l];
        ep[k] = __expf(p);
        q[k]  = a[k] - lse_a + 0.5f * p;
    }

    float part = 0.0f;

    #pragma unroll
    for (int j = 0; j < 8; j++) {
        const int n = br + 2048 * j;
        const float rv = rr[n * 64 + l];

        // monotone select: idx = #(rv > c[k]), clamped; gather via SEL chain
        float msel = m[0], esel = ep[0];
        #pragma unroll
        for (int k = 1; k < K_COMP; k++) {
            bool g = rv > c[k - 1];
            msel = g ? m[k]  : msel;
            esel = g ? ep[k] : esel;
        }

        const float hv = msel + rsqrtf(esel) * ue[n * 64 + l];
        g_h[n * 64 + l] = hv;

        float st = 0.0f;
        #pragma unroll
        for (int k = 0; k < K_COMP; k++) {
            float dd = hv - m[k];
            st += __expf(q[k] - 0.5f * ep[k] * dd * dd);
        }
        part += -0.5f * hv * hv - __logf(st);
    }

    part = block_reduce_256(part);
    if (threadIdx.x == 0) atomicAdd(&g_accum[0], part);
}

// ---------------------------------------------------------------------------
// Decoder: tensor-core bf16 GEMM + fused mixture epilogue.
// Grid 512 = 128 M-tiles(128 rows) x 4 d-quarters; 8 warps = 8 x m16 rows.
// ---------------------------------------------------------------------------
__global__ __launch_bounds__(256, 3) void dec_k(const float* __restrict__ x,
                                                const float* __restrict__ bd)
{
    extern __shared__ uint32_t dsm[];
    uint32_t* bufB = dsm;                       // [0, 12288) u32 : 2x24KB
    uint32_t* hsm  = dsm + 6144;                // h tile inside bufB[1] (prologue only)

    const int tid  = threadIdx.x;
    const int lane = tid & 31;
    const int warp = tid >> 5;
    const int mt   = blockIdx.x & 127;
    const int ds   = blockIdx.x >> 7;
    const int row0 = mt * 128;
    const int dc0  = ds * 8;

    const uint32_t sb_bufB = smem_u32(bufB);
    const uint32_t sb_h    = smem_u32(hsm);

    // stage h tile (128 rows x 64 bf16 = 16KB) into bufB[1] space
    {
        int r = tid >> 1, q = tid & 1;
        const float* hp = g_h + (row0 + r) * 64 + q * 32;
        #pragma unroll
        for (int j = 0; j < 16; j++) {
            float2 v = *reinterpret_cast<const float2*>(hp + 2 * j);
            uint32_t off = r * 128 + (q * 32 + 2 * j) * 2;
            hsm[SW128(off) >> 2] = bf16x2_pack(v.y, v.x);
        }
    }

    // prefetch d-chunk dc0 into bufB[0]
    {
        const uint32_t* gsrc = g_wT + dc0 * 6144;
        #pragma unroll
        for (int j = 0; j < 6; j++) {
            int c = tid + j * 256;
            uint32_t so = (uint32_t)(c >> 6) * 1024 + SW128((c & 63) * 16);
            CP_ASYNC16(sb_bufB + so, gsrc + c * 4);
        }
        CP_COMMIT();
    }
    __syncthreads();

    // A fragments (this warp's 16 rows, K=64); held for the whole kernel
    uint32_t afr[4][4];
    {
        const int m0 = warp * 16;
        #pragma unroll
        for (int s = 0; s < 4; s++) {
            int r = m0 + ((lane >> 3) & 1) * 8 + (lane & 7);
            uint32_t off = r * 128 + s * 32 + ((lane >> 4) & 1) * 16;
            LDMATRIX_X4(afr[s][0], afr[s][1], afr[s][2], afr[s][3], sb_h + SW128(off));
        }
    }
    __syncthreads();   // all afr loads complete before bufB[1] is overwritten

    // epilogue geometry
    const int g8  = lane >> 2;
    const int c2  = (lane & 3) * 2;
    const int xr0 = (row0 + warp * 16 + g8) & (B_ROWS - 1);
    const int xr1 = (row0 + warp * 16 + g8 + 8) & (B_ROWS - 1);

    float part = 0.0f;

    for (int ic = 0; ic < 8; ic++) {
        const int dc = dc0 + ic;
        const uint32_t curB = sb_bufB + (ic & 1) * 24576;

        if (ic < 7) {
            const uint32_t* gsrc = g_wT + (dc + 1) * 6144;
            const uint32_t nxtB = sb_bufB + ((ic + 1) & 1) * 24576;
            #pragma unroll
            for (int j = 0; j < 6; j++) {
                int c = tid + j * 256;
                uint32_t so = (uint32_t)(c >> 6) * 1024 + SW128((c & 63) * 16);
                CP_ASYNC16(nxtB + so, gsrc + c * 4);
            }
            CP_COMMIT();
            CP_WAIT(1);
        } else {
            CP_WAIT(0);
        }
        __syncthreads();

        const int d0 = dc * 8 + c2;
        float2 x0 = *reinterpret_cast<const float2*>(x + xr0 * D_DATA + d0);
        float2 x1 = *reinterpret_cast<const float2*>(x + xr1 * D_DATA + d0);

        float s_t[4] = {0.f, 0.f, 0.f, 0.f};
        float s_a[4] = {0.f, 0.f, 0.f, 0.f};

        #pragma unroll
        for (int kc = 0; kc < K_COMP; kc++) {
            float cm[4] = {0.f, 0.f, 0.f, 0.f};
            float cp_[4] = {0.f, 0.f, 0.f, 0.f};
            float ca[4] = {0.f, 0.f, 0.f, 0.f};

            const uint32_t tb = curB + kc * 3072;
            const uint32_t boff = (uint32_t)(lane & 7) * 128 + (uint32_t)(lane >> 3) * 16;
            #pragma unroll
            for (int s2 = 0; s2 < 2; s2++) {
                uint32_t b0, b1, b2, b3;
                uint32_t a_sw = SW128(boff + s2 * 64);
                LDMATRIX_X4(b0, b1, b2, b3, tb + a_sw);
                MMA_BF16(cm, afr[2*s2][0], afr[2*s2][1], afr[2*s2][2], afr[2*s2][3], b0, b1);
                MMA_BF16(cm, afr[2*s2+1][0], afr[2*s2+1][1], afr[2*s2+1][2], afr[2*s2+1][3], b2, b3);
                LDMATRIX_X4(b0, b1, b2, b3, tb + 1024 + a_sw);
                MMA_BF16(cp_, afr[2*s2][0], afr[2*s2][1], afr[2*s2][2], afr[2*s2][3], b0, b1);
                MMA_BF16(cp_, afr[2*s2+1][0], afr[2*s2+1][1], afr[2*s2+1][2], afr[2*s2+1][3], b2, b3);
                LDMATRIX_X4(b0, b1, b2, b3, tb + 2048 + a_sw);
                MMA_BF16(ca, afr[2*s2][0], afr[2*s2][1], afr[2*s2][2], afr[2*s2][3], b0, b1);
                MMA_BF16(ca, afr[2*s2+1][0], afr[2*s2+1][1], afr[2*s2+1][2], afr[2*s2+1][3], b2, b3);
            }

            const int bi = kc * 256 + d0;
            float2 bm2 = __ldg(reinterpret_cast<const float2*>(bd + bi));
            float2 bp2 = __ldg(reinterpret_cast<const float2*>(bd + 2048 + bi));
            float2 ba2 = __ldg(reinterpret_cast<const float2*>(bd + 4096 + bi));

            #pragma unroll
            for (int p = 0; p < 4; p++) {
                float bm = (p & 1) ? bm2.y : bm2.x;
                float bp = (p & 1) ? bp2.y : bp2.x;
                float ba = (p & 1) ? ba2.y : ba2.x;
                float xval = (p == 0) ? x0.x : (p == 1) ? x0.y : (p == 2) ? x1.x : x1.y;
                float m  = cm[p] + bm;
                float pv = cp_[p] + bp;
                float av = ca[p] + ba;
                float dd = xval - m;
                float tt = av + 0.5f * pv - 0.5f * __expf(pv) * dd * dd;
                s_t[p] += __expf(tt);
                s_a[p] += __expf(av);
            }
        }

        #pragma unroll
        for (int p = 0; p < 4; p++)
            part += __logf(s_t[p]) - __logf(s_a[p]);

        __syncthreads();   // all curB reads done before it is refilled (ic+2)
    }

    // block reduce over 256 threads
    {
        __shared__ float red[8];
        #pragma unroll
        for (int o = 16; o > 0; o >>= 1) part += __shfl_down_sync(0xffffffffu, part, o);
        if (lane == 0) red[warp] = part;
        __syncthreads();
        if (tid == 0) {
            float s = 0.0f;
            #pragma unroll
            for (int w = 0; w < 8; w++) s += red[w];
            atomicAdd(&g_accum[1], s);
        }
    }
}

// ---------------------------------------------------------------------------
// Final: out = -( (accum0 + accum1)/N + c2 ),  c2 = -0.5*D*log(2*pi)
// ---------------------------------------------------------------------------
__global__ void final_k(float* __restrict__ out)
{
    if (threadIdx.x == 0) {
        const float c2 = -0.5f * 256.0f * 1.8378770664093453f;
        out[0] = -((g_accum[0] + g_accum[1]) / (float)N_ROWS + c2);
    }
}

extern "C" void kernel_launch(void* const* d_in, const int* in_sizes, int n_in,
                              void* d_out, int out_size) {
    const float* x  = (const float*)d_in[0];
    const float* We = (const float*)d_in[1];
    const float* be = (const float*)d_in[2];
    const float* Wd = (const float*)d_in[3];
    const float* bd = (const float*)d_in[4];
    const float* ue = (const float*)d_in[5];
    const float* rr = (const float*)d_in[6];
    float* out = (float*)d_out;

    static bool attr_set = false;
    if (!attr_set) {
        cudaFuncSetAttribute(dec_k, cudaFuncAttributeMaxDynamicSharedMemorySize, 49152);
        cudaFuncSetAttribute(enc_tc, cudaFuncAttributeMaxDynamicSharedMemorySize, 49152);
        attr_set = true;
    }

    prep_all<<<6144, 256>>>(Wd, x, We);
    enc_tc<<<dim3(24, 16), 256, 49152>>>(be);
    sample_k<<<512, 256>>>(ue, rr);
    dec_k<<<NB_DEC, 256, 49152>>>(x, bd);
    final_k<<<1, 32>>>(out);
}

// round 14
// speedup vs baseline: 1.5658x; 1.0294x over previous
#include <cuda_runtime.h>
#include <cuda_bf16.h>
#include <cstdint>

#define K_COMP   8
#define L_LAT    64
#define D_DATA   256
#define N_ROWS   16384
#define B_ROWS   2048
#define ENC_OUT  1536   // 3*K*L
#define DEC_OUT  6144   // 3*K*D
#define D_SPLIT  8
#define IC_PER   (32 / D_SPLIT)    // 4 chunks per CTA
#define NB_DEC   (128 * D_SPLIT)   // 1024
#define WT_N     196608
#define EA_N     786432
#define EB_N     589824

__device__ float    g_pred_e[B_ROWS * ENC_OUT];
__device__ float    g_h[N_ROWS * L_LAT];
__device__ uint32_t g_wT[WT_N];
__device__ uint32_t g_eA[EA_N];
__device__ uint32_t g_eB[EB_N];
__device__ float    g_accum[2];
__device__ unsigned int g_done;

typedef unsigned long long u64;

// ---- helpers -------------------------------------------------------------
__device__ __forceinline__ uint32_t bf16x2_pack(float hi, float lo) {
    uint32_t o; asm("cvt.rn.bf16x2.f32 %0, %1, %2;" : "=r"(o) : "f"(hi), "f"(lo)); return o;
}
__device__ __forceinline__ float bf16_rf(float v) {
    __nv_bfloat16 b = __float2bfloat16(v);
    return __bfloat162float(b);
}
__device__ __forceinline__ uint32_t smem_u32(const void* p) {
    uint32_t a;
    asm("{ .reg .u64 t; cvta.to.shared.u64 t, %1; cvt.u32.u64 %0, t; }" : "=r"(a) : "l"(p));
    return a;
}
#define SW128(b) ((b) ^ (((b) >> 3) & 0x70))

#define LDMATRIX_X4(r0, r1, r2, r3, addr)                                     \
    asm volatile("ldmatrix.sync.aligned.m8n8.x4.shared.b16 {%0,%1,%2,%3}, [%4];" \
        : "=r"(r0), "=r"(r1), "=r"(r2), "=r"(r3) : "r"(addr))

#define MMA_BF16(c, a0, a1, a2, a3, b0, b1)                                   \
    asm volatile("mma.sync.aligned.m16n8k16.row.col.f32.bf16.bf16.f32 "       \
        "{%0,%1,%2,%3}, {%4,%5,%6,%7}, {%8,%9}, {%0,%1,%2,%3};"               \
        : "+f"((c)[0]), "+f"((c)[1]), "+f"((c)[2]), "+f"((c)[3])              \
        : "r"(a0), "r"(a1), "r"(a2), "r"(a3), "r"(b0), "r"(b1))

#define CP_ASYNC16(saddr, gaddr)                                              \
    asm volatile("cp.async.cg.shared.global [%0], [%1], 16;" :: "r"(saddr), "l"(gaddr))
#define CP_COMMIT() asm volatile("cp.async.commit_group;")
#define CP_WAIT(n)  asm volatile("cp.async.wait_group %0;" :: "n"(n))

__device__ __forceinline__ float block_reduce_256(float v) {
    __shared__ float red[8];
    int lane = threadIdx.x & 31, wid = threadIdx.x >> 5;
    #pragma unroll
    for (int o = 16; o > 0; o >>= 1) v += __shfl_down_sync(0xffffffffu, v, o);
    if (lane == 0) red[wid] = v;
    __syncthreads();
    if (wid == 0) {
        v = (lane < 8) ? red[lane] : 0.0f;
        #pragma unroll
        for (int o = 4; o > 0; o >>= 1) v += __shfl_down_sync(0xffffffffu, v, o);
    }
    return v;
}

// ---------------------------------------------------------------------------
// Fused prep: [0,768) W_d tiles; [768,3840) enc A'; rest enc B'.
// ---------------------------------------------------------------------------
__global__ __launch_bounds__(256) void prep_all(const float* __restrict__ Wd,
                                                const float* __restrict__ x,
                                                const float* __restrict__ We)
{
    const int b = blockIdx.x;
    if (b == 0 && threadIdx.x < 2) g_accum[threadIdx.x] = 0.0f;
    if (b == 0 && threadIdx.x == 2) g_done = 0u;

    if (b < 768) {
        int i = b * 256 + threadIdx.x;
        int kp = i & 31;
        int n  = (i >> 5) & 7;
        int tile = i >> 8;
        int t = tile % 3;
        int q = tile / 3;
        int kc = q & 7, dc = q >> 3;
        int col = t * 2048 + kc * 256 + dc * 8 + n;
        float w0 = Wd[(2 * kp) * DEC_OUT + col];
        float w1 = Wd[(2 * kp + 1) * DEC_OUT + col];
        g_wT[i] = bf16x2_pack(w1, w0);
    } else if (b < 3840) {
        int i = (b - 768) * 256 + threadIdx.x;
        int row = i / 384, j = i % 384;
        int k0 = 2 * j;
        float v0, v1;
        if (k0 < 512) {
            v0 = bf16_rf(x[row * 256 + (k0 & 255)]);
            v1 = bf16_rf(x[row * 256 + ((k0 + 1) & 255)]);
        } else {
            float a0 = x[row * 256 + (k0 - 512)];
            float a1 = x[row * 256 + (k0 - 511)];
            v0 = a0 - bf16_rf(a0);
            v1 = a1 - bf16_rf(a1);
        }
        g_eA[i] = bf16x2_pack(v1, v0);
    } else {
        int i = (b - 3840) * 256 + threadIdx.x;
        int kp = i & 31;
        int n  = (i >> 5) & 7;
        int r  = i >> 8;
        int nt = r % 192, kc = r / 192;
        int col = nt * 8 + n;
        float v[2];
        #pragma unroll
        for (int s = 0; s < 2; s++) {
            int k = kc * 64 + 2 * kp + s;
            if (k < 256) {
                v[s] = bf16_rf(We[k * ENC_OUT + col]);
            } else if (k < 512) {
                float a = We[(k - 256) * ENC_OUT + col];
                v[s] = a - bf16_rf(a);
            } else {
                v[s] = bf16_rf(We[(k - 512) * ENC_OUT + col]);
            }
        }
        g_eB[i] = bf16x2_pack(v[1], v[0]);
    }
}

// ---------------------------------------------------------------------------
// Encoder GEMM (tensor core, split-bf16 K=768): pred_e = A' @ B' + b_e
// ---------------------------------------------------------------------------
__global__ __launch_bounds__(256, 3) void enc_tc(const float* __restrict__ be)
{
    extern __shared__ uint32_t esm[];
    const uint32_t sA0 = smem_u32(esm);
    const uint32_t sA1 = sA0 + 16384;
    const uint32_t sB0 = sA1 + 16384;
    const uint32_t sB1 = sB0 + 8192;

    const int tid  = threadIdx.x;
    const int lane = tid & 31;
    const int warp = tid >> 5;
    const int bn = blockIdx.x * 64, bm = blockIdx.y * 128;
    const int nt0 = blockIdx.x * 8;

    {
        #pragma unroll
        for (int t = 0; t < 4; t++) {
            int u = tid + t * 256;
            int row = u >> 3, gg = u & 7;
            CP_ASYNC16(sA0 + SW128(row * 128 + gg * 16),
                       g_eA + (uint32_t)(bm + row) * 384 + gg * 4);
        }
        #pragma unroll
        for (int t = 0; t < 2; t++) {
            int u = tid + t * 256;
            CP_ASYNC16(sB0 + (uint32_t)(u >> 6) * 1024 + SW128((u & 63) * 16),
                       g_eB + (uint32_t)(nt0 + (u >> 6)) * 256 + (u & 63) * 4);
        }
        CP_COMMIT();
    }

    float c[8][4];
    #pragma unroll
    for (int nt = 0; nt < 8; nt++)
        #pragma unroll
        for (int p = 0; p < 4; p++) c[nt][p] = 0.0f;

    const int m0 = warp * 16;
    const int ar = m0 + ((lane >> 3) & 1) * 8 + (lane & 7);
    const uint32_t akoff = ((lane >> 4) & 1) * 16;
    const uint32_t boff = (uint32_t)(lane & 7) * 128 + (uint32_t)(lane >> 3) * 16;

    for (int kc = 0; kc < 12; kc++) {
        const uint32_t curA = (kc & 1) ? sA1 : sA0;
        const uint32_t curB = (kc & 1) ? sB1 : sB0;

        if (kc < 11) {
            const uint32_t nA = (kc & 1) ? sA0 : sA1;
            const uint32_t nB = (kc & 1) ? sB0 : sB1;
            #pragma unroll
            for (int t = 0; t < 4; t++) {
                int u = tid + t * 256;
                int row = u >> 3, gg = u & 7;
                CP_ASYNC16(nA + SW128(row * 128 + gg * 16),
                           g_eA + (uint32_t)(bm + row) * 384 + (kc + 1) * 32 + gg * 4);
            }
            #pragma unroll
            for (int t = 0; t < 2; t++) {
                int u = tid + t * 256;
                CP_ASYNC16(nB + (uint32_t)(u >> 6) * 1024 + SW128((u & 63) * 16),
                           g_eB + ((uint32_t)(kc + 1) * 192 + nt0 + (u >> 6)) * 256 + (u & 63) * 4);
            }
            CP_COMMIT();
            CP_WAIT(1);
        } else {
            CP_WAIT(0);
        }
        __syncthreads();

        uint32_t afr[4][4];
        #pragma unroll
        for (int s = 0; s < 4; s++) {
            uint32_t off = (uint32_t)ar * 128 + s * 32 + akoff;
            LDMATRIX_X4(afr[s][0], afr[s][1], afr[s][2], afr[s][3], curA + SW128(off));
        }

        #pragma unroll
        for (int nt = 0; nt < 8; nt++) {
            const uint32_t tb = curB + nt * 1024;
            #pragma unroll
            for (int s2 = 0; s2 < 2; s2++) {
                uint32_t b0, b1, b2, b3;
                LDMATRIX_X4(b0, b1, b2, b3, tb + SW128(boff + s2 * 64));
                MMA_BF16(c[nt], afr[2*s2][0], afr[2*s2][1], afr[2*s2][2], afr[2*s2][3], b0, b1);
                MMA_BF16(c[nt], afr[2*s2+1][0], afr[2*s2+1][1], afr[2*s2+1][2], afr[2*s2+1][3], b2, b3);
            }
        }
        __syncthreads();
    }

    const int g8 = lane >> 2;
    const int c2 = (lane & 3) * 2;
    const int r0 = bm + m0 + g8, r1 = r0 + 8;
    #pragma unroll
    for (int nt = 0; nt < 8; nt++) {
        int col = bn + nt * 8 + c2;
        float b0 = be[col], b1 = be[col + 1];
        g_pred_e[r0 * ENC_OUT + col]     = c[nt][0] + b0;
        g_pred_e[r0 * ENC_OUT + col + 1] = c[nt][1] + b1;
        g_pred_e[r1 * ENC_OUT + col]     = c[nt][2] + b0;
        g_pred_e[r1 * ENC_OUT + col + 1] = c[nt][3] + b1;
    }
}

// ---------------------------------------------------------------------------
// Sampling + h + (L_q - L_e) partials, replica-folded.
// ---------------------------------------------------------------------------
__global__ __launch_bounds__(256) void sample_k(const float* __restrict__ ue,
                                                const float* __restrict__ rr)
{
    const int l  = threadIdx.x & 63;
    const int rb = threadIdx.x >> 6;
    const int br = blockIdx.x * 4 + rb;
    const float* row = g_pred_e + br * ENC_OUT;

    float m[K_COMP], ep[K_COMP], q[K_COMP], c[K_COMP];

    float a[K_COMP], e[K_COMP];
    float amax = -1e30f;
    #pragma unroll
    for (int k = 0; k < K_COMP; k++) {
        a[k] = row[1024 + k * 64 + l];
        amax = fmaxf(amax, a[k]);
    }
    float s = 0.0f;
    #pragma unroll
    for (int k = 0; k < K_COMP; k++) { e[k] = __expf(a[k] - amax); s += e[k]; }
    const float lse_a = amax + __logf(s);
    const float inv = 1.0f / s;
    {
        float cc = 0.0f;
        #pragma unroll
        for (int k = 0; k < K_COMP; k++) { cc += e[k] * inv; c[k] = cc; }
    }
    #pragma unroll
    for (int k = 0; k < K_COMP; k++) {
        m[k]  = row[k * 64 + l];
        float p = row[512 + k * 64 + l];
        ep[k] = __expf(p);
        q[k]  = a[k] - lse_a + 0.5f * p;
    }

    float part = 0.0f;

    #pragma unroll
    for (int j = 0; j < 8; j++) {
        const int n = br + 2048 * j;
        const float rv = rr[n * 64 + l];

        float msel = m[0], esel = ep[0];
        #pragma unroll
        for (int k = 1; k < K_COMP; k++) {
            bool g = rv > c[k - 1];
            msel = g ? m[k]  : msel;
            esel = g ? ep[k] : esel;
        }

        const float hv = msel + rsqrtf(esel) * ue[n * 64 + l];
        g_h[n * 64 + l] = hv;

        float st = 0.0f;
        #pragma unroll
        for (int k = 0; k < K_COMP; k++) {
            float dd = hv - m[k];
            st += __expf(q[k] - 0.5f * ep[k] * dd * dd);
        }
        part += -0.5f * hv * hv - __logf(st);
    }

    part = block_reduce_256(part);
    if (threadIdx.x == 0) atomicAdd(&g_accum[0], part);
}

// ---------------------------------------------------------------------------
// Decoder: tensor-core bf16 GEMM + fused mixture epilogue + fused final.
// Grid 1024 = 128 M-tiles(128 rows) x 8 d-eighths (4 chunks each).
// Fine d-split smooths wave quantization (6.92 avg vs 7 max CTAs/SM).
// Last CTA (atomic counter) writes the final scalar output.
// ---------------------------------------------------------------------------
__global__ __launch_bounds__(256, 3) void dec_k(const float* __restrict__ x,
                                                const float* __restrict__ bd,
                                                float* __restrict__ out)
{
    extern __shared__ uint32_t dsm[];
    uint32_t* bufB = dsm;                       // [0, 12288) u32 : 2x24KB
    uint32_t* hsm  = dsm + 6144;                // h tile inside bufB[1] (prologue only)

    const int tid  = threadIdx.x;
    const int lane = tid & 31;
    const int warp = tid >> 5;
    const int mt   = blockIdx.x & 127;
    const int ds   = blockIdx.x >> 7;
    const int row0 = mt * 128;
    const int dc0  = ds * IC_PER;

    const uint32_t sb_bufB = smem_u32(bufB);
    const uint32_t sb_h    = smem_u32(hsm);

    // stage h tile (128 rows x 64 bf16 = 16KB) into bufB[1] space
    {
        int r = tid >> 1, q = tid & 1;
        const float* hp = g_h + (row0 + r) * 64 + q * 32;
        #pragma unroll
        for (int j = 0; j < 16; j++) {
            float2 v = *reinterpret_cast<const float2*>(hp + 2 * j);
            uint32_t off = r * 128 + (q * 32 + 2 * j) * 2;
            hsm[SW128(off) >> 2] = bf16x2_pack(v.y, v.x);
        }
    }

    // prefetch d-chunk dc0 into bufB[0]
    {
        const uint32_t* gsrc = g_wT + dc0 * 6144;
        #pragma unroll
        for (int j = 0; j < 6; j++) {
            int c = tid + j * 256;
            uint32_t so = (uint32_t)(c >> 6) * 1024 + SW128((c & 63) * 16);
            CP_ASYNC16(sb_bufB + so, gsrc + c * 4);
        }
        CP_COMMIT();
    }
    __syncthreads();

    // A fragments (this warp's 16 rows, K=64); held for the whole kernel
    uint32_t afr[4][4];
    {
        const int m0 = warp * 16;
        #pragma unroll
        for (int s = 0; s < 4; s++) {
            int r = m0 + ((lane >> 3) & 1) * 8 + (lane & 7);
            uint32_t off = r * 128 + s * 32 + ((lane >> 4) & 1) * 16;
            LDMATRIX_X4(afr[s][0], afr[s][1], afr[s][2], afr[s][3], sb_h + SW128(off));
        }
    }
    __syncthreads();   // all afr loads complete before bufB[1] is overwritten

    // epilogue geometry
    const int g8  = lane >> 2;
    const int c2  = (lane & 3) * 2;
    const int xr0 = (row0 + warp * 16 + g8) & (B_ROWS - 1);
    const int xr1 = (row0 + warp * 16 + g8 + 8) & (B_ROWS - 1);

    float part = 0.0f;

    for (int ic = 0; ic < IC_PER; ic++) {
        const int dc = dc0 + ic;
        const uint32_t curB = sb_bufB + (ic & 1) * 24576;

        if (ic < IC_PER - 1) {
            const uint32_t* gsrc = g_wT + (dc + 1) * 6144;
            const uint32_t nxtB = sb_bufB + ((ic + 1) & 1) * 24576;
            #pragma unroll
            for (int j = 0; j < 6; j++) {
                int c = tid + j * 256;
                uint32_t so = (uint32_t)(c >> 6) * 1024 + SW128((c & 63) * 16);
                CP_ASYNC16(nxtB + so, gsrc + c * 4);
            }
            CP_COMMIT();
            CP_WAIT(1);
        } else {
            CP_WAIT(0);
        }
        __syncthreads();

        const int d0 = dc * 8 + c2;
        float2 x0 = *reinterpret_cast<const float2*>(x + xr0 * D_DATA + d0);
        float2 x1 = *reinterpret_cast<const float2*>(x + xr1 * D_DATA + d0);

        float s_t[4] = {0.f, 0.f, 0.f, 0.f};
        float s_a[4] = {0.f, 0.f, 0.f, 0.f};

        #pragma unroll
        for (int kc = 0; kc < K_COMP; kc++) {
            float cm[4] = {0.f, 0.f, 0.f, 0.f};
            float cp_[4] = {0.f, 0.f, 0.f, 0.f};
            float ca[4] = {0.f, 0.f, 0.f, 0.f};

            const uint32_t tb = curB + kc * 3072;
            const uint32_t boff = (uint32_t)(lane & 7) * 128 + (uint32_t)(lane >> 3) * 16;
            #pragma unroll
            for (int s2 = 0; s2 < 2; s2++) {
                uint32_t b0, b1, b2, b3;
                uint32_t a_sw = SW128(boff + s2 * 64);
                LDMATRIX_X4(b0, b1, b2, b3, tb + a_sw);
                MMA_BF16(cm, afr[2*s2][0], afr[2*s2][1], afr[2*s2][2], afr[2*s2][3], b0, b1);
                MMA_BF16(cm, afr[2*s2+1][0], afr[2*s2+1][1], afr[2*s2+1][2], afr[2*s2+1][3], b2, b3);
                LDMATRIX_X4(b0, b1, b2, b3, tb + 1024 + a_sw);
                MMA_BF16(cp_, afr[2*s2][0], afr[2*s2][1], afr[2*s2][2], afr[2*s2][3], b0, b1);
                MMA_BF16(cp_, afr[2*s2+1][0], afr[2*s2+1][1], afr[2*s2+1][2], afr[2*s2+1][3], b2, b3);
                LDMATRIX_X4(b0, b1, b2, b3, tb + 2048 + a_sw);
                MMA_BF16(ca, afr[2*s2][0], afr[2*s2][1], afr[2*s2][2], afr[2*s2][3], b0, b1);
                MMA_BF16(ca, afr[2*s2+1][0], afr[2*s2+1][1], afr[2*s2+1][2], afr[2*s2+1][3], b2, b3);
            }

            const int bi = kc * 256 + d0;
            float2 bm2 = __ldg(reinterpret_cast<const float2*>(bd + bi));
            float2 bp2 = __ldg(reinterpret_cast<const float2*>(bd + 2048 + bi));
            float2 ba2 = __ldg(reinterpret_cast<const float2*>(bd + 4096 + bi));

            #pragma unroll
            for (int p = 0; p < 4; p++) {
                float bm = (p & 1) ? bm2.y : bm2.x;
                float bp = (p & 1) ? bp2.y : bp2.x;
                float ba = (p & 1) ? ba2.y : ba2.x;
                float xval = (p == 0) ? x0.x : (p == 1) ? x0.y : (p == 2) ? x1.x : x1.y;
                float m  = cm[p] + bm;
                float pv = cp_[p] + bp;
                float av = ca[p] + ba;
                float dd = xval - m;
                float tt = av + 0.5f * pv - 0.5f * __expf(pv) * dd * dd;
                s_t[p] += __expf(tt);
                s_a[p] += __expf(av);
            }
        }

        #pragma unroll
        for (int p = 0; p < 4; p++)
            part += __logf(s_t[p]) - __logf(s_a[p]);

        __syncthreads();   // all curB reads done before it is refilled (ic+2)
    }

    // block reduce + last-CTA final transform
    {
        __shared__ float red[8];
        #pragma unroll
        for (int o = 16; o > 0; o >>= 1) part += __shfl_down_sync(0xffffffffu, part, o);
        if (lane == 0) red[warp] = part;
        __syncthreads();
        if (tid == 0) {
            float s = 0.0f;
            #pragma unroll
            for (int w = 0; w < 8; w++) s += red[w];
            atomicAdd(&g_accum[1], s);
            __threadfence();
            unsigned int v = atomicAdd(&g_done, 1u);
            if (v == NB_DEC - 1) {
                const float c2f = -0.5f * 256.0f * 1.8378770664093453f;
                out[0] = -((g_accum[0] + g_accum[1]) / (float)N_ROWS + c2f);
            }
        }
    }
}

extern "C" void kernel_launch(void* const* d_in, const int* in_sizes, int n_in,
                              void* d_out, int out_size) {
    const float* x  = (const float*)d_in[0];
    const float* We = (const float*)d_in[1];
    const float* be = (const float*)d_in[2];
    const float* Wd = (const float*)d_in[3];
    const float* bd = (const float*)d_in[4];
    const float* ue = (const float*)d_in[5];
    const float* rr = (const float*)d_in[6];
    float* out = (float*)d_out;

    static bool attr_set = false;
    if (!attr_set) {
        cudaFuncSetAttribute(dec_k, cudaFuncAttributeMaxDynamicSharedMemorySize, 49152);
        cudaFuncSetAttribute(enc_tc, cudaFuncAttributeMaxDynamicSharedMemorySize, 49152);
        attr_set = true;
    }

    prep_all<<<6144, 256>>>(Wd, x, We);
    enc_tc<<<dim3(24, 16), 256, 49152>>>(be);
    sample_k<<<512, 256>>>(ue, rr);
    dec_k<<<NB_DEC, 256, 49152>>>(x, bd, out);
}

// round 15
// speedup vs baseline: 1.6272x; 1.0392x over previous
#include <cuda_runtime.h>
#include <cuda_bf16.h>
#include <cstdint>

#define K_COMP   8
#define L_LAT    64
#define D_DATA   256
#define N_ROWS   16384
#define B_ROWS   2048
#define ENC_OUT  1536   // 3*K*L
#define DEC_OUT  6144   // 3*K*D
#define D_SPLIT  8
#define IC_PER   (32 / D_SPLIT)    // 4 chunks per CTA
#define NB_DEC   (128 * D_SPLIT)   // 1024
#define WT_N     196608
#define EA_N     786432
#define EB_N     589824

__device__ float    g_pred_e[B_ROWS * ENC_OUT];
__device__ float    g_h[N_ROWS * L_LAT];
__device__ uint32_t g_wT[WT_N];
__device__ uint32_t g_eA[EA_N];
__device__ uint32_t g_eB[EB_N];
__device__ float    g_accum[2];
__device__ unsigned int g_done;

typedef unsigned long long u64;

// ---- helpers -------------------------------------------------------------
__device__ __forceinline__ uint32_t bf16x2_pack(float hi, float lo) {
    uint32_t o; asm("cvt.rn.bf16x2.f32 %0, %1, %2;" : "=r"(o) : "f"(hi), "f"(lo)); return o;
}
__device__ __forceinline__ float bf16_rf(float v) {
    __nv_bfloat16 b = __float2bfloat16(v);
    return __bfloat162float(b);
}
__device__ __forceinline__ uint32_t smem_u32(const void* p) {
    uint32_t a;
    asm("{ .reg .u64 t; cvta.to.shared.u64 t, %1; cvt.u32.u64 %0, t; }" : "=r"(a) : "l"(p));
    return a;
}
#define SW128(b) ((b) ^ (((b) >> 3) & 0x70))

#define LDMATRIX_X4(r0, r1, r2, r3, addr)                                     \
    asm volatile("ldmatrix.sync.aligned.m8n8.x4.shared.b16 {%0,%1,%2,%3}, [%4];" \
        : "=r"(r0), "=r"(r1), "=r"(r2), "=r"(r3) : "r"(addr))

#define MMA_BF16(c, a0, a1, a2, a3, b0, b1)                                   \
    asm volatile("mma.sync.aligned.m16n8k16.row.col.f32.bf16.bf16.f32 "       \
        "{%0,%1,%2,%3}, {%4,%5,%6,%7}, {%8,%9}, {%0,%1,%2,%3};"               \
        : "+f"((c)[0]), "+f"((c)[1]), "+f"((c)[2]), "+f"((c)[3])              \
        : "r"(a0), "r"(a1), "r"(a2), "r"(a3), "r"(b0), "r"(b1))

#define CP_ASYNC16(saddr, gaddr)                                              \
    asm volatile("cp.async.cg.shared.global [%0], [%1], 16;" :: "r"(saddr), "l"(gaddr))
#define CP_COMMIT() asm volatile("cp.async.commit_group;")
#define CP_WAIT(n)  asm volatile("cp.async.wait_group %0;" :: "n"(n))

__device__ __forceinline__ float block_reduce_256(float v) {
    __shared__ float red[8];
    int lane = threadIdx.x & 31, wid = threadIdx.x >> 5;
    #pragma unroll
    for (int o = 16; o > 0; o >>= 1) v += __shfl_down_sync(0xffffffffu, v, o);
    if (lane == 0) red[wid] = v;
    __syncthreads();
    if (wid == 0) {
        v = (lane < 8) ? red[lane] : 0.0f;
        #pragma unroll
        for (int o = 4; o > 0; o >>= 1) v += __shfl_down_sync(0xffffffffu, v, o);
    }
    return v;
}

// ---------------------------------------------------------------------------
// Fused prep, COALESCED:
//   blocks [0,192):   W_d pack via smem transpose (64x32 fp32 tile each)
//   blocks [192,3264): enc A' pack (already coalesced)
//   blocks [3264,3840): enc B' pack via smem transpose
// ---------------------------------------------------------------------------
__global__ __launch_bounds__(256) void prep_all(const float* __restrict__ Wd,
                                                const float* __restrict__ x,
                                                const float* __restrict__ We)
{
    const int b = blockIdx.x;
    const int tid = threadIdx.x;
    if (b == 0 && tid < 2) g_accum[tid] = 0.0f;
    if (b == 0 && tid == 2) g_done = 0u;

    __shared__ float sw[64][33];

    if (b < 192) {
        // ---- W_d pack: block = (tkc 0..23, dcg 0..7) ----
        const int dcg = b & 7;
        const int tkc = b >> 3;
        const int t  = tkc % 3;
        const int kc = tkc / 3;
        const int colbase = t * 2048 + kc * 256 + dcg * 32;

        // stage 64 rows x 32 cols (coalesced float4 loads)
        {
            int row = tid >> 2, part = tid & 3;
            const float* src = Wd + row * DEC_OUT + colbase + part * 8;
            float4 v0 = *reinterpret_cast<const float4*>(src);
            float4 v1 = *reinterpret_cast<const float4*>(src + 4);
            float* d = &sw[row][part * 8];
            d[0] = v0.x; d[1] = v0.y; d[2] = v0.z; d[3] = v0.w;
            d[4] = v1.x; d[5] = v1.y; d[6] = v1.z; d[7] = v1.w;
        }
        __syncthreads();

        const int n  = tid >> 5;
        const int kp = tid & 31;
        #pragma unroll
        for (int dcp = 0; dcp < 4; dcp++) {
            const int dc = dcg * 4 + dcp;
            const int tile = (dc * 8 + kc) * 3 + t;
            float w0 = sw[2 * kp][dcp * 8 + n];
            float w1 = sw[2 * kp + 1][dcp * 8 + n];
            g_wT[tile * 256 + tid] = bf16x2_pack(w1, w0);
        }
    } else if (b < 3264) {
        // ---- enc A' pack (coalesced) ----
        int i = (b - 192) * 256 + tid;
        int row = i / 384, j = i % 384;
        int k0 = 2 * j;
        float v0, v1;
        if (k0 < 512) {
            v0 = bf16_rf(x[row * 256 + (k0 & 255)]);
            v1 = bf16_rf(x[row * 256 + ((k0 + 1) & 255)]);
        } else {
            float a0 = x[row * 256 + (k0 - 512)];
            float a1 = x[row * 256 + (k0 - 511)];
            v0 = a0 - bf16_rf(a0);
            v1 = a1 - bf16_rf(a1);
        }
        g_eA[i] = bf16x2_pack(v1, v0);
    } else {
        // ---- enc B' pack: block = (kc 0..11, cg 0..47) ----
        const int bb = b - 3264;
        const int kc = bb / 48;
        const int cg = bb % 48;
        // region: kc<4 -> wh of rows kc*64.. ; kc<8 -> wl of (kc-4)*64.. ; else wh of (kc-8)*64..
        const int kbase = (kc < 4) ? kc * 64 : (kc < 8) ? (kc - 4) * 64 : (kc - 8) * 64;
        const bool lo = (kc >= 4) && (kc < 8);

        {
            int row = tid >> 2, part = tid & 3;
            const float* src = We + (kbase + row) * ENC_OUT + cg * 32 + part * 8;
            float4 v0 = *reinterpret_cast<const float4*>(src);
            float4 v1 = *reinterpret_cast<const float4*>(src + 4);
            float t0[8] = {v0.x, v0.y, v0.z, v0.w, v1.x, v1.y, v1.z, v1.w};
            float* d = &sw[row][part * 8];
            #pragma unroll
            for (int j = 0; j < 8; j++)
                d[j] = lo ? (t0[j] - bf16_rf(t0[j])) : bf16_rf(t0[j]);
        }
        __syncthreads();

        const int n  = tid >> 5;
        const int kp = tid & 31;
        #pragma unroll
        for (int ntp = 0; ntp < 4; ntp++) {
            const int nt = cg * 4 + ntp;
            const int r = kc * 192 + nt;
            float w0 = sw[2 * kp][ntp * 8 + n];
            float w1 = sw[2 * kp + 1][ntp * 8 + n];
            g_eB[r * 256 + tid] = bf16x2_pack(w1, w0);
        }
    }
}

// ---------------------------------------------------------------------------
// Encoder GEMM (tensor core, split-bf16 K=768): pred_e = A' @ B' + b_e
// ---------------------------------------------------------------------------
__global__ __launch_bounds__(256, 3) void enc_tc(const float* __restrict__ be)
{
    extern __shared__ uint32_t esm[];
    const uint32_t sA0 = smem_u32(esm);
    const uint32_t sA1 = sA0 + 16384;
    const uint32_t sB0 = sA1 + 16384;
    const uint32_t sB1 = sB0 + 8192;

    const int tid  = threadIdx.x;
    const int lane = tid & 31;
    const int warp = tid >> 5;
    const int bn = blockIdx.x * 64, bm = blockIdx.y * 128;
    const int nt0 = blockIdx.x * 8;

    {
        #pragma unroll
        for (int t = 0; t < 4; t++) {
            int u = tid + t * 256;
            int row = u >> 3, gg = u & 7;
            CP_ASYNC16(sA0 + SW128(row * 128 + gg * 16),
                       g_eA + (uint32_t)(bm + row) * 384 + gg * 4);
        }
        #pragma unroll
        for (int t = 0; t < 2; t++) {
            int u = tid + t * 256;
            CP_ASYNC16(sB0 + (uint32_t)(u >> 6) * 1024 + SW128((u & 63) * 16),
                       g_eB + (uint32_t)(nt0 + (u >> 6)) * 256 + (u & 63) * 4);
        }
        CP_COMMIT();
    }

    float c[8][4];
    #pragma unroll
    for (int nt = 0; nt < 8; nt++)
        #pragma unroll
        for (int p = 0; p < 4; p++) c[nt][p] = 0.0f;

    const int m0 = warp * 16;
    const int ar = m0 + ((lane >> 3) & 1) * 8 + (lane & 7);
    const uint32_t akoff = ((lane >> 4) & 1) * 16;
    const uint32_t boff = (uint32_t)(lane & 7) * 128 + (uint32_t)(lane >> 3) * 16;

    for (int kc = 0; kc < 12; kc++) {
        const uint32_t curA = (kc & 1) ? sA1 : sA0;
        const uint32_t curB = (kc & 1) ? sB1 : sB0;

        if (kc < 11) {
            const uint32_t nA = (kc & 1) ? sA0 : sA1;
            const uint32_t nB = (kc & 1) ? sB0 : sB1;
            #pragma unroll
            for (int t = 0; t < 4; t++) {
                int u = tid + t * 256;
                int row = u >> 3, gg = u & 7;
                CP_ASYNC16(nA + SW128(row * 128 + gg * 16),
                           g_eA + (uint32_t)(bm + row) * 384 + (kc + 1) * 32 + gg * 4);
            }
            #pragma unroll
            for (int t = 0; t < 2; t++) {
                int u = tid + t * 256;
                CP_ASYNC16(nB + (uint32_t)(u >> 6) * 1024 + SW128((u & 63) * 16),
                           g_eB + ((uint32_t)(kc + 1) * 192 + nt0 + (u >> 6)) * 256 + (u & 63) * 4);
            }
            CP_COMMIT();
            CP_WAIT(1);
        } else {
            CP_WAIT(0);
        }
        __syncthreads();

        uint32_t afr[4][4];
        #pragma unroll
        for (int s = 0; s < 4; s++) {
            uint32_t off = (uint32_t)ar * 128 + s * 32 + akoff;
            LDMATRIX_X4(afr[s][0], afr[s][1], afr[s][2], afr[s][3], curA + SW128(off));
        }

        #pragma unroll
        for (int nt = 0; nt < 8; nt++) {
            const uint32_t tb = curB + nt * 1024;
            #pragma unroll
            for (int s2 = 0; s2 < 2; s2++) {
                uint32_t b0, b1, b2, b3;
                LDMATRIX_X4(b0, b1, b2, b3, tb + SW128(boff + s2 * 64));
                MMA_BF16(c[nt], afr[2*s2][0], afr[2*s2][1], afr[2*s2][2], afr[2*s2][3], b0, b1);
                MMA_BF16(c[nt], afr[2*s2+1][0], afr[2*s2+1][1], afr[2*s2+1][2], afr[2*s2+1][3], b2, b3);
            }
        }
        __syncthreads();
    }

    const int g8 = lane >> 2;
    const int c2 = (lane & 3) * 2;
    const int r0 = bm + m0 + g8, r1 = r0 + 8;
    #pragma unroll
    for (int nt = 0; nt < 8; nt++) {
        int col = bn + nt * 8 + c2;
        float b0 = be[col], b1 = be[col + 1];
        g_pred_e[r0 * ENC_OUT + col]     = c[nt][0] + b0;
        g_pred_e[r0 * ENC_OUT + col + 1] = c[nt][1] + b1;
        g_pred_e[r1 * ENC_OUT + col]     = c[nt][2] + b0;
        g_pred_e[r1 * ENC_OUT + col + 1] = c[nt][3] + b1;
    }
}

// ---------------------------------------------------------------------------
// Sampling + h + (L_q - L_e) partials, replica-folded.
// ---------------------------------------------------------------------------
__global__ __launch_bounds__(256) void sample_k(const float* __restrict__ ue,
                                                const float* __restrict__ rr)
{
    const int l  = threadIdx.x & 63;
    const int rb = threadIdx.x >> 6;
    const int br = blockIdx.x * 4 + rb;
    const float* row = g_pred_e + br * ENC_OUT;

    float m[K_COMP], ep[K_COMP], q[K_COMP], c[K_COMP];

    float a[K_COMP], e[K_COMP];
    float amax = -1e30f;
    #pragma unroll
    for (int k = 0; k < K_COMP; k++) {
        a[k] = row[1024 + k * 64 + l];
        amax = fmaxf(amax, a[k]);
    }
    float s = 0.0f;
    #pragma unroll
    for (int k = 0; k < K_COMP; k++) { e[k] = __expf(a[k] - amax); s += e[k]; }
    const float lse_a = amax + __logf(s);
    const float inv = 1.0f / s;
    {
        float cc = 0.0f;
        #pragma unroll
        for (int k = 0; k < K_COMP; k++) { cc += e[k] * inv; c[k] = cc; }
    }
    #pragma unroll
    for (int k = 0; k < K_COMP; k++) {
        m[k]  = row[k * 64 + l];
        float p = row[512 + k * 64 + l];
        ep[k] = __expf(p);
        q[k]  = a[k] - lse_a + 0.5f * p;
    }

    float part = 0.0f;

    #pragma unroll
    for (int j = 0; j < 8; j++) {
        const int n = br + 2048 * j;
        const float rv = rr[n * 64 + l];

        float msel = m[0], esel = ep[0];
        #pragma unroll
        for (int k = 1; k < K_COMP; k++) {
            bool g = rv > c[k - 1];
            msel = g ? m[k]  : msel;
            esel = g ? ep[k] : esel;
        }

        const float hv = msel + rsqrtf(esel) * ue[n * 64 + l];
        g_h[n * 64 + l] = hv;

        float st = 0.0f;
        #pragma unroll
        for (int k = 0; k < K_COMP; k++) {
            float dd = hv - m[k];
            st += __expf(q[k] - 0.5f * ep[k] * dd * dd);
        }
        part += -0.5f * hv * hv - __logf(st);
    }

    part = block_reduce_256(part);
    if (threadIdx.x == 0) atomicAdd(&g_accum[0], part);
}

// ---------------------------------------------------------------------------
// Decoder: tensor-core bf16 GEMM + fused mixture epilogue + fused final.
// Grid 1024 = 128 M-tiles(128 rows) x 8 d-eighths (4 chunks each).
// ---------------------------------------------------------------------------
__global__ __launch_bounds__(256, 3) void dec_k(const float* __restrict__ x,
                                                const float* __restrict__ bd,
                                                float* __restrict__ out)
{
    extern __shared__ uint32_t dsm[];
    uint32_t* bufB = dsm;                       // [0, 12288) u32 : 2x24KB
    uint32_t* hsm  = dsm + 6144;                // h tile inside bufB[1] (prologue only)

    const int tid  = threadIdx.x;
    const int lane = tid & 31;
    const int warp = tid >> 5;
    const int mt   = blockIdx.x & 127;
    const int ds   = blockIdx.x >> 7;
    const int row0 = mt * 128;
    const int dc0  = ds * IC_PER;

    const uint32_t sb_bufB = smem_u32(bufB);
    const uint32_t sb_h    = smem_u32(hsm);

    // stage h tile (128 rows x 64 bf16 = 16KB) into bufB[1] space
    {
        int r = tid >> 1, q = tid & 1;
        const float* hp = g_h + (row0 + r) * 64 + q * 32;
        #pragma unroll
        for (int j = 0; j < 16; j++) {
            float2 v = *reinterpret_cast<const float2*>(hp + 2 * j);
            uint32_t off = r * 128 + (q * 32 + 2 * j) * 2;
            hsm[SW128(off) >> 2] = bf16x2_pack(v.y, v.x);
        }
    }

    // prefetch d-chunk dc0 into bufB[0]
    {
        const uint32_t* gsrc = g_wT + dc0 * 6144;
        #pragma unroll
        for (int j = 0; j < 6; j++) {
            int c = tid + j * 256;
            uint32_t so = (uint32_t)(c >> 6) * 1024 + SW128((c & 63) * 16);
            CP_ASYNC16(sb_bufB + so, gsrc + c * 4);
        }
        CP_COMMIT();
    }
    __syncthreads();

    // A fragments (this warp's 16 rows, K=64); held for the whole kernel
    uint32_t afr[4][4];
    {
        const int m0 = warp * 16;
        #pragma unroll
        for (int s = 0; s < 4; s++) {
            int r = m0 + ((lane >> 3) & 1) * 8 + (lane & 7);
            uint32_t off = r * 128 + s * 32 + ((lane >> 4) & 1) * 16;
            LDMATRIX_X4(afr[s][0], afr[s][1], afr[s][2], afr[s][3], sb_h + SW128(off));
        }
    }
    __syncthreads();   // all afr loads complete before bufB[1] is overwritten

    // epilogue geometry
    const int g8  = lane >> 2;
    const int c2  = (lane & 3) * 2;
    const int xr0 = (row0 + warp * 16 + g8) & (B_ROWS - 1);
    const int xr1 = (row0 + warp * 16 + g8 + 8) & (B_ROWS - 1);

    float part = 0.0f;

    for (int ic = 0; ic < IC_PER; ic++) {
        const int dc = dc0 + ic;
        const uint32_t curB = sb_bufB + (ic & 1) * 24576;

        if (ic < IC_PER - 1) {
            const uint32_t* gsrc = g_wT + (dc + 1) * 6144;
            const uint32_t nxtB = sb_bufB + ((ic + 1) & 1) * 24576;
            #pragma unroll
            for (int j = 0; j < 6; j++) {
                int c = tid + j * 256;
                uint32_t so = (uint32_t)(c >> 6) * 1024 + SW128((c & 63) * 16);
                CP_ASYNC16(nxtB + so, gsrc + c * 4);
            }
            CP_COMMIT();
            CP_WAIT(1);
        } else {
            CP_WAIT(0);
        }
        __syncthreads();

        const int d0 = dc * 8 + c2;
        float2 x0 = *reinterpret_cast<const float2*>(x + xr0 * D_DATA + d0);
        float2 x1 = *reinterpret_cast<const float2*>(x + xr1 * D_DATA + d0);

        float s_t[4] = {0.f, 0.f, 0.f, 0.f};
        float s_a[4] = {0.f, 0.f, 0.f, 0.f};

        #pragma unroll
        for (int kc = 0; kc < K_COMP; kc++) {
            float cm[4] = {0.f, 0.f, 0.f, 0.f};
            float cp_[4] = {0.f, 0.f, 0.f, 0.f};
            float ca[4] = {0.f, 0.f, 0.f, 0.f};

            const uint32_t tb = curB + kc * 3072;
            const uint32_t boff = (uint32_t)(lane & 7) * 128 + (uint32_t)(lane >> 3) * 16;
            #pragma unroll
            for (int s2 = 0; s2 < 2; s2++) {
                uint32_t b0, b1, b2, b3;
                uint32_t a_sw = SW128(boff + s2 * 64);
                LDMATRIX_X4(b0, b1, b2, b3, tb + a_sw);
                MMA_BF16(cm, afr[2*s2][0], afr[2*s2][1], afr[2*s2][2], afr[2*s2][3], b0, b1);
                MMA_BF16(cm, afr[2*s2+1][0], afr[2*s2+1][1], afr[2*s2+1][2], afr[2*s2+1][3], b2, b3);
                LDMATRIX_X4(b0, b1, b2, b3, tb + 1024 + a_sw);
                MMA_BF16(cp_, afr[2*s2][0], afr[2*s2][1], afr[2*s2][2], afr[2*s2][3], b0, b1);
                MMA_BF16(cp_, afr[2*s2+1][0], afr[2*s2+1][1], afr[2*s2+1][2], afr[2*s2+1][3], b2, b3);
                LDMATRIX_X4(b0, b1, b2, b3, tb + 2048 + a_sw);
                MMA_BF16(ca, afr[2*s2][0], afr[2*s2][1], afr[2*s2][2], afr[2*s2][3], b0, b1);
                MMA_BF16(ca, afr[2*s2+1][0], afr[2*s2+1][1], afr[2*s2+1][2], afr[2*s2+1][3], b2, b3);
            }

            const int bi = kc * 256 + d0;
            float2 bm2 = __ldg(reinterpret_cast<const float2*>(bd + bi));
            float2 bp2 = __ldg(reinterpret_cast<const float2*>(bd + 2048 + bi));
            float2 ba2 = __ldg(reinterpret_cast<const float2*>(bd + 4096 + bi));

            #pragma unroll
            for (int p = 0; p < 4; p++) {
                float bm = (p & 1) ? bm2.y : bm2.x;
                float bp = (p & 1) ? bp2.y : bp2.x;
                float ba = (p & 1) ? ba2.y : ba2.x;
                float xval = (p == 0) ? x0.x : (p == 1) ? x0.y : (p == 2) ? x1.x : x1.y;
                float m  = cm[p] + bm;
                float pv = cp_[p] + bp;
                float av = ca[p] + ba;
                float dd = xval - m;
                float tt = av + 0.5f * pv - 0.5f * __expf(pv) * dd * dd;
                s_t[p] += __expf(tt);
                s_a[p] += __expf(av);
            }
        }

        #pragma unroll
        for (int p = 0; p < 4; p++)
            part += __logf(s_t[p]) - __logf(s_a[p]);

        __syncthreads();   // all curB reads done before it is refilled (ic+2)
    }

    // block reduce + last-CTA final transform
    {
        __shared__ float red[8];
        #pragma unroll
        for (int o = 16; o > 0; o >>= 1) part += __shfl_down_sync(0xffffffffu, part, o);
        if (lane == 0) red[warp] = part;
        __syncthreads();
        if (tid == 0) {
            float s = 0.0f;
            #pragma unroll
            for (int w = 0; w < 8; w++) s += red[w];
            atomicAdd(&g_accum[1], s);
            __threadfence();
            unsigned int v = atomicAdd(&g_done, 1u);
            if (v == NB_DEC - 1) {
                const float c2f = -0.5f * 256.0f * 1.8378770664093453f;
                out[0] = -((g_accum[0] + g_accum[1]) / (float)N_ROWS + c2f);
            }
        }
    }
}

extern "C" void kernel_launch(void* const* d_in, const int* in_sizes, int n_in,
                              void* d_out, int out_size) {
    const float* x  = (const float*)d_in[0];
    const float* We = (const float*)d_in[1];
    const float* be = (const float*)d_in[2];
    const float* Wd = (const float*)d_in[3];
    const float* bd = (const float*)d_in[4];
    const float* ue = (const float*)d_in[5];
    const float* rr = (const float*)d_in[6];
    float* out = (float*)d_out;

    static bool attr_set = false;
    if (!attr_set) {
        cudaFuncSetAttribute(dec_k, cudaFuncAttributeMaxDynamicSharedMemorySize, 49152);
        cudaFuncSetAttribute(enc_tc, cudaFuncAttributeMaxDynamicSharedMemorySize, 49152);
        attr_set = true;
    }

    prep_all<<<3840, 256>>>(Wd, x, We);
    enc_tc<<<dim3(24, 16), 256, 49152>>>(be);
    sample_k<<<512, 256>>>(ue, rr);
    dec_k<<<NB_DEC, 256, 49152>>>(x, bd, out);
}